// round 2
// baseline (speedup 1.0000x reference)
#include <cuda_runtime.h>
#include <math.h>

#define BB 16
#define TT 77
#define SSRC 300
#define NHID 300
#define LL 677
#define DM 512
#define NH 8
#define HD 64
#define TOKS 10832   // 16*77 + 16*300 + 16*300

// ----- scratch arena (floats) -----
#define OFF_ST    0L
#define OFF_ADA   8192L         // 3*16*3072 = 147456
#define OFF_NBUF  155648L       // TOKS*512
#define OFF_QKV   5701632L      // 3 * TOKS*512
#define OFF_QA    22339584L     // [B,H,L,64]
#define OFF_KA    27885568L
#define OFF_VA    33431552L
#define OFF_OGAT  38977536L     // gathered attn out, token-major [TOKS,512]
#define OFF_ABUF  44523520L
#define OFF_HBUF  50069504L
#define OFF_N2    55615488L
#define OFF_U     61161472L     // TOKS*4096
#define OFF_G     105529344L    // TOKS*2048
#define OFF_FF    127713280L
#define ARENA_SZ  133259264L

__device__ float d_arena[ARENA_SZ];

// ---------------------------------------------------------------------------
// silu(temb) -> st
__global__ void k_silu(const float* __restrict__ temb) {
    int i = blockIdx.x * blockDim.x + threadIdx.x;
    if (i < BB * DM) {
        float v = temb[i];
        d_arena[OFF_ST + i] = v / (1.f + __expf(-v));
    }
}

// ---------------------------------------------------------------------------
// generic fp32 GEMM: C = A @ B + bias.  A rows live in the arena (offA),
// B/bias are external pointers, C in arena (offC).  blockIdx.z batches B/bias/C.
__global__ void k_gemm(const float* __restrict__ Bmat, const float* __restrict__ bias,
                       long offA, long offC, int M, int N, int K,
                       long szB, long szBias, long szC) {
    const float* A  = d_arena + offA;
    const float* Bm = Bmat + (long)blockIdx.z * szB;
    const float* bi = bias + (long)blockIdx.z * szBias;
    float*       C  = d_arena + offC + (long)blockIdx.z * szC;

    __shared__ float As[16][68];
    __shared__ float Bs[16][64];

    int tid = threadIdx.x;
    int tx = tid & 15, ty = tid >> 4;

    int arow = tid >> 2;           // 0..63
    int akc  = (tid & 3) << 2;     // 0,4,8,12
    int brow = tid >> 4;           // 0..15
    int bcol = (tid & 15) << 2;    // 0..60

    long grow  = (long)blockIdx.y * 64 + arow;
    int  gcolB = blockIdx.x * 64 + bcol;

    float acc[4][4];
#pragma unroll
    for (int i = 0; i < 4; i++)
#pragma unroll
        for (int j = 0; j < 4; j++) acc[i][j] = 0.f;

    for (int kt = 0; kt < K; kt += 16) {
        float4 a4 = make_float4(0.f, 0.f, 0.f, 0.f);
        if (grow < M) a4 = *(const float4*)&A[grow * K + kt + akc];
        As[akc + 0][arow] = a4.x;
        As[akc + 1][arow] = a4.y;
        As[akc + 2][arow] = a4.z;
        As[akc + 3][arow] = a4.w;

        float4 b4 = *(const float4*)&Bm[(long)(kt + brow) * N + gcolB];
        *(float4*)&Bs[brow][bcol] = b4;
        __syncthreads();

#pragma unroll
        for (int k = 0; k < 16; k++) {
            float4 av = *(const float4*)&As[k][ty << 2];
            float4 bv = *(const float4*)&Bs[k][tx << 2];
            float a[4] = {av.x, av.y, av.z, av.w};
            float b[4] = {bv.x, bv.y, bv.z, bv.w};
#pragma unroll
            for (int i = 0; i < 4; i++)
#pragma unroll
                for (int j = 0; j < 4; j++) acc[i][j] += a[i] * b[j];
        }
        __syncthreads();
    }

    int crow0 = blockIdx.y * 64 + (ty << 2);
    int ccol0 = blockIdx.x * 64 + (tx << 2);
    float4 bi4 = *(const float4*)&bi[ccol0];
#pragma unroll
    for (int i = 0; i < 4; i++) {
        if (crow0 + i < M) {
            float4 o;
            o.x = acc[i][0] + bi4.x;
            o.y = acc[i][1] + bi4.y;
            o.z = acc[i][2] + bi4.z;
            o.w = acc[i][3] + bi4.w;
            *(float4*)&C[(long)(crow0 + i) * N + ccol0] = o;
        }
    }
}

// ---------------------------------------------------------------------------
__device__ __forceinline__ void block_ln_stats(float s, float q, float* mean, float* ri) {
    __shared__ float sh[8];
    int lane = threadIdx.x & 31, wid = threadIdx.x >> 5;
#pragma unroll
    for (int off = 16; off; off >>= 1) {
        s += __shfl_xor_sync(~0u, s, off);
        q += __shfl_xor_sync(~0u, q, off);
    }
    if (lane == 0) { sh[wid] = s; sh[4 + wid] = q; }
    __syncthreads();
    if (threadIdx.x == 0) {
        float S = sh[0] + sh[1] + sh[2] + sh[3];
        float Q = sh[4] + sh[5] + sh[6] + sh[7];
        float m = S * (1.f / 512.f);
        float v = Q * (1.f / 512.f) - m * m;
        sh[0] = m;
        sh[1] = rsqrtf(v + 1e-6f);
    }
    __syncthreads();
    *mean = sh[0];
    *ri   = sh[1];
}

// LN(x) * (1+sc_a) + sh_a   -> nbuf
__global__ void k_modln(const float* __restrict__ inp, int istream, int len, long tokOff) {
    int row = blockIdx.x;            // 0..B*len-1
    int b = row / len;
    int tid = threadIdx.x;           // 128
    float4 v = *(const float4*)&inp[(long)row * DM + tid * 4];
    float s = v.x + v.y + v.z + v.w;
    float q = v.x * v.x + v.y * v.y + v.z * v.z + v.w * v.w;
    float mean, ri;
    block_ln_stats(s, q, &mean, &ri);
    const float* ada = d_arena + OFF_ADA + ((long)istream * BB + b) * 3072;
    float4 sc = *(const float4*)&ada[512 + tid * 4];
    float4 shv = *(const float4*)&ada[tid * 4];
    float4 o;
    o.x = (v.x - mean) * ri * (1.f + sc.x) + shv.x;
    o.y = (v.y - mean) * ri * (1.f + sc.y) + shv.y;
    o.z = (v.z - mean) * ri * (1.f + sc.z) + shv.z;
    o.w = (v.w - mean) * ri * (1.f + sc.w) + shv.w;
    *(float4*)&d_arena[OFF_NBUF + (tokOff + row) * DM + tid * 4] = o;
}

// ---------------------------------------------------------------------------
// qkv raw -> per-head RMS norm, RoPE-xpos (motion) / learned pos (text),
// scatter to [B,H,L,64] layout.  One warp per (b,l,h); lane owns d and d+32.
__global__ void k_qkvx(const float* __restrict__ gqk,
                       const float* __restrict__ pos_q,
                       const float* __restrict__ pos_k) {
    int w = threadIdx.x >> 5;
    int lane = threadIdx.x & 31;
    int g = blockIdx.x * 4 + w;              // exactly BB*LL*NH warps
    int h = g & 7;
    int bl = g >> 3;
    int l = bl % LL;
    int b = bl / LL;

    int istream, t;
    long r;
    if (l < TT)            { istream = 2; t = l;            r = (long)b * TT + t; }
    else if (l < TT + SSRC){ istream = 1; t = l - TT;       r = 1232 + (long)b * SSRC + t; }
    else                   { istream = 0; t = l - TT - SSRC; r = 6032 + (long)b * NHID + t; }

    long base = r * DM + h * HD;
    float q0 = d_arena[OFF_QKV + base + lane];
    float q1 = d_arena[OFF_QKV + base + lane + 32];
    float k0 = d_arena[OFF_QKV + (long)TOKS * DM + base + lane];
    float k1 = d_arena[OFF_QKV + (long)TOKS * DM + base + lane + 32];
    float v0 = d_arena[OFF_QKV + 2L * TOKS * DM + base + lane];
    float v1 = d_arena[OFF_QKV + 2L * TOKS * DM + base + lane + 32];

    float sq = q0 * q0 + q1 * q1;
    float sk = k0 * k0 + k1 * k1;
#pragma unroll
    for (int off = 16; off; off >>= 1) {
        sq += __shfl_xor_sync(~0u, sq, off);
        sk += __shfl_xor_sync(~0u, sk, off);
    }
    float rq = rsqrtf(sq * (1.f / 64.f) + 1e-6f);
    float rk = rsqrtf(sk * (1.f / 64.f) + 1e-6f);
    q0 *= rq * gqk[(istream * 2 + 0) * 64 + lane];
    q1 *= rq * gqk[(istream * 2 + 0) * 64 + lane + 32];
    k0 *= rk * gqk[(istream * 2 + 1) * 64 + lane];
    k1 *= rk * gqk[(istream * 2 + 1) * 64 + lane + 32];

    if (istream == 2) {
        q0 += pos_q[t * 64 + lane];
        q1 += pos_q[t * 64 + lane + 32];
        k0 += pos_k[t * 64 + lane];
        k1 += pos_k[t * 64 + lane + 32];
    } else {
        // rotate_half partners: value at d^1 (same slot, lane^1)
        float rq0 = __shfl_xor_sync(~0u, q0, 1);
        float rq1 = __shfl_xor_sync(~0u, q1, 1);
        float rk0 = __shfl_xor_sync(~0u, k0, 1);
        float rk1 = __shfl_xor_sync(~0u, k1, 1);
        float tf = (float)t;
        float pw = (tf - 150.f) * (1.f / 512.f);
        // slot 0: d = lane
        {
            int d = lane, ii = d >> 1;
            float inv = powf(10000.f, -(float)(2 * ii) * (1.f / 64.f));
            float ang = tf * inv;
            float c = cosf(ang), s = sinf(ang);
            float scl = powf(((float)(2 * ii) + 25.6f) * (1.f / 89.6f), pw);
            float rotq = (d & 1) ? rq0 : -rq0;
            float rotk = (d & 1) ? rk0 : -rk0;
            float csq = c * scl, snq = s * scl;
            float csk = c / scl, snk = s / scl;
            q0 = q0 * csq + rotq * snq;
            k0 = k0 * csk + rotk * snk;
        }
        // slot 1: d = lane + 32
        {
            int d = lane + 32, ii = d >> 1;
            float inv = powf(10000.f, -(float)(2 * ii) * (1.f / 64.f));
            float ang = tf * inv;
            float c = cosf(ang), s = sinf(ang);
            float scl = powf(((float)(2 * ii) + 25.6f) * (1.f / 89.6f), pw);
            float rotq = (d & 1) ? rq1 : -rq1;
            float rotk = (d & 1) ? rk1 : -rk1;
            float csq = c * scl, snq = s * scl;
            float csk = c / scl, snk = s / scl;
            q1 = q1 * csq + rotq * snq;
            k1 = k1 * csk + rotk * snk;
        }
    }

    long o = (((long)(b * NH + h)) * LL + l) * HD;
    d_arena[OFF_QA + o + lane]      = q0;
    d_arena[OFF_QA + o + lane + 32] = q1;
    d_arena[OFF_KA + o + lane]      = k0;
    d_arena[OFF_KA + o + lane + 32] = k1;
    d_arena[OFF_VA + o + lane]      = v0;
    d_arena[OFF_VA + o + lane + 32] = v1;
}

// ---------------------------------------------------------------------------
// flash attention: block = 4 warps = 4 queries for one (b,h); 32-key tiles.
// Writes directly into the gathered token-major layout (OGAT).
#define QTILES 170   // ceil(677/4)
__global__ void k_attn(const int* __restrict__ valid) {
    __shared__ float Qs[4][64];
    __shared__ float Ks[32][65];
    __shared__ float Vs[32][64];
    __shared__ int   sVal[LL];

    int tid = threadIdx.x;
    int w = tid >> 5, lane = tid & 31;
    int bh = blockIdx.x / QTILES;
    int qt = blockIdx.x % QTILES;
    int b = bh >> 3, h = bh & 7;
    int l = qt * 4 + w;
    bool qok = l < LL;

    for (int m = tid; m < LL; m += 128) sVal[m] = valid[b * LL + m];

    long hbase = (long)bh * LL * HD;
    if (qok) {
        Qs[w][lane]      = d_arena[OFF_QA + hbase + (long)l * HD + lane];
        Qs[w][lane + 32] = d_arena[OFF_QA + hbase + (long)l * HD + lane + 32];
    }
    __syncthreads();
    int qv = qok ? sVal[l] : 0;

    float mrun = -INFINITY, lrun = 0.f, o0 = 0.f, o1 = 0.f;

    for (int kb = 0; kb < LL; kb += 32) {
        for (int e = tid; e < 512; e += 128) {   // 32 keys * 16 float4
            int j = e >> 4;
            int d4 = (e & 15) << 2;
            float4 kv = make_float4(0.f, 0.f, 0.f, 0.f);
            float4 vv = kv;
            int m = kb + j;
            if (m < LL) {
                long p = hbase + (long)m * HD + d4;
                kv = *(const float4*)&d_arena[OFF_KA + p];
                vv = *(const float4*)&d_arena[OFF_VA + p];
            }
            Ks[j][d4 + 0] = kv.x; Ks[j][d4 + 1] = kv.y;
            Ks[j][d4 + 2] = kv.z; Ks[j][d4 + 3] = kv.w;
            *(float4*)&Vs[j][d4] = vv;
        }
        __syncthreads();

        if (qok) {
            int m = kb + lane;
            float acc = 0.f;
#pragma unroll
            for (int d = 0; d < 64; d += 4) {
                acc += Qs[w][d] * Ks[lane][d]
                     + Qs[w][d + 1] * Ks[lane][d + 1]
                     + Qs[w][d + 2] * Ks[lane][d + 2]
                     + Qs[w][d + 3] * Ks[lane][d + 3];
            }
            bool ok = (m < LL) && (((qv != 0) && (sVal[m] != 0)) || (m == l));
            float sc = ok ? acc * 0.125f : -INFINITY;

            float mt = sc;
#pragma unroll
            for (int off = 16; off; off >>= 1) mt = fmaxf(mt, __shfl_xor_sync(~0u, mt, off));
            float nm = fmaxf(mrun, mt);
            if (nm > -INFINITY) {
                float corr = __expf(mrun - nm);
                lrun *= corr; o0 *= corr; o1 *= corr;
                float p = (sc > -INFINITY) ? __expf(sc - nm) : 0.f;
                float ps = p;
#pragma unroll
                for (int off = 16; off; off >>= 1) ps += __shfl_xor_sync(~0u, ps, off);
                lrun += ps;
#pragma unroll
                for (int j = 0; j < 32; j++) {
                    float pj = __shfl_sync(~0u, p, j);
                    o0 += pj * Vs[j][lane];
                    o1 += pj * Vs[j][lane + 32];
                }
                mrun = nm;
            }
        }
        __syncthreads();
    }

    if (qok) {
        float inv = 1.f / lrun;
        int rr;
        if (l < TT)             rr = b * TT + l;
        else if (l < TT + SSRC) rr = 1232 + b * SSRC + (l - TT);
        else                    rr = 6032 + b * NHID + (l - TT - SSRC);
        long op = (long)rr * DM + h * HD;
        d_arena[OFF_OGAT + op + lane]      = o0 * inv;
        d_arena[OFF_OGAT + op + lane + 32] = o1 * inv;
    }
}

// ---------------------------------------------------------------------------
// h = x + g_a * a ; n2 = LN(h)*(1+sc_m)+sh_m
__global__ void k_resln(const float* __restrict__ inp, int istream, int len, long tokOff) {
    int row = blockIdx.x;
    int b = row / len;
    int tid = threadIdx.x;
    long rb = (tokOff + row) * (long)DM;
    const float* ada = d_arena + OFF_ADA + ((long)istream * BB + b) * 3072;

    float4 x4 = *(const float4*)&inp[(long)row * DM + tid * 4];
    float4 a4 = *(const float4*)&d_arena[OFF_ABUF + rb + tid * 4];
    float4 g4 = *(const float4*)&ada[1024 + tid * 4];
    float4 hv;
    hv.x = x4.x + g4.x * a4.x;
    hv.y = x4.y + g4.y * a4.y;
    hv.z = x4.z + g4.z * a4.z;
    hv.w = x4.w + g4.w * a4.w;
    *(float4*)&d_arena[OFF_HBUF + rb + tid * 4] = hv;

    float s = hv.x + hv.y + hv.z + hv.w;
    float q = hv.x * hv.x + hv.y * hv.y + hv.z * hv.z + hv.w * hv.w;
    float mean, ri;
    block_ln_stats(s, q, &mean, &ri);
    float4 sc = *(const float4*)&ada[2048 + tid * 4];
    float4 shv = *(const float4*)&ada[1536 + tid * 4];
    float4 o;
    o.x = (hv.x - mean) * ri * (1.f + sc.x) + shv.x;
    o.y = (hv.y - mean) * ri * (1.f + sc.y) + shv.y;
    o.z = (hv.z - mean) * ri * (1.f + sc.z) + shv.z;
    o.w = (hv.w - mean) * ri * (1.f + sc.w) + shv.w;
    *(float4*)&d_arena[OFF_N2 + rb + tid * 4] = o;
}

// ---------------------------------------------------------------------------
// g = lin * gelu_exact(gate)
__global__ void k_geglu() {
    long idx = (long)blockIdx.x * blockDim.x + threadIdx.x;  // TOKS*512 float4 units
    if (idx >= (long)TOKS * 512) return;
    long rrow = idx >> 9;
    int j4 = (int)(idx & 511) << 2;
    float4 lin = *(const float4*)&d_arena[OFF_U + rrow * 4096 + j4];
    float4 gt  = *(const float4*)&d_arena[OFF_U + rrow * 4096 + 2048 + j4];
    float4 o;
    o.x = lin.x * (0.5f * gt.x * (1.f + erff(gt.x * 0.7071067811865475f)));
    o.y = lin.y * (0.5f * gt.y * (1.f + erff(gt.y * 0.7071067811865475f)));
    o.z = lin.z * (0.5f * gt.z * (1.f + erff(gt.z * 0.7071067811865475f)));
    o.w = lin.w * (0.5f * gt.w * (1.f + erff(gt.w * 0.7071067811865475f)));
    *(float4*)&d_arena[OFF_G + rrow * 2048 + j4] = o;
}

// ---------------------------------------------------------------------------
// out = h + g_m * ff, scattered to concat layout [txt, src, hid]
__global__ void k_final(float* __restrict__ out, int istream, int len, long tokOff, int catOff) {
    int row = blockIdx.x;
    int b = row / len;
    int t = row % len;
    int tid = threadIdx.x;
    long rb = (tokOff + row) * (long)DM;
    const float* ada = d_arena + OFF_ADA + ((long)istream * BB + b) * 3072;
    float4 hv = *(const float4*)&d_arena[OFF_HBUF + rb + tid * 4];
    float4 fv = *(const float4*)&d_arena[OFF_FF + rb + tid * 4];
    float4 gm = *(const float4*)&ada[2560 + tid * 4];
    float4 o;
    o.x = hv.x + gm.x * fv.x;
    o.y = hv.y + gm.y * fv.y;
    o.z = hv.z + gm.z * fv.z;
    o.w = hv.w + gm.w * fv.w;
    *(float4*)&out[((long)b * LL + catOff + t) * DM + tid * 4] = o;
}

// ---------------------------------------------------------------------------
extern "C" void kernel_launch(void* const* d_in, const int* in_sizes, int n_in,
                              void* d_out, int out_size) {
    const float* x     = (const float*)d_in[0];
    const float* src   = (const float*)d_in[1];
    const float* txt   = (const float*)d_in[2];
    const float* temb  = (const float*)d_in[3];
    const float* Wqkv  = (const float*)d_in[4];
    const float* bqkv  = (const float*)d_in[5];
    const float* Wo    = (const float*)d_in[6];
    const float* bo    = (const float*)d_in[7];
    const float* gqk   = (const float*)d_in[8];
    const float* Wada  = (const float*)d_in[9];
    const float* bada  = (const float*)d_in[10];
    const float* Wff1  = (const float*)d_in[11];
    const float* bff1  = (const float*)d_in[12];
    const float* Wff2  = (const float*)d_in[13];
    const float* bff2  = (const float*)d_in[14];
    const float* pos_q = (const float*)d_in[15];
    const float* pos_k = (const float*)d_in[16];
    const int*   valid = (const int*)d_in[17];
    float* out = (float*)d_out;

    // ref-stream metadata: i=0 hidden(x), i=1 src, i=2 txt
    const int  lens[3]    = {NHID, SSRC, TT};
    const long tokOffs[3] = {6032, 1232, 0};
    const int  catOffs[3] = {377, 77, 0};
    const float* inps[3]  = {x, src, txt};

    // 1. silu(temb)
    k_silu<<<(BB * DM + 255) / 256, 256>>>(temb);

    // 2. ada = st @ Wada[s] + bada[s]
    {
        dim3 g(3072 / 64, 1, 3);
        k_gemm<<<g, 256>>>(Wada, bada, OFF_ST, OFF_ADA, BB, 3072, DM,
                           512L * 3072, 3072L, 16L * 3072);
    }

    // 3. modulated LN per stream
    for (int i = 0; i < 3; i++)
        k_modln<<<BB * lens[i], 128>>>(inps[i], i, lens[i], tokOffs[i]);

    // 4. QKV GEMMs (z over q,k,v)
    for (int i = 0; i < 3; i++) {
        int M = BB * lens[i];
        dim3 g(DM / 64, (M + 63) / 64, 3);
        k_gemm<<<g, 256>>>(Wqkv + (long)i * 3 * DM * DM, bqkv + (long)i * 3 * DM,
                           OFF_NBUF + tokOffs[i] * DM, OFF_QKV + tokOffs[i] * DM,
                           M, DM, DM, (long)DM * DM, (long)DM, (long)TOKS * DM);
    }

    // 5. RMS + RoPE/pos, scatter to [B,H,L,64]
    k_qkvx<<<(BB * LL * NH) / 4, 128>>>(gqk, pos_q, pos_k);

    // 6. attention
    k_attn<<<BB * NH * QTILES, 128>>>(valid);

    // 7. output projection
    for (int i = 0; i < 3; i++) {
        int M = BB * lens[i];
        dim3 g(DM / 64, (M + 63) / 64, 1);
        k_gemm<<<g, 256>>>(Wo + (long)i * DM * DM, bo + (long)i * DM,
                           OFF_OGAT + tokOffs[i] * DM, OFF_ABUF + tokOffs[i] * DM,
                           M, DM, DM, 0, 0, 0);
    }

    // 8. residual + LN2 (modulated)
    for (int i = 0; i < 3; i++)
        k_resln<<<BB * lens[i], 128>>>(inps[i], i, lens[i], tokOffs[i]);

    // 9. FF1
    for (int i = 0; i < 3; i++) {
        int M = BB * lens[i];
        dim3 g(4096 / 64, (M + 63) / 64, 1);
        k_gemm<<<g, 256>>>(Wff1 + (long)i * DM * 4096, bff1 + (long)i * 4096,
                           OFF_N2 + tokOffs[i] * DM, OFF_U + tokOffs[i] * 4096,
                           M, 4096, DM, 0, 0, 0);
    }

    // 10. GeGLU gate
    k_geglu<<<(int)(((long)TOKS * 512 + 255) / 256), 256>>>();

    // 11. FF2
    for (int i = 0; i < 3; i++) {
        int M = BB * lens[i];
        dim3 g(DM / 64, (M + 63) / 64, 1);
        k_gemm<<<g, 256>>>(Wff2 + (long)i * 2048 * DM, bff2 + (long)i * DM,
                           OFF_G + tokOffs[i] * 2048, OFF_FF + tokOffs[i] * DM,
                           M, DM, 2048, 0, 0, 0);
    }

    // 12. final residual + scatter to output concat layout
    for (int i = 0; i < 3; i++)
        k_final<<<BB * lens[i], 128>>>(out, i, lens[i], tokOffs[i], catOffs[i]);
}

// round 3
// speedup vs baseline: 1.5391x; 1.5391x over previous
#include <cuda_runtime.h>
#include <math.h>
#include <stdint.h>

#define BB 16
#define TT 77
#define SSRC 300
#define NHID 300
#define LL 677
#define DM 512
#define NH 8
#define HD 64
#define TOKS 10832   // 16*77 + 16*300 + 16*300

// ----- scratch arena (floats) -----
#define OFF_ST    0L
#define OFF_ADA   8192L         // 3*16*3072 = 147456
#define OFF_NBUF  155648L       // TOKS*512
#define OFF_QKV   5701632L      // 3 * TOKS*512
#define OFF_QA    22339584L     // [B,H,L,64]
#define OFF_KA    27885568L
#define OFF_VA    33431552L
#define OFF_OGAT  38977536L     // gathered attn out, token-major [TOKS,512]
#define OFF_ABUF  44523520L
#define OFF_HBUF  50069504L
#define OFF_N2    55615488L
#define OFF_U     61161472L     // TOKS*4096
#define OFF_G     105529344L    // TOKS*2048
#define OFF_FF    127713280L
#define ARENA_SZ  133259264L

__device__ float d_arena[ARENA_SZ];

// ---------------------------------------------------------------------------
__global__ void k_silu(const float* __restrict__ temb) {
    int i = blockIdx.x * blockDim.x + threadIdx.x;
    if (i < BB * DM) {
        float v = temb[i];
        d_arena[OFF_ST + i] = v / (1.f + __expf(-v));
    }
}

// ---------------------------------------------------------------------------
// small SIMT GEMM, kept only for the tiny ada projection (M=16)
__global__ void k_gemm(const float* __restrict__ Bmat, const float* __restrict__ bias,
                       long offA, long offC, int M, int N, int K,
                       long szB, long szBias, long szC) {
    const float* A  = d_arena + offA;
    const float* Bm = Bmat + (long)blockIdx.z * szB;
    const float* bi = bias + (long)blockIdx.z * szBias;
    float*       C  = d_arena + offC + (long)blockIdx.z * szC;

    __shared__ float As[16][68];
    __shared__ float Bs[16][64];

    int tid = threadIdx.x;
    int tx = tid & 15, ty = tid >> 4;

    int arow = tid >> 2;
    int akc  = (tid & 3) << 2;
    int brow = tid >> 4;
    int bcol = (tid & 15) << 2;

    long grow  = (long)blockIdx.y * 64 + arow;
    int  gcolB = blockIdx.x * 64 + bcol;

    float acc[4][4];
#pragma unroll
    for (int i = 0; i < 4; i++)
#pragma unroll
        for (int j = 0; j < 4; j++) acc[i][j] = 0.f;

    for (int kt = 0; kt < K; kt += 16) {
        float4 a4 = make_float4(0.f, 0.f, 0.f, 0.f);
        if (grow < M) a4 = *(const float4*)&A[grow * K + kt + akc];
        As[akc + 0][arow] = a4.x;
        As[akc + 1][arow] = a4.y;
        As[akc + 2][arow] = a4.z;
        As[akc + 3][arow] = a4.w;

        float4 b4 = *(const float4*)&Bm[(long)(kt + brow) * N + gcolB];
        *(float4*)&Bs[brow][bcol] = b4;
        __syncthreads();

#pragma unroll
        for (int k = 0; k < 16; k++) {
            float4 av = *(const float4*)&As[k][ty << 2];
            float4 bv = *(const float4*)&Bs[k][tx << 2];
            float a[4] = {av.x, av.y, av.z, av.w};
            float b[4] = {bv.x, bv.y, bv.z, bv.w};
#pragma unroll
            for (int i = 0; i < 4; i++)
#pragma unroll
                for (int j = 0; j < 4; j++) acc[i][j] += a[i] * b[j];
        }
        __syncthreads();
    }

    int crow0 = blockIdx.y * 64 + (ty << 2);
    int ccol0 = blockIdx.x * 64 + (tx << 2);
    float4 bi4 = *(const float4*)&bi[ccol0];
#pragma unroll
    for (int i = 0; i < 4; i++) {
        if (crow0 + i < M) {
            float4 o;
            o.x = acc[i][0] + bi4.x;
            o.y = acc[i][1] + bi4.y;
            o.z = acc[i][2] + bi4.z;
            o.w = acc[i][3] + bi4.w;
            *(float4*)&C[(long)(crow0 + i) * N + ccol0] = o;
        }
    }
}

// ---------------------------------------------------------------------------
// tf32 tensor-core GEMM: C = A @ B + bias
// block tile 128x128, K-tile 16, 8 warps (4m x 2n), warp tile 32x64,
// mma.sync.m16n8k8.tf32, double-buffered smem, reg-staged prefetch.
#define A_PAD 20
#define B_PAD 136

__device__ __forceinline__ float tf32r(float x) {
    uint32_t u;
    asm("cvt.rna.tf32.f32 %0, %1;" : "=r"(u) : "f"(x));
    return __uint_as_float(u);
}

__device__ __forceinline__ void mma_tf32(float c[4], const uint32_t a[4], const uint32_t b[2]) {
    asm volatile(
        "mma.sync.aligned.m16n8k8.row.col.f32.tf32.tf32.f32 "
        "{%0,%1,%2,%3},{%4,%5,%6,%7},{%8,%9},{%0,%1,%2,%3};"
        : "+f"(c[0]), "+f"(c[1]), "+f"(c[2]), "+f"(c[3])
        : "r"(a[0]), "r"(a[1]), "r"(a[2]), "r"(a[3]), "r"(b[0]), "r"(b[1]));
}

__global__ void __launch_bounds__(256, 2)
k_gemm_tc(const float* __restrict__ Bmat, const float* __restrict__ bias,
          long offA, long offC, int M, int N, int K,
          long szB, long szBias, long szC) {
    const float* A  = d_arena + offA;
    const float* Bm = Bmat + (long)blockIdx.z * szB;
    const float* bi = bias + (long)blockIdx.z * szBias;
    float*       C  = d_arena + offC + (long)blockIdx.z * szC;

    __shared__ float As[2][128][A_PAD];
    __shared__ float Bs[2][16][B_PAD];

    int tid  = threadIdx.x;
    int lane = tid & 31, wid = tid >> 5;
    int wm = wid & 3, wn = wid >> 2;       // warp grid 4 (m) x 2 (n)
    int g  = lane >> 2, tg = lane & 3;

    int m0 = blockIdx.y * 128;
    int n0 = blockIdx.x * 128;

    int ar = tid >> 1;            // A stage: row 0..127
    int ak = (tid & 1) << 3;      // A stage: k 0 or 8
    int bk = tid >> 4;            // B stage: k 0..15
    int bn = (tid & 15) << 2;     // B stage: n 0..60 (and +64)

    float acc[2][8][4];
#pragma unroll
    for (int mi = 0; mi < 2; mi++)
#pragma unroll
        for (int ni = 0; ni < 8; ni++)
#pragma unroll
            for (int r = 0; r < 4; r++) acc[mi][ni][r] = 0.f;

    int nk = K >> 4;

    // stage tile 0 into buffer 0
    {
        long grow = m0 + ar;
        float4 a0 = make_float4(0.f, 0.f, 0.f, 0.f), a1 = a0;
        if (grow < M) {
            a0 = *(const float4*)&A[grow * K + ak];
            a1 = *(const float4*)&A[grow * K + ak + 4];
        }
        As[0][ar][ak + 0] = tf32r(a0.x); As[0][ar][ak + 1] = tf32r(a0.y);
        As[0][ar][ak + 2] = tf32r(a0.z); As[0][ar][ak + 3] = tf32r(a0.w);
        As[0][ar][ak + 4] = tf32r(a1.x); As[0][ar][ak + 5] = tf32r(a1.y);
        As[0][ar][ak + 6] = tf32r(a1.z); As[0][ar][ak + 7] = tf32r(a1.w);

        float4 b0 = *(const float4*)&Bm[(long)bk * N + n0 + bn];
        float4 b1 = *(const float4*)&Bm[(long)bk * N + n0 + bn + 64];
        Bs[0][bk][bn + 0]  = tf32r(b0.x); Bs[0][bk][bn + 1]  = tf32r(b0.y);
        Bs[0][bk][bn + 2]  = tf32r(b0.z); Bs[0][bk][bn + 3]  = tf32r(b0.w);
        Bs[0][bk][bn + 64] = tf32r(b1.x); Bs[0][bk][bn + 65] = tf32r(b1.y);
        Bs[0][bk][bn + 66] = tf32r(b1.z); Bs[0][bk][bn + 67] = tf32r(b1.w);
    }
    __syncthreads();

    int cur = 0;
    for (int kt = 0; kt < nk; kt++) {
        float4 pa0, pa1, pb0, pb1;
        bool has = (kt + 1) < nk;
        if (has) {
            long grow = m0 + ar;
            int kbase = (kt + 1) << 4;
            pa0 = make_float4(0.f, 0.f, 0.f, 0.f); pa1 = pa0;
            if (grow < M) {
                pa0 = *(const float4*)&A[grow * K + kbase + ak];
                pa1 = *(const float4*)&A[grow * K + kbase + ak + 4];
            }
            pb0 = *(const float4*)&Bm[(long)(kbase + bk) * N + n0 + bn];
            pb1 = *(const float4*)&Bm[(long)(kbase + bk) * N + n0 + bn + 64];
        }

#pragma unroll
        for (int k0 = 0; k0 < 16; k0 += 8) {
            uint32_t af[2][4];
#pragma unroll
            for (int mi = 0; mi < 2; mi++) {
                int r = wm * 32 + mi * 16 + g;
                af[mi][0] = __float_as_uint(As[cur][r][k0 + tg]);
                af[mi][1] = __float_as_uint(As[cur][r + 8][k0 + tg]);
                af[mi][2] = __float_as_uint(As[cur][r][k0 + tg + 4]);
                af[mi][3] = __float_as_uint(As[cur][r + 8][k0 + tg + 4]);
            }
            uint32_t bf[8][2];
#pragma unroll
            for (int ni = 0; ni < 8; ni++) {
                int cn = wn * 64 + ni * 8 + g;
                bf[ni][0] = __float_as_uint(Bs[cur][k0 + tg][cn]);
                bf[ni][1] = __float_as_uint(Bs[cur][k0 + tg + 4][cn]);
            }
#pragma unroll
            for (int mi = 0; mi < 2; mi++)
#pragma unroll
                for (int ni = 0; ni < 8; ni++)
                    mma_tf32(acc[mi][ni], af[mi], bf[ni]);
        }

        if (has) {
            int nxt = cur ^ 1;
            As[nxt][ar][ak + 0] = tf32r(pa0.x); As[nxt][ar][ak + 1] = tf32r(pa0.y);
            As[nxt][ar][ak + 2] = tf32r(pa0.z); As[nxt][ar][ak + 3] = tf32r(pa0.w);
            As[nxt][ar][ak + 4] = tf32r(pa1.x); As[nxt][ar][ak + 5] = tf32r(pa1.y);
            As[nxt][ar][ak + 6] = tf32r(pa1.z); As[nxt][ar][ak + 7] = tf32r(pa1.w);
            Bs[nxt][bk][bn + 0]  = tf32r(pb0.x); Bs[nxt][bk][bn + 1]  = tf32r(pb0.y);
            Bs[nxt][bk][bn + 2]  = tf32r(pb0.z); Bs[nxt][bk][bn + 3]  = tf32r(pb0.w);
            Bs[nxt][bk][bn + 64] = tf32r(pb1.x); Bs[nxt][bk][bn + 65] = tf32r(pb1.y);
            Bs[nxt][bk][bn + 66] = tf32r(pb1.z); Bs[nxt][bk][bn + 67] = tf32r(pb1.w);
        }
        __syncthreads();
        cur ^= 1;
    }

    // epilogue: acc + bias -> C
#pragma unroll
    for (int mi = 0; mi < 2; mi++) {
        int row = m0 + wm * 32 + mi * 16 + g;
#pragma unroll
        for (int ni = 0; ni < 8; ni++) {
            int col = n0 + wn * 64 + ni * 8 + tg * 2;
            float bx = bi[col], by = bi[col + 1];
            if (row < M) {
                float2 o = make_float2(acc[mi][ni][0] + bx, acc[mi][ni][1] + by);
                *(float2*)&C[(long)row * N + col] = o;
            }
            if (row + 8 < M) {
                float2 o = make_float2(acc[mi][ni][2] + bx, acc[mi][ni][3] + by);
                *(float2*)&C[(long)(row + 8) * N + col] = o;
            }
        }
    }
}

// ---------------------------------------------------------------------------
__device__ __forceinline__ void block_ln_stats(float s, float q, float* mean, float* ri) {
    __shared__ float sh[8];
    int lane = threadIdx.x & 31, wid = threadIdx.x >> 5;
#pragma unroll
    for (int off = 16; off; off >>= 1) {
        s += __shfl_xor_sync(~0u, s, off);
        q += __shfl_xor_sync(~0u, q, off);
    }
    if (lane == 0) { sh[wid] = s; sh[4 + wid] = q; }
    __syncthreads();
    if (threadIdx.x == 0) {
        float S = sh[0] + sh[1] + sh[2] + sh[3];
        float Q = sh[4] + sh[5] + sh[6] + sh[7];
        float m = S * (1.f / 512.f);
        float v = Q * (1.f / 512.f) - m * m;
        sh[0] = m;
        sh[1] = rsqrtf(v + 1e-6f);
    }
    __syncthreads();
    *mean = sh[0];
    *ri   = sh[1];
}

__global__ void k_modln(const float* __restrict__ inp, int istream, int len, long tokOff) {
    int row = blockIdx.x;
    int b = row / len;
    int tid = threadIdx.x;
    float4 v = *(const float4*)&inp[(long)row * DM + tid * 4];
    float s = v.x + v.y + v.z + v.w;
    float q = v.x * v.x + v.y * v.y + v.z * v.z + v.w * v.w;
    float mean, ri;
    block_ln_stats(s, q, &mean, &ri);
    const float* ada = d_arena + OFF_ADA + ((long)istream * BB + b) * 3072;
    float4 sc = *(const float4*)&ada[512 + tid * 4];
    float4 shv = *(const float4*)&ada[tid * 4];
    float4 o;
    o.x = (v.x - mean) * ri * (1.f + sc.x) + shv.x;
    o.y = (v.y - mean) * ri * (1.f + sc.y) + shv.y;
    o.z = (v.z - mean) * ri * (1.f + sc.z) + shv.z;
    o.w = (v.w - mean) * ri * (1.f + sc.w) + shv.w;
    *(float4*)&d_arena[OFF_NBUF + (tokOff + row) * DM + tid * 4] = o;
}

// ---------------------------------------------------------------------------
__global__ void k_qkvx(const float* __restrict__ gqk,
                       const float* __restrict__ pos_q,
                       const float* __restrict__ pos_k) {
    int w = threadIdx.x >> 5;
    int lane = threadIdx.x & 31;
    int g = blockIdx.x * 4 + w;
    int h = g & 7;
    int bl = g >> 3;
    int l = bl % LL;
    int b = bl / LL;

    int istream, t;
    long r;
    if (l < TT)            { istream = 2; t = l;            r = (long)b * TT + t; }
    else if (l < TT + SSRC){ istream = 1; t = l - TT;       r = 1232 + (long)b * SSRC + t; }
    else                   { istream = 0; t = l - TT - SSRC; r = 6032 + (long)b * NHID + t; }

    long base = r * DM + h * HD;
    float q0 = d_arena[OFF_QKV + base + lane];
    float q1 = d_arena[OFF_QKV + base + lane + 32];
    float k0 = d_arena[OFF_QKV + (long)TOKS * DM + base + lane];
    float k1 = d_arena[OFF_QKV + (long)TOKS * DM + base + lane + 32];
    float v0 = d_arena[OFF_QKV + 2L * TOKS * DM + base + lane];
    float v1 = d_arena[OFF_QKV + 2L * TOKS * DM + base + lane + 32];

    float sq = q0 * q0 + q1 * q1;
    float sk = k0 * k0 + k1 * k1;
#pragma unroll
    for (int off = 16; off; off >>= 1) {
        sq += __shfl_xor_sync(~0u, sq, off);
        sk += __shfl_xor_sync(~0u, sk, off);
    }
    float rq = rsqrtf(sq * (1.f / 64.f) + 1e-6f);
    float rk = rsqrtf(sk * (1.f / 64.f) + 1e-6f);
    q0 *= rq * gqk[(istream * 2 + 0) * 64 + lane];
    q1 *= rq * gqk[(istream * 2 + 0) * 64 + lane + 32];
    k0 *= rk * gqk[(istream * 2 + 1) * 64 + lane];
    k1 *= rk * gqk[(istream * 2 + 1) * 64 + lane + 32];

    if (istream == 2) {
        q0 += pos_q[t * 64 + lane];
        q1 += pos_q[t * 64 + lane + 32];
        k0 += pos_k[t * 64 + lane];
        k1 += pos_k[t * 64 + lane + 32];
    } else {
        float rq0 = __shfl_xor_sync(~0u, q0, 1);
        float rq1 = __shfl_xor_sync(~0u, q1, 1);
        float rk0 = __shfl_xor_sync(~0u, k0, 1);
        float rk1 = __shfl_xor_sync(~0u, k1, 1);
        float tf = (float)t;
        float pw = (tf - 150.f) * (1.f / 512.f);
        {
            int d = lane, ii = d >> 1;
            float inv = powf(10000.f, -(float)(2 * ii) * (1.f / 64.f));
            float ang = tf * inv;
            float c = cosf(ang), s = sinf(ang);
            float scl = powf(((float)(2 * ii) + 25.6f) * (1.f / 89.6f), pw);
            float rotq = (d & 1) ? rq0 : -rq0;
            float rotk = (d & 1) ? rk0 : -rk0;
            q0 = q0 * (c * scl) + rotq * (s * scl);
            k0 = k0 * (c / scl) + rotk * (s / scl);
        }
        {
            int d = lane + 32, ii = d >> 1;
            float inv = powf(10000.f, -(float)(2 * ii) * (1.f / 64.f));
            float ang = tf * inv;
            float c = cosf(ang), s = sinf(ang);
            float scl = powf(((float)(2 * ii) + 25.6f) * (1.f / 89.6f), pw);
            float rotq = (d & 1) ? rq1 : -rq1;
            float rotk = (d & 1) ? rk1 : -rk1;
            q1 = q1 * (c * scl) + rotq * (s * scl);
            k1 = k1 * (c / scl) + rotk * (s / scl);
        }
    }

    long o = (((long)(b * NH + h)) * LL + l) * HD;
    d_arena[OFF_QA + o + lane]      = q0;
    d_arena[OFF_QA + o + lane + 32] = q1;
    d_arena[OFF_KA + o + lane]      = k0;
    d_arena[OFF_KA + o + lane + 32] = k1;
    d_arena[OFF_VA + o + lane]      = v0;
    d_arena[OFF_VA + o + lane + 32] = v1;
}

// ---------------------------------------------------------------------------
#define QTILES 170
__global__ void k_attn(const int* __restrict__ valid) {
    __shared__ float Qs[4][64];
    __shared__ float Ks[32][65];
    __shared__ float Vs[32][64];
    __shared__ int   sVal[LL];

    int tid = threadIdx.x;
    int w = tid >> 5, lane = tid & 31;
    int bh = blockIdx.x / QTILES;
    int qt = blockIdx.x % QTILES;
    int b = bh >> 3;
    int l = qt * 4 + w;
    bool qok = l < LL;

    for (int m = tid; m < LL; m += 128) sVal[m] = valid[b * LL + m];

    long hbase = (long)bh * LL * HD;
    if (qok) {
        Qs[w][lane]      = d_arena[OFF_QA + hbase + (long)l * HD + lane];
        Qs[w][lane + 32] = d_arena[OFF_QA + hbase + (long)l * HD + lane + 32];
    }
    __syncthreads();
    int qv = qok ? sVal[l] : 0;

    float mrun = -INFINITY, lrun = 0.f, o0 = 0.f, o1 = 0.f;

    for (int kb = 0; kb < LL; kb += 32) {
        for (int e = tid; e < 512; e += 128) {
            int j = e >> 4;
            int d4 = (e & 15) << 2;
            float4 kv = make_float4(0.f, 0.f, 0.f, 0.f);
            float4 vv = kv;
            int m = kb + j;
            if (m < LL) {
                long p = hbase + (long)m * HD + d4;
                kv = *(const float4*)&d_arena[OFF_KA + p];
                vv = *(const float4*)&d_arena[OFF_VA + p];
            }
            Ks[j][d4 + 0] = kv.x; Ks[j][d4 + 1] = kv.y;
            Ks[j][d4 + 2] = kv.z; Ks[j][d4 + 3] = kv.w;
            *(float4*)&Vs[j][d4] = vv;
        }
        __syncthreads();

        if (qok) {
            int m = kb + lane;
            float acc = 0.f;
#pragma unroll
            for (int d = 0; d < 64; d += 4) {
                acc += Qs[w][d] * Ks[lane][d]
                     + Qs[w][d + 1] * Ks[lane][d + 1]
                     + Qs[w][d + 2] * Ks[lane][d + 2]
                     + Qs[w][d + 3] * Ks[lane][d + 3];
            }
            bool ok = (m < LL) && (((qv != 0) && (sVal[m] != 0)) || (m == l));
            float sc = ok ? acc * 0.125f : -INFINITY;

            float mt = sc;
#pragma unroll
            for (int off = 16; off; off >>= 1) mt = fmaxf(mt, __shfl_xor_sync(~0u, mt, off));
            float nm = fmaxf(mrun, mt);
            if (nm > -INFINITY) {
                float corr = __expf(mrun - nm);
                lrun *= corr; o0 *= corr; o1 *= corr;
                float p = (sc > -INFINITY) ? __expf(sc - nm) : 0.f;
                float ps = p;
#pragma unroll
                for (int off = 16; off; off >>= 1) ps += __shfl_xor_sync(~0u, ps, off);
                lrun += ps;
#pragma unroll
                for (int j = 0; j < 32; j++) {
                    float pj = __shfl_sync(~0u, p, j);
                    o0 += pj * Vs[j][lane];
                    o1 += pj * Vs[j][lane + 32];
                }
                mrun = nm;
            }
        }
        __syncthreads();
    }

    if (qok) {
        float inv = 1.f / lrun;
        int rr;
        if (l < TT)             rr = b * TT + l;
        else if (l < TT + SSRC) rr = 1232 + b * SSRC + (l - TT);
        else                    rr = 6032 + b * NHID + (l - TT - SSRC);
        long op = (long)rr * DM + (bh & 7) * HD;
        d_arena[OFF_OGAT + op + lane]      = o0 * inv;
        d_arena[OFF_OGAT + op + lane + 32] = o1 * inv;
    }
}

// ---------------------------------------------------------------------------
__global__ void k_resln(const float* __restrict__ inp, int istream, int len, long tokOff) {
    int row = blockIdx.x;
    int b = row / len;
    int tid = threadIdx.x;
    long rb = (tokOff + row) * (long)DM;
    const float* ada = d_arena + OFF_ADA + ((long)istream * BB + b) * 3072;

    float4 x4 = *(const float4*)&inp[(long)row * DM + tid * 4];
    float4 a4 = *(const float4*)&d_arena[OFF_ABUF + rb + tid * 4];
    float4 g4 = *(const float4*)&ada[1024 + tid * 4];
    float4 hv;
    hv.x = x4.x + g4.x * a4.x;
    hv.y = x4.y + g4.y * a4.y;
    hv.z = x4.z + g4.z * a4.z;
    hv.w = x4.w + g4.w * a4.w;
    *(float4*)&d_arena[OFF_HBUF + rb + tid * 4] = hv;

    float s = hv.x + hv.y + hv.z + hv.w;
    float q = hv.x * hv.x + hv.y * hv.y + hv.z * hv.z + hv.w * hv.w;
    float mean, ri;
    block_ln_stats(s, q, &mean, &ri);
    float4 sc = *(const float4*)&ada[2048 + tid * 4];
    float4 shv = *(const float4*)&ada[1536 + tid * 4];
    float4 o;
    o.x = (hv.x - mean) * ri * (1.f + sc.x) + shv.x;
    o.y = (hv.y - mean) * ri * (1.f + sc.y) + shv.y;
    o.z = (hv.z - mean) * ri * (1.f + sc.z) + shv.z;
    o.w = (hv.w - mean) * ri * (1.f + sc.w) + shv.w;
    *(float4*)&d_arena[OFF_N2 + rb + tid * 4] = o;
}

// ---------------------------------------------------------------------------
__global__ void k_geglu() {
    long idx = (long)blockIdx.x * blockDim.x + threadIdx.x;
    if (idx >= (long)TOKS * 512) return;
    long rrow = idx >> 9;
    int j4 = (int)(idx & 511) << 2;
    float4 lin = *(const float4*)&d_arena[OFF_U + rrow * 4096 + j4];
    float4 gt  = *(const float4*)&d_arena[OFF_U + rrow * 4096 + 2048 + j4];
    float4 o;
    o.x = lin.x * (0.5f * gt.x * (1.f + erff(gt.x * 0.7071067811865475f)));
    o.y = lin.y * (0.5f * gt.y * (1.f + erff(gt.y * 0.7071067811865475f)));
    o.z = lin.z * (0.5f * gt.z * (1.f + erff(gt.z * 0.7071067811865475f)));
    o.w = lin.w * (0.5f * gt.w * (1.f + erff(gt.w * 0.7071067811865475f)));
    *(float4*)&d_arena[OFF_G + rrow * 2048 + j4] = o;
}

// ---------------------------------------------------------------------------
__global__ void k_final(float* __restrict__ out, int istream, int len, long tokOff, int catOff) {
    int row = blockIdx.x;
    int b = row / len;
    int t = row % len;
    int tid = threadIdx.x;
    long rb = (tokOff + row) * (long)DM;
    const float* ada = d_arena + OFF_ADA + ((long)istream * BB + b) * 3072;
    float4 hv = *(const float4*)&d_arena[OFF_HBUF + rb + tid * 4];
    float4 fv = *(const float4*)&d_arena[OFF_FF + rb + tid * 4];
    float4 gm = *(const float4*)&ada[2560 + tid * 4];
    float4 o;
    o.x = hv.x + gm.x * fv.x;
    o.y = hv.y + gm.y * fv.y;
    o.z = hv.z + gm.z * fv.z;
    o.w = hv.w + gm.w * fv.w;
    *(float4*)&out[((long)b * LL + catOff + t) * DM + tid * 4] = o;
}

// ---------------------------------------------------------------------------
extern "C" void kernel_launch(void* const* d_in, const int* in_sizes, int n_in,
                              void* d_out, int out_size) {
    const float* x     = (const float*)d_in[0];
    const float* src   = (const float*)d_in[1];
    const float* txt   = (const float*)d_in[2];
    const float* temb  = (const float*)d_in[3];
    const float* Wqkv  = (const float*)d_in[4];
    const float* bqkv  = (const float*)d_in[5];
    const float* Wo    = (const float*)d_in[6];
    const float* bo    = (const float*)d_in[7];
    const float* gqk   = (const float*)d_in[8];
    const float* Wada  = (const float*)d_in[9];
    const float* bada  = (const float*)d_in[10];
    const float* Wff1  = (const float*)d_in[11];
    const float* bff1  = (const float*)d_in[12];
    const float* Wff2  = (const float*)d_in[13];
    const float* bff2  = (const float*)d_in[14];
    const float* pos_q = (const float*)d_in[15];
    const float* pos_k = (const float*)d_in[16];
    const int*   valid = (const int*)d_in[17];
    float* out = (float*)d_out;

    const int  lens[3]    = {NHID, SSRC, TT};
    const long tokOffs[3] = {6032, 1232, 0};
    const int  catOffs[3] = {377, 77, 0};
    const float* inps[3]  = {x, src, txt};

    // 1. silu(temb)
    k_silu<<<(BB * DM + 255) / 256, 256>>>(temb);

    // 2. ada = st @ Wada[s] + bada[s]  (tiny M=16 -> SIMT gemm)
    {
        dim3 g(3072 / 64, 1, 3);
        k_gemm<<<g, 256>>>(Wada, bada, OFF_ST, OFF_ADA, BB, 3072, DM,
                           512L * 3072, 3072L, 16L * 3072);
    }

    // 3. modulated LN per stream
    for (int i = 0; i < 3; i++)
        k_modln<<<BB * lens[i], 128>>>(inps[i], i, lens[i], tokOffs[i]);

    // 4. QKV GEMMs (z over q,k,v) -- tensor cores
    for (int i = 0; i < 3; i++) {
        int M = BB * lens[i];
        dim3 g(DM / 128, (M + 127) / 128, 3);
        k_gemm_tc<<<g, 256>>>(Wqkv + (long)i * 3 * DM * DM, bqkv + (long)i * 3 * DM,
                              OFF_NBUF + tokOffs[i] * DM, OFF_QKV + tokOffs[i] * DM,
                              M, DM, DM, (long)DM * DM, (long)DM, (long)TOKS * DM);
    }

    // 5. RMS + RoPE/pos, scatter to [B,H,L,64]
    k_qkvx<<<(BB * LL * NH) / 4, 128>>>(gqk, pos_q, pos_k);

    // 6. attention
    k_attn<<<BB * NH * QTILES, 128>>>(valid);

    // 7. output projection -- tensor cores
    for (int i = 0; i < 3; i++) {
        int M = BB * lens[i];
        dim3 g(DM / 128, (M + 127) / 128, 1);
        k_gemm_tc<<<g, 256>>>(Wo + (long)i * DM * DM, bo + (long)i * DM,
                              OFF_OGAT + tokOffs[i] * DM, OFF_ABUF + tokOffs[i] * DM,
                              M, DM, DM, 0, 0, 0);
    }

    // 8. residual + LN2 (modulated)
    for (int i = 0; i < 3; i++)
        k_resln<<<BB * lens[i], 128>>>(inps[i], i, lens[i], tokOffs[i]);

    // 9. FF1 -- tensor cores
    for (int i = 0; i < 3; i++) {
        int M = BB * lens[i];
        dim3 g(4096 / 128, (M + 127) / 128, 1);
        k_gemm_tc<<<g, 256>>>(Wff1 + (long)i * DM * 4096, bff1 + (long)i * 4096,
                              OFF_N2 + tokOffs[i] * DM, OFF_U + tokOffs[i] * 4096,
                              M, 4096, DM, 0, 0, 0);
    }

    // 10. GeGLU gate
    k_geglu<<<(int)(((long)TOKS * 512 + 255) / 256), 256>>>();

    // 11. FF2 -- tensor cores
    for (int i = 0; i < 3; i++) {
        int M = BB * lens[i];
        dim3 g(DM / 128, (M + 127) / 128, 1);
        k_gemm_tc<<<g, 256>>>(Wff2 + (long)i * 2048 * DM, bff2 + (long)i * DM,
                              OFF_G + tokOffs[i] * 2048, OFF_FF + tokOffs[i] * DM,
                              M, DM, 2048, 0, 0, 0);
    }

    // 12. final residual + scatter to output concat layout
    for (int i = 0; i < 3; i++)
        k_final<<<BB * lens[i], 128>>>(out, i, lens[i], tokOffs[i], catOffs[i]);
}

// round 5
// speedup vs baseline: 3.3561x; 2.1806x over previous
#include <cuda_runtime.h>
#include <math.h>
#include <stdint.h>

#define BB 16
#define TT 77
#define SSRC 300
#define NHID 300
#define LL 677
#define DM 512
#define NH 8
#define HD 64
#define TOKS 10832   // 16*77 + 16*300 + 16*300

// ----- scratch arena (floats) -----
#define OFF_ST    0L
#define OFF_ADA   8192L
#define OFF_NBUF  155648L
#define OFF_QKV   5701632L
#define OFF_QA    22339584L
#define OFF_KA    27885568L
#define OFF_VA    33431552L
#define OFF_OGAT  38977536L
#define OFF_ABUF  44523520L
#define OFF_HBUF  50069504L
#define OFF_N2    55615488L
#define OFF_U     61161472L
#define OFF_G     105529344L
#define OFF_FF    127713280L
#define ARENA_SZ  133259264L

__device__ float d_arena[ARENA_SZ];

// ---------------------------------------------------------------------------
__global__ void k_silu(const float* __restrict__ temb) {
    int i = blockIdx.x * blockDim.x + threadIdx.x;
    if (i < BB * DM) {
        float v = temb[i];
        d_arena[OFF_ST + i] = v / (1.f + __expf(-v));
    }
}

// ---------------------------------------------------------------------------
// small SIMT GEMM for the tiny ada projection (M=16)
__global__ void k_gemm(const float* __restrict__ Bmat, const float* __restrict__ bias,
                       long offA, long offC, int M, int N, int K,
                       long szB, long szBias, long szC) {
    const float* A  = d_arena + offA;
    const float* Bm = Bmat + (long)blockIdx.z * szB;
    const float* bi = bias + (long)blockIdx.z * szBias;
    float*       C  = d_arena + offC + (long)blockIdx.z * szC;

    __shared__ float As[16][68];
    __shared__ float Bs[16][64];

    int tid = threadIdx.x;
    int tx = tid & 15, ty = tid >> 4;
    int arow = tid >> 2;
    int akc  = (tid & 3) << 2;
    int brow = tid >> 4;
    int bcol = (tid & 15) << 2;
    long grow  = (long)blockIdx.y * 64 + arow;
    int  gcolB = blockIdx.x * 64 + bcol;

    float acc[4][4];
#pragma unroll
    for (int i = 0; i < 4; i++)
#pragma unroll
        for (int j = 0; j < 4; j++) acc[i][j] = 0.f;

    for (int kt = 0; kt < K; kt += 16) {
        float4 a4 = make_float4(0.f, 0.f, 0.f, 0.f);
        if (grow < M) a4 = *(const float4*)&A[grow * K + kt + akc];
        As[akc + 0][arow] = a4.x;
        As[akc + 1][arow] = a4.y;
        As[akc + 2][arow] = a4.z;
        As[akc + 3][arow] = a4.w;
        float4 b4 = *(const float4*)&Bm[(long)(kt + brow) * N + gcolB];
        *(float4*)&Bs[brow][bcol] = b4;
        __syncthreads();
#pragma unroll
        for (int k = 0; k < 16; k++) {
            float4 av = *(const float4*)&As[k][ty << 2];
            float4 bv = *(const float4*)&Bs[k][tx << 2];
            float a[4] = {av.x, av.y, av.z, av.w};
            float b[4] = {bv.x, bv.y, bv.z, bv.w};
#pragma unroll
            for (int i = 0; i < 4; i++)
#pragma unroll
                for (int j = 0; j < 4; j++) acc[i][j] += a[i] * b[j];
        }
        __syncthreads();
    }

    int crow0 = blockIdx.y * 64 + (ty << 2);
    int ccol0 = blockIdx.x * 64 + (tx << 2);
    float4 bi4 = *(const float4*)&bi[ccol0];
#pragma unroll
    for (int i = 0; i < 4; i++) {
        if (crow0 + i < M) {
            float4 o;
            o.x = acc[i][0] + bi4.x;
            o.y = acc[i][1] + bi4.y;
            o.z = acc[i][2] + bi4.z;
            o.w = acc[i][3] + bi4.w;
            *(float4*)&C[(long)(crow0 + i) * N + ccol0] = o;
        }
    }
}

// ---------------------------------------------------------------------------
__device__ __forceinline__ void mma_tf32(float c[4], const uint32_t a[4], const uint32_t b[2]) {
    asm volatile(
        "mma.sync.aligned.m16n8k8.row.col.f32.tf32.tf32.f32 "
        "{%0,%1,%2,%3},{%4,%5,%6,%7},{%8,%9},{%0,%1,%2,%3};"
        : "+f"(c[0]), "+f"(c[1]), "+f"(c[2]), "+f"(c[3])
        : "r"(a[0]), "r"(a[1]), "r"(a[2]), "r"(a[3]), "r"(b[0]), "r"(b[1]));
}

__device__ __forceinline__ uint32_t smem_u32(const void* p) {
    return (uint32_t)__cvta_generic_to_shared(p);
}
__device__ __forceinline__ void cp16(uint32_t dst, const float* src, int sz) {
    asm volatile("cp.async.cg.shared.global [%0], [%1], 16, %2;\n"
                 :: "r"(dst), "l"(src), "r"(sz));
}
__device__ __forceinline__ void cp_commit() { asm volatile("cp.async.commit_group;\n"); }
template <int N> __device__ __forceinline__ void cp_wait() {
    asm volatile("cp.async.wait_group %0;\n" :: "n"(N));
}

// ---------------------------------------------------------------------------
// batched tf32 GEMM with cp.async, K-tile 32, 128x128 block tile, 8 warps.
struct GemmDesc {
    const float* Bp;
    const float* bip;
    long szB, szBias;
    long offA[9], offC[9];
    int  M[9];
    int  N, K;
};

// dyn smem: As[2][128][36] floats (9216), Bs[2][32][136] (8704) -> 71680 B
#define GT_SMEM 71680
#define AS_IDX(buf, r, k) ((buf) * 4608 + (r) * 36 + (k))
#define BS_IDX(buf, k, n) (9216 + (buf) * 4352 + (k) * 136 + (n))

__global__ void __launch_bounds__(256, 2)
k_gemm_tc2(GemmDesc d) {
    extern __shared__ float dsm[];
    int z = blockIdx.z;
    int M = d.M[z];
    int m0 = blockIdx.y * 128;
    if (m0 >= M) return;
    int N = d.N, K = d.K;
    const float* A  = d_arena + d.offA[z];
    const float* Bm = d.Bp + (long)z * d.szB;
    const float* bi = d.bip + (long)z * d.szBias;
    float*       C  = d_arena + d.offC[z];

    int tid  = threadIdx.x;
    int lane = tid & 31, wid = tid >> 5;
    int wm = wid & 3, wn = wid >> 2;
    int g  = lane >> 2, tg = lane & 3;
    int n0 = blockIdx.x * 128;

    int ar  = tid >> 1;
    int ac0 = (tid & 1) << 4;
    int bk  = tid >> 3;
    int bn0 = (tid & 7) << 4;

    long grow = m0 + ar;
    long arowc = (grow < M ? grow : (long)(M - 1));
    int  asz = (grow < M) ? 16 : 0;

    float acc[2][8][4];
#pragma unroll
    for (int mi = 0; mi < 2; mi++)
#pragma unroll
        for (int ni = 0; ni < 8; ni++)
#pragma unroll
            for (int r = 0; r < 4; r++) acc[mi][ni][r] = 0.f;

    int nk = K >> 5;

    {
        const float* as = A + arowc * K + ac0;
        const float* bs = Bm + (long)bk * N + n0 + bn0;
#pragma unroll
        for (int c = 0; c < 16; c += 4) cp16(smem_u32(&dsm[AS_IDX(0, ar, ac0 + c)]), as + c, asz);
#pragma unroll
        for (int c = 0; c < 16; c += 4) cp16(smem_u32(&dsm[BS_IDX(0, bk, bn0 + c)]), bs + c, 16);
        cp_commit();
    }

    for (int kt = 0; kt < nk; kt++) {
        int cur = kt & 1;
        if (kt + 1 < nk) {
            int nxt = cur ^ 1;
            int kbase = (kt + 1) << 5;
            const float* as = A + arowc * K + kbase + ac0;
            const float* bs = Bm + (long)(kbase + bk) * N + n0 + bn0;
#pragma unroll
            for (int c = 0; c < 16; c += 4) cp16(smem_u32(&dsm[AS_IDX(nxt, ar, ac0 + c)]), as + c, asz);
#pragma unroll
            for (int c = 0; c < 16; c += 4) cp16(smem_u32(&dsm[BS_IDX(nxt, bk, bn0 + c)]), bs + c, 16);
            cp_commit();
            cp_wait<1>();
        } else {
            cp_wait<0>();
        }
        __syncthreads();

#pragma unroll
        for (int k0 = 0; k0 < 32; k0 += 8) {
            uint32_t af[2][4];
#pragma unroll
            for (int mi = 0; mi < 2; mi++) {
                int r = wm * 32 + mi * 16 + g;
                af[mi][0] = __float_as_uint(dsm[AS_IDX(cur, r, k0 + tg)]);
                af[mi][1] = __float_as_uint(dsm[AS_IDX(cur, r + 8, k0 + tg)]);
                af[mi][2] = __float_as_uint(dsm[AS_IDX(cur, r, k0 + tg + 4)]);
                af[mi][3] = __float_as_uint(dsm[AS_IDX(cur, r + 8, k0 + tg + 4)]);
            }
            uint32_t bf[8][2];
#pragma unroll
            for (int ni = 0; ni < 8; ni++) {
                int cn = wn * 64 + ni * 8 + g;
                bf[ni][0] = __float_as_uint(dsm[BS_IDX(cur, k0 + tg, cn)]);
                bf[ni][1] = __float_as_uint(dsm[BS_IDX(cur, k0 + tg + 4, cn)]);
            }
#pragma unroll
            for (int mi = 0; mi < 2; mi++)
#pragma unroll
                for (int ni = 0; ni < 8; ni++)
                    mma_tf32(acc[mi][ni], af[mi], bf[ni]);
        }
        __syncthreads();
    }

#pragma unroll
    for (int mi = 0; mi < 2; mi++) {
        int row = m0 + wm * 32 + mi * 16 + g;
#pragma unroll
        for (int ni = 0; ni < 8; ni++) {
            int col = n0 + wn * 64 + ni * 8 + tg * 2;
            float bx = bi[col], by = bi[col + 1];
            if (row < M) {
                float2 o = make_float2(acc[mi][ni][0] + bx, acc[mi][ni][1] + by);
                *(float2*)&C[(long)row * N + col] = o;
            }
            if (row + 8 < M) {
                float2 o = make_float2(acc[mi][ni][2] + bx, acc[mi][ni][3] + by);
                *(float2*)&C[(long)(row + 8) * N + col] = o;
            }
        }
    }
}

// ---------------------------------------------------------------------------
__device__ __forceinline__ void block_ln_stats(float s, float q, float* mean, float* ri) {
    __shared__ float sh[8];
    int lane = threadIdx.x & 31, wid = threadIdx.x >> 5;
#pragma unroll
    for (int off = 16; off; off >>= 1) {
        s += __shfl_xor_sync(~0u, s, off);
        q += __shfl_xor_sync(~0u, q, off);
    }
    if (lane == 0) { sh[wid] = s; sh[4 + wid] = q; }
    __syncthreads();
    if (threadIdx.x == 0) {
        float S = sh[0] + sh[1] + sh[2] + sh[3];
        float Q = sh[4] + sh[5] + sh[6] + sh[7];
        float m = S * (1.f / 512.f);
        float v = Q * (1.f / 512.f) - m * m;
        sh[0] = m;
        sh[1] = rsqrtf(v + 1e-6f);
    }
    __syncthreads();
    *mean = sh[0];
    *ri   = sh[1];
}

__global__ void k_modln(const float* __restrict__ inp, int istream, int len, long tokOff) {
    int row = blockIdx.x;
    int b = row / len;
    int tid = threadIdx.x;
    float4 v = *(const float4*)&inp[(long)row * DM + tid * 4];
    float s = v.x + v.y + v.z + v.w;
    float q = v.x * v.x + v.y * v.y + v.z * v.z + v.w * v.w;
    float mean, ri;
    block_ln_stats(s, q, &mean, &ri);
    const float* ada = d_arena + OFF_ADA + ((long)istream * BB + b) * 3072;
    float4 sc = *(const float4*)&ada[512 + tid * 4];
    float4 shv = *(const float4*)&ada[tid * 4];
    float4 o;
    o.x = (v.x - mean) * ri * (1.f + sc.x) + shv.x;
    o.y = (v.y - mean) * ri * (1.f + sc.y) + shv.y;
    o.z = (v.z - mean) * ri * (1.f + sc.z) + shv.z;
    o.w = (v.w - mean) * ri * (1.f + sc.w) + shv.w;
    *(float4*)&d_arena[OFF_NBUF + (tokOff + row) * DM + tid * 4] = o;
}

// ---------------------------------------------------------------------------
__global__ void k_qkvx(const float* __restrict__ gqk,
                       const float* __restrict__ pos_q,
                       const float* __restrict__ pos_k) {
    int w = threadIdx.x >> 5;
    int lane = threadIdx.x & 31;
    int g = blockIdx.x * 4 + w;
    int h = g & 7;
    int bl = g >> 3;
    int l = bl % LL;
    int b = bl / LL;

    int istream, t;
    long r;
    if (l < TT)            { istream = 2; t = l;            r = (long)b * TT + t; }
    else if (l < TT + SSRC){ istream = 1; t = l - TT;       r = 1232 + (long)b * SSRC + t; }
    else                   { istream = 0; t = l - TT - SSRC; r = 6032 + (long)b * NHID + t; }

    long base = r * DM + h * HD;
    float q0 = d_arena[OFF_QKV + base + lane];
    float q1 = d_arena[OFF_QKV + base + lane + 32];
    float k0 = d_arena[OFF_QKV + (long)TOKS * DM + base + lane];
    float k1 = d_arena[OFF_QKV + (long)TOKS * DM + base + lane + 32];
    float v0 = d_arena[OFF_QKV + 2L * TOKS * DM + base + lane];
    float v1 = d_arena[OFF_QKV + 2L * TOKS * DM + base + lane + 32];

    float sq = q0 * q0 + q1 * q1;
    float sk = k0 * k0 + k1 * k1;
#pragma unroll
    for (int off = 16; off; off >>= 1) {
        sq += __shfl_xor_sync(~0u, sq, off);
        sk += __shfl_xor_sync(~0u, sk, off);
    }
    float rq = rsqrtf(sq * (1.f / 64.f) + 1e-6f);
    float rk = rsqrtf(sk * (1.f / 64.f) + 1e-6f);
    q0 *= rq * gqk[(istream * 2 + 0) * 64 + lane];
    q1 *= rq * gqk[(istream * 2 + 0) * 64 + lane + 32];
    k0 *= rk * gqk[(istream * 2 + 1) * 64 + lane];
    k1 *= rk * gqk[(istream * 2 + 1) * 64 + lane + 32];

    if (istream == 2) {
        q0 += pos_q[t * 64 + lane];
        q1 += pos_q[t * 64 + lane + 32];
        k0 += pos_k[t * 64 + lane];
        k1 += pos_k[t * 64 + lane + 32];
    } else {
        float rq0 = __shfl_xor_sync(~0u, q0, 1);
        float rq1 = __shfl_xor_sync(~0u, q1, 1);
        float rk0 = __shfl_xor_sync(~0u, k0, 1);
        float rk1 = __shfl_xor_sync(~0u, k1, 1);
        float tf = (float)t;
        float pw = (tf - 150.f) * (1.f / 512.f);
        {
            int d = lane, ii = d >> 1;
            float inv = powf(10000.f, -(float)(2 * ii) * (1.f / 64.f));
            float ang = tf * inv;
            float c = cosf(ang), s = sinf(ang);
            float scl = powf(((float)(2 * ii) + 25.6f) * (1.f / 89.6f), pw);
            float rotq = (d & 1) ? rq0 : -rq0;
            float rotk = (d & 1) ? rk0 : -rk0;
            q0 = q0 * (c * scl) + rotq * (s * scl);
            k0 = k0 * (c / scl) + rotk * (s / scl);
        }
        {
            int d = lane + 32, ii = d >> 1;
            float inv = powf(10000.f, -(float)(2 * ii) * (1.f / 64.f));
            float ang = tf * inv;
            float c = cosf(ang), s = sinf(ang);
            float scl = powf(((float)(2 * ii) + 25.6f) * (1.f / 89.6f), pw);
            float rotq = (d & 1) ? rq1 : -rq1;
            float rotk = (d & 1) ? rk1 : -rk1;
            q1 = q1 * (c * scl) + rotq * (s * scl);
            k1 = k1 * (c / scl) + rotk * (s / scl);
        }
    }

    long o = (((long)(b * NH + h)) * LL + l) * HD;
    d_arena[OFF_QA + o + lane]      = q0;
    d_arena[OFF_QA + o + lane + 32] = q1;
    d_arena[OFF_KA + o + lane]      = k0;
    d_arena[OFF_KA + o + lane + 32] = k1;
    d_arena[OFF_VA + o + lane]      = v0;
    d_arena[OFF_VA + o + lane + 32] = v1;
}

// ---------------------------------------------------------------------------
// tensor-core flash attention: 64 queries/block, 4 warps, K-tile 32.
// All tile strides = 68 floats (272B = 17*16: float4-aligned, conflict-free).
#define QTILES 11
__device__ __forceinline__ int tok_row(int l, int b) {
    if (l < TT)        return b * TT + l;
    if (l < TT + SSRC) return 1232 + b * SSRC + (l - TT);
    return 6032 + b * NHID + (l - TT - SSRC);
}

__global__ void __launch_bounds__(128)
k_attn_tc(const int* __restrict__ valid) {
    __shared__ float Qs[64][68];
    __shared__ float Ks[32][68];
    __shared__ float Vs[32][68];
    __shared__ float Ps[64][36];
    __shared__ int   sVal[LL];

    int tid = threadIdx.x;
    int lane = tid & 31, wid = tid >> 5;
    int g = lane >> 2, tg = lane & 3;
    int bh = blockIdx.x / QTILES;
    int qt = blockIdx.x % QTILES;
    int b = bh >> 3, h = bh & 7;
    int qbase = qt * 64;
    long hbase = (long)bh * LL * HD;

    for (int m = tid; m < LL; m += 128) sVal[m] = valid[b * LL + m];

    // stage Q tile (zero-fill OOB rows)
    for (int e = tid; e < 1024; e += 128) {
        int r = e >> 4, c4 = (e & 15) << 2;
        int l = qbase + r;
        float4 v = make_float4(0.f, 0.f, 0.f, 0.f);
        if (l < LL) v = *(const float4*)&d_arena[OFF_QA + hbase + (long)l * HD + c4];
        *(float4*)&Qs[r][c4] = v;
    }
    __syncthreads();

    int l0 = qbase + wid * 16 + g;
    int l1 = l0 + 8;
    int qv0 = (l0 < LL) ? sVal[l0] : 0;
    int qv1 = (l1 < LL) ? sVal[l1] : 0;

    float m0r = -1e30f, m1r = -1e30f;
    float l0r = 0.f, l1r = 0.f;
    float of[8][4];
#pragma unroll
    for (int ni = 0; ni < 8; ni++)
#pragma unroll
        for (int c = 0; c < 4; c++) of[ni][c] = 0.f;

    for (int kb = 0; kb < LL; kb += 32) {
        for (int e = tid; e < 512; e += 128) {
            int j = e >> 4, c4 = (e & 15) << 2;
            int m = kb + j;
            float4 kv = make_float4(0.f, 0.f, 0.f, 0.f), vv = kv;
            if (m < LL) {
                long p = hbase + (long)m * HD + c4;
                kv = *(const float4*)&d_arena[OFF_KA + p];
                vv = *(const float4*)&d_arena[OFF_VA + p];
            }
            *(float4*)&Ks[j][c4] = kv;
            *(float4*)&Vs[j][c4] = vv;
        }
        __syncthreads();

        // S = Q @ K^T over the FULL head dim (k0 = 0..64)
        float sf[4][4];
#pragma unroll
        for (int ni = 0; ni < 4; ni++)
#pragma unroll
            for (int c = 0; c < 4; c++) sf[ni][c] = 0.f;
#pragma unroll
        for (int k0 = 0; k0 < 64; k0 += 8) {
            uint32_t af[4];
            int r = wid * 16 + g;
            af[0] = __float_as_uint(Qs[r][k0 + tg]);
            af[1] = __float_as_uint(Qs[r + 8][k0 + tg]);
            af[2] = __float_as_uint(Qs[r][k0 + tg + 4]);
            af[3] = __float_as_uint(Qs[r + 8][k0 + tg + 4]);
#pragma unroll
            for (int ni = 0; ni < 4; ni++) {
                uint32_t bf[2];
                bf[0] = __float_as_uint(Ks[ni * 8 + g][k0 + tg]);
                bf[1] = __float_as_uint(Ks[ni * 8 + g][k0 + tg + 4]);
                mma_tf32(sf[ni], af, bf);
            }
        }

        // masking + online softmax
        float rmax0 = -1e30f, rmax1 = -1e30f;
        float sv[4][4];
        int okm[4][4];
#pragma unroll
        for (int ni = 0; ni < 4; ni++) {
#pragma unroll
            for (int c = 0; c < 2; c++) {
                int key = kb + ni * 8 + tg * 2 + c;
                int kvv = (key < LL) ? sVal[key] : 0;
                int ok0 = (key < LL) && (((qv0 != 0) && (kvv != 0)) || (key == l0));
                int ok1 = (key < LL) && (((qv1 != 0) && (kvv != 0)) || (key == l1));
                float s0 = sf[ni][c] * 0.125f;
                float s1 = sf[ni][c + 2] * 0.125f;
                sv[ni][c] = s0; sv[ni][c + 2] = s1;
                okm[ni][c] = ok0; okm[ni][c + 2] = ok1;
                if (ok0) rmax0 = fmaxf(rmax0, s0);
                if (ok1) rmax1 = fmaxf(rmax1, s1);
            }
        }
        rmax0 = fmaxf(rmax0, __shfl_xor_sync(~0u, rmax0, 1));
        rmax0 = fmaxf(rmax0, __shfl_xor_sync(~0u, rmax0, 2));
        rmax1 = fmaxf(rmax1, __shfl_xor_sync(~0u, rmax1, 1));
        rmax1 = fmaxf(rmax1, __shfl_xor_sync(~0u, rmax1, 2));
        float nm0 = fmaxf(m0r, rmax0);
        float nm1 = fmaxf(m1r, rmax1);
        float corr0 = __expf(m0r - nm0);
        float corr1 = __expf(m1r - nm1);

        float rs0 = 0.f, rs1 = 0.f;
        float pv[4][4];
#pragma unroll
        for (int ni = 0; ni < 4; ni++) {
#pragma unroll
            for (int c = 0; c < 2; c++) {
                float p0 = okm[ni][c]     ? __expf(sv[ni][c] - nm0)     : 0.f;
                float p1 = okm[ni][c + 2] ? __expf(sv[ni][c + 2] - nm1) : 0.f;
                pv[ni][c] = p0; pv[ni][c + 2] = p1;
                rs0 += p0; rs1 += p1;
            }
        }
        rs0 += __shfl_xor_sync(~0u, rs0, 1);
        rs0 += __shfl_xor_sync(~0u, rs0, 2);
        rs1 += __shfl_xor_sync(~0u, rs1, 1);
        rs1 += __shfl_xor_sync(~0u, rs1, 2);
        l0r = l0r * corr0 + rs0;
        l1r = l1r * corr1 + rs1;
        m0r = nm0; m1r = nm1;

#pragma unroll
        for (int ni = 0; ni < 8; ni++) {
            of[ni][0] *= corr0; of[ni][1] *= corr0;
            of[ni][2] *= corr1; of[ni][3] *= corr1;
        }

        // store P fragment (per-warp rows, warp-private)
        {
            int r = wid * 16 + g;
#pragma unroll
            for (int ni = 0; ni < 4; ni++) {
                int cc = ni * 8 + tg * 2;
                *(float2*)&Ps[r][cc]     = make_float2(pv[ni][0], pv[ni][1]);
                *(float2*)&Ps[r + 8][cc] = make_float2(pv[ni][2], pv[ni][3]);
            }
        }
        __syncwarp();

        // O += P @ V   (16x64 per warp, k = 32 keys)
#pragma unroll
        for (int k0 = 0; k0 < 32; k0 += 8) {
            uint32_t af[4];
            int r = wid * 16 + g;
            af[0] = __float_as_uint(Ps[r][k0 + tg]);
            af[1] = __float_as_uint(Ps[r + 8][k0 + tg]);
            af[2] = __float_as_uint(Ps[r][k0 + tg + 4]);
            af[3] = __float_as_uint(Ps[r + 8][k0 + tg + 4]);
#pragma unroll
            for (int ni = 0; ni < 8; ni++) {
                uint32_t bf[2];
                bf[0] = __float_as_uint(Vs[k0 + tg][ni * 8 + g]);
                bf[1] = __float_as_uint(Vs[k0 + tg + 4][ni * 8 + g]);
                mma_tf32(of[ni], af, bf);
            }
        }
        __syncwarp();
        __syncthreads();
    }

    float inv0 = 1.f / l0r;
    float inv1 = 1.f / l1r;
    if (l0 < LL) {
        long op = (long)tok_row(l0, b) * DM + h * HD;
#pragma unroll
        for (int ni = 0; ni < 8; ni++) {
            int dd = ni * 8 + tg * 2;
            *(float2*)&d_arena[OFF_OGAT + op + dd] =
                make_float2(of[ni][0] * inv0, of[ni][1] * inv0);
        }
    }
    if (l1 < LL) {
        long op = (long)tok_row(l1, b) * DM + h * HD;
#pragma unroll
        for (int ni = 0; ni < 8; ni++) {
            int dd = ni * 8 + tg * 2;
            *(float2*)&d_arena[OFF_OGAT + op + dd] =
                make_float2(of[ni][2] * inv1, of[ni][3] * inv1);
        }
    }
}

// ---------------------------------------------------------------------------
__global__ void k_resln(const float* __restrict__ inp, int istream, int len, long tokOff) {
    int row = blockIdx.x;
    int b = row / len;
    int tid = threadIdx.x;
    long rb = (tokOff + row) * (long)DM;
    const float* ada = d_arena + OFF_ADA + ((long)istream * BB + b) * 3072;

    float4 x4 = *(const float4*)&inp[(long)row * DM + tid * 4];
    float4 a4 = *(const float4*)&d_arena[OFF_ABUF + rb + tid * 4];
    float4 g4 = *(const float4*)&ada[1024 + tid * 4];
    float4 hv;
    hv.x = x4.x + g4.x * a4.x;
    hv.y = x4.y + g4.y * a4.y;
    hv.z = x4.z + g4.z * a4.z;
    hv.w = x4.w + g4.w * a4.w;
    *(float4*)&d_arena[OFF_HBUF + rb + tid * 4] = hv;

    float s = hv.x + hv.y + hv.z + hv.w;
    float q = hv.x * hv.x + hv.y * hv.y + hv.z * hv.z + hv.w * hv.w;
    float mean, ri;
    block_ln_stats(s, q, &mean, &ri);
    float4 sc = *(const float4*)&ada[2048 + tid * 4];
    float4 shv = *(const float4*)&ada[1536 + tid * 4];
    float4 o;
    o.x = (hv.x - mean) * ri * (1.f + sc.x) + shv.x;
    o.y = (hv.y - mean) * ri * (1.f + sc.y) + shv.y;
    o.z = (hv.z - mean) * ri * (1.f + sc.z) + shv.z;
    o.w = (hv.w - mean) * ri * (1.f + sc.w) + shv.w;
    *(float4*)&d_arena[OFF_N2 + rb + tid * 4] = o;
}

// ---------------------------------------------------------------------------
__global__ void k_geglu() {
    long idx = (long)blockIdx.x * blockDim.x + threadIdx.x;
    if (idx >= (long)TOKS * 512) return;
    long rrow = idx >> 9;
    int j4 = (int)(idx & 511) << 2;
    float4 lin = *(const float4*)&d_arena[OFF_U + rrow * 4096 + j4];
    float4 gt  = *(const float4*)&d_arena[OFF_U + rrow * 4096 + 2048 + j4];
    float4 o;
    o.x = lin.x * (0.5f * gt.x * (1.f + erff(gt.x * 0.7071067811865475f)));
    o.y = lin.y * (0.5f * gt.y * (1.f + erff(gt.y * 0.7071067811865475f)));
    o.z = lin.z * (0.5f * gt.z * (1.f + erff(gt.z * 0.7071067811865475f)));
    o.w = lin.w * (0.5f * gt.w * (1.f + erff(gt.w * 0.7071067811865475f)));
    *(float4*)&d_arena[OFF_G + rrow * 2048 + j4] = o;
}

// ---------------------------------------------------------------------------
__global__ void k_final(float* __restrict__ out, int istream, int len, long tokOff, int catOff) {
    int row = blockIdx.x;
    int b = row / len;
    int t = row % len;
    int tid = threadIdx.x;
    long rb = (tokOff + row) * (long)DM;
    const float* ada = d_arena + OFF_ADA + ((long)istream * BB + b) * 3072;
    float4 hv = *(const float4*)&d_arena[OFF_HBUF + rb + tid * 4];
    float4 fv = *(const float4*)&d_arena[OFF_FF + rb + tid * 4];
    float4 gm = *(const float4*)&ada[2560 + tid * 4];
    float4 o;
    o.x = hv.x + gm.x * fv.x;
    o.y = hv.y + gm.y * fv.y;
    o.z = hv.z + gm.z * fv.z;
    o.w = hv.w + gm.w * fv.w;
    *(float4*)&out[((long)b * LL + catOff + t) * DM + tid * 4] = o;
}

// ---------------------------------------------------------------------------
extern "C" void kernel_launch(void* const* d_in, const int* in_sizes, int n_in,
                              void* d_out, int out_size) {
    const float* x     = (const float*)d_in[0];
    const float* src   = (const float*)d_in[1];
    const float* txt   = (const float*)d_in[2];
    const float* temb  = (const float*)d_in[3];
    const float* Wqkv  = (const float*)d_in[4];
    const float* bqkv  = (const float*)d_in[5];
    const float* Wo    = (const float*)d_in[6];
    const float* bo    = (const float*)d_in[7];
    const float* gqk   = (const float*)d_in[8];
    const float* Wada  = (const float*)d_in[9];
    const float* bada  = (const float*)d_in[10];
    const float* Wff1  = (const float*)d_in[11];
    const float* bff1  = (const float*)d_in[12];
    const float* Wff2  = (const float*)d_in[13];
    const float* bff2  = (const float*)d_in[14];
    const float* pos_q = (const float*)d_in[15];
    const float* pos_k = (const float*)d_in[16];
    const int*   valid = (const int*)d_in[17];
    float* out = (float*)d_out;

    static bool attr_set = false;
    if (!attr_set) {
        cudaFuncSetAttribute(k_gemm_tc2, cudaFuncAttributeMaxDynamicSharedMemorySize, GT_SMEM);
        attr_set = true;
    }

    const int  lens[3]    = {NHID, SSRC, TT};
    const long tokOffs[3] = {6032, 1232, 0};
    const int  catOffs[3] = {377, 77, 0};
    const float* inps[3]  = {x, src, txt};

    // 1. silu(temb)
    k_silu<<<(BB * DM + 255) / 256, 256>>>(temb);

    // 2. ada = st @ Wada[s] + bada[s]
    {
        dim3 g(3072 / 64, 1, 3);
        k_gemm<<<g, 256>>>(Wada, bada, OFF_ST, OFF_ADA, BB, 3072, DM,
                           512L * 3072, 3072L, 16L * 3072);
    }

    // 3. modulated LN per stream
    for (int i = 0; i < 3; i++)
        k_modln<<<BB * lens[i], 128>>>(inps[i], i, lens[i], tokOffs[i]);

    // 4. QKV GEMMs: one batched launch, z = s*3 + j
    {
        GemmDesc d;
        d.Bp = Wqkv; d.bip = bqkv;
        d.szB = (long)DM * DM; d.szBias = DM;
        d.N = DM; d.K = DM;
        for (int z = 0; z < 9; z++) {
            int s = z / 3, j = z % 3;
            d.offA[z] = OFF_NBUF + tokOffs[s] * DM;
            d.offC[z] = OFF_QKV + (long)j * TOKS * DM + tokOffs[s] * DM;
            d.M[z]    = BB * lens[s];
        }
        dim3 g(DM / 128, 38, 9);
        k_gemm_tc2<<<g, 256, GT_SMEM>>>(d);
    }

    // 5. RMS + RoPE/pos, scatter to [B,H,L,64]
    k_qkvx<<<(BB * LL * NH) / 4, 128>>>(gqk, pos_q, pos_k);

    // 6. attention (tensor-core flash)
    k_attn_tc<<<BB * NH * QTILES, 128>>>(valid);

    // 7. output projection: batched z = stream
    {
        GemmDesc d;
        d.Bp = Wo; d.bip = bo;
        d.szB = (long)DM * DM; d.szBias = DM;
        d.N = DM; d.K = DM;
        for (int z = 0; z < 3; z++) {
            d.offA[z] = OFF_OGAT + tokOffs[z] * DM;
            d.offC[z] = OFF_ABUF + tokOffs[z] * DM;
            d.M[z]    = BB * lens[z];
        }
        dim3 g(DM / 128, 38, 3);
        k_gemm_tc2<<<g, 256, GT_SMEM>>>(d);
    }

    // 8. residual + LN2
    for (int i = 0; i < 3; i++)
        k_resln<<<BB * lens[i], 128>>>(inps[i], i, lens[i], tokOffs[i]);

    // 9. FF1: batched
    {
        GemmDesc d;
        d.Bp = Wff1; d.bip = bff1;
        d.szB = (long)DM * 4096; d.szBias = 4096;
        d.N = 4096; d.K = DM;
        for (int z = 0; z < 3; z++) {
            d.offA[z] = OFF_N2 + tokOffs[z] * DM;
            d.offC[z] = OFF_U + tokOffs[z] * 4096;
            d.M[z]    = BB * lens[z];
        }
        dim3 g(4096 / 128, 38, 3);
        k_gemm_tc2<<<g, 256, GT_SMEM>>>(d);
    }

    // 10. GeGLU
    k_geglu<<<(int)(((long)TOKS * 512 + 255) / 256), 256>>>();

    // 11. FF2: batched
    {
        GemmDesc d;
        d.Bp = Wff2; d.bip = bff2;
        d.szB = 2048L * DM; d.szBias = DM;
        d.N = DM; d.K = 2048;
        for (int z = 0; z < 3; z++) {
            d.offA[z] = OFF_G + tokOffs[z] * 2048;
            d.offC[z] = OFF_FF + tokOffs[z] * DM;
            d.M[z]    = BB * lens[z];
        }
        dim3 g(DM / 128, 38, 3);
        k_gemm_tc2<<<g, 256, GT_SMEM>>>(d);
    }

    // 12. final residual + scatter
    for (int i = 0; i < 3; i++)
        k_final<<<BB * lens[i], 128>>>(out, i, lens[i], tokOffs[i], catOffs[i]);
}

// round 6
// speedup vs baseline: 3.3912x; 1.0104x over previous
#include <cuda_runtime.h>
#include <math.h>
#include <stdint.h>

#define BB 16
#define TT 77
#define SSRC 300
#define NHID 300
#define LL 677
#define DM 512
#define NH 8
#define HD 64
#define TOKS 10832   // 16*77 + 16*300 + 16*300

// ----- scratch arena (floats) -----
#define OFF_ST    0L
#define OFF_ADA   8192L
#define OFF_NBUF  155648L
#define OFF_QKV   5701632L
#define OFF_QA    22339584L
#define OFF_KA    27885568L
#define OFF_VA    33431552L
#define OFF_OGAT  38977536L
#define OFF_ABUF  44523520L
#define OFF_HBUF  50069504L
#define OFF_N2    55615488L
#define OFF_G     61161472L     // TOKS*2048
#define ARENA_SZ  133259264L

__device__ float d_arena[ARENA_SZ];

// ---------------------------------------------------------------------------
__global__ void k_silu(const float* __restrict__ temb) {
    int i = blockIdx.x * blockDim.x + threadIdx.x;
    if (i < BB * DM) {
        float v = temb[i];
        d_arena[OFF_ST + i] = v / (1.f + __expf(-v));
    }
}

// ---------------------------------------------------------------------------
// small SIMT GEMM for the tiny ada projection (M=16)
__global__ void k_gemm(const float* __restrict__ Bmat, const float* __restrict__ bias,
                       long offA, long offC, int M, int N, int K,
                       long szB, long szBias, long szC) {
    const float* A  = d_arena + offA;
    const float* Bm = Bmat + (long)blockIdx.z * szB;
    const float* bi = bias + (long)blockIdx.z * szBias;
    float*       C  = d_arena + offC + (long)blockIdx.z * szC;

    __shared__ float As[16][68];
    __shared__ float Bs[16][64];

    int tid = threadIdx.x;
    int tx = tid & 15, ty = tid >> 4;
    int arow = tid >> 2;
    int akc  = (tid & 3) << 2;
    int brow = tid >> 4;
    int bcol = (tid & 15) << 2;
    long grow  = (long)blockIdx.y * 64 + arow;
    int  gcolB = blockIdx.x * 64 + bcol;

    float acc[4][4];
#pragma unroll
    for (int i = 0; i < 4; i++)
#pragma unroll
        for (int j = 0; j < 4; j++) acc[i][j] = 0.f;

    for (int kt = 0; kt < K; kt += 16) {
        float4 a4 = make_float4(0.f, 0.f, 0.f, 0.f);
        if (grow < M) a4 = *(const float4*)&A[grow * K + kt + akc];
        As[akc + 0][arow] = a4.x;
        As[akc + 1][arow] = a4.y;
        As[akc + 2][arow] = a4.z;
        As[akc + 3][arow] = a4.w;
        float4 b4 = *(const float4*)&Bm[(long)(kt + brow) * N + gcolB];
        *(float4*)&Bs[brow][bcol] = b4;
        __syncthreads();
#pragma unroll
        for (int k = 0; k < 16; k++) {
            float4 av = *(const float4*)&As[k][ty << 2];
            float4 bv = *(const float4*)&Bs[k][tx << 2];
            float a[4] = {av.x, av.y, av.z, av.w};
            float b[4] = {bv.x, bv.y, bv.z, bv.w};
#pragma unroll
            for (int i = 0; i < 4; i++)
#pragma unroll
                for (int j = 0; j < 4; j++) acc[i][j] += a[i] * b[j];
        }
        __syncthreads();
    }

    int crow0 = blockIdx.y * 64 + (ty << 2);
    int ccol0 = blockIdx.x * 64 + (tx << 2);
    float4 bi4 = *(const float4*)&bi[ccol0];
#pragma unroll
    for (int i = 0; i < 4; i++) {
        if (crow0 + i < M) {
            float4 o;
            o.x = acc[i][0] + bi4.x;
            o.y = acc[i][1] + bi4.y;
            o.z = acc[i][2] + bi4.z;
            o.w = acc[i][3] + bi4.w;
            *(float4*)&C[(long)(crow0 + i) * N + ccol0] = o;
        }
    }
}

// ---------------------------------------------------------------------------
__device__ __forceinline__ void mma_tf32(float c[4], const uint32_t a[4], const uint32_t b[2]) {
    asm volatile(
        "mma.sync.aligned.m16n8k8.row.col.f32.tf32.tf32.f32 "
        "{%0,%1,%2,%3},{%4,%5,%6,%7},{%8,%9},{%0,%1,%2,%3};"
        : "+f"(c[0]), "+f"(c[1]), "+f"(c[2]), "+f"(c[3])
        : "r"(a[0]), "r"(a[1]), "r"(a[2]), "r"(a[3]), "r"(b[0]), "r"(b[1]));
}

__device__ __forceinline__ uint32_t smem_u32(const void* p) {
    return (uint32_t)__cvta_generic_to_shared(p);
}
__device__ __forceinline__ void cp16(uint32_t dst, const float* src, int sz) {
    asm volatile("cp.async.cg.shared.global [%0], [%1], 16, %2;\n"
                 :: "r"(dst), "l"(src), "r"(sz));
}
__device__ __forceinline__ void cp_commit() { asm volatile("cp.async.commit_group;\n"); }
template <int N> __device__ __forceinline__ void cp_wait() {
    asm volatile("cp.async.wait_group %0;\n" :: "n"(N));
}

// smem layout shared by all tc GEMMs:
// As[2][128][36] floats (9216), Bs[2][32][136] (8704) -> 17920 floats = 71680 B
#define GT_SMEM 71680
#define AS_IDX(buf, r, k) ((buf) * 4608 + (r) * 36 + (k))
#define BS_IDX(buf, k, n) (9216 + (buf) * 4352 + (k) * 136 + (n))

// shared mainloop macro body: stages A (rows of d_arena) and B (arbitrary col map)
// Kept as straight code in each kernel for clarity.

struct GemmDesc {
    const float* Bp;
    const float* bip;
    long szB, szBias;
    long offA[9], offC[9];
    int  M[9];
    int  N, K;
};

__global__ void __launch_bounds__(256, 2)
k_gemm_tc2(GemmDesc d) {
    extern __shared__ float dsm[];
    int z = blockIdx.z;
    int M = d.M[z];
    int m0 = blockIdx.y * 128;
    if (m0 >= M) return;
    int N = d.N, K = d.K;
    const float* A  = d_arena + d.offA[z];
    const float* Bm = d.Bp + (long)z * d.szB;
    const float* bi = d.bip + (long)z * d.szBias;
    float*       C  = d_arena + d.offC[z];

    int tid  = threadIdx.x;
    int lane = tid & 31, wid = tid >> 5;
    int wm = wid & 3, wn = wid >> 2;
    int g  = lane >> 2, tg = lane & 3;
    int n0 = blockIdx.x * 128;

    int ar  = tid >> 1;
    int ac0 = (tid & 1) << 4;
    int bk  = tid >> 3;
    int bn0 = (tid & 7) << 4;

    long grow = m0 + ar;
    long arowc = (grow < M ? grow : (long)(M - 1));
    int  asz = (grow < M) ? 16 : 0;

    float acc[2][8][4];
#pragma unroll
    for (int mi = 0; mi < 2; mi++)
#pragma unroll
        for (int ni = 0; ni < 8; ni++)
#pragma unroll
            for (int r = 0; r < 4; r++) acc[mi][ni][r] = 0.f;

    int nk = K >> 5;

    {
        const float* as = A + arowc * K + ac0;
        const float* bs = Bm + (long)bk * N + n0 + bn0;
#pragma unroll
        for (int c = 0; c < 16; c += 4) cp16(smem_u32(&dsm[AS_IDX(0, ar, ac0 + c)]), as + c, asz);
#pragma unroll
        for (int c = 0; c < 16; c += 4) cp16(smem_u32(&dsm[BS_IDX(0, bk, bn0 + c)]), bs + c, 16);
        cp_commit();
    }

    for (int kt = 0; kt < nk; kt++) {
        int cur = kt & 1;
        if (kt + 1 < nk) {
            int nxt = cur ^ 1;
            int kbase = (kt + 1) << 5;
            const float* as = A + arowc * K + kbase + ac0;
            const float* bs = Bm + (long)(kbase + bk) * N + n0 + bn0;
#pragma unroll
            for (int c = 0; c < 16; c += 4) cp16(smem_u32(&dsm[AS_IDX(nxt, ar, ac0 + c)]), as + c, asz);
#pragma unroll
            for (int c = 0; c < 16; c += 4) cp16(smem_u32(&dsm[BS_IDX(nxt, bk, bn0 + c)]), bs + c, 16);
            cp_commit();
            cp_wait<1>();
        } else {
            cp_wait<0>();
        }
        __syncthreads();

#pragma unroll
        for (int k0 = 0; k0 < 32; k0 += 8) {
            uint32_t af[2][4];
#pragma unroll
            for (int mi = 0; mi < 2; mi++) {
                int r = wm * 32 + mi * 16 + g;
                af[mi][0] = __float_as_uint(dsm[AS_IDX(cur, r, k0 + tg)]);
                af[mi][1] = __float_as_uint(dsm[AS_IDX(cur, r + 8, k0 + tg)]);
                af[mi][2] = __float_as_uint(dsm[AS_IDX(cur, r, k0 + tg + 4)]);
                af[mi][3] = __float_as_uint(dsm[AS_IDX(cur, r + 8, k0 + tg + 4)]);
            }
            uint32_t bf[8][2];
#pragma unroll
            for (int ni = 0; ni < 8; ni++) {
                int cn = wn * 64 + ni * 8 + g;
                bf[ni][0] = __float_as_uint(dsm[BS_IDX(cur, k0 + tg, cn)]);
                bf[ni][1] = __float_as_uint(dsm[BS_IDX(cur, k0 + tg + 4, cn)]);
            }
#pragma unroll
            for (int mi = 0; mi < 2; mi++)
#pragma unroll
                for (int ni = 0; ni < 8; ni++)
                    mma_tf32(acc[mi][ni], af[mi], bf[ni]);
        }
        __syncthreads();
    }

#pragma unroll
    for (int mi = 0; mi < 2; mi++) {
        int row = m0 + wm * 32 + mi * 16 + g;
#pragma unroll
        for (int ni = 0; ni < 8; ni++) {
            int col = n0 + wn * 64 + ni * 8 + tg * 2;
            float bx = bi[col], by = bi[col + 1];
            if (row < M) {
                float2 o = make_float2(acc[mi][ni][0] + bx, acc[mi][ni][1] + by);
                *(float2*)&C[(long)row * N + col] = o;
            }
            if (row + 8 < M) {
                float2 o = make_float2(acc[mi][ni][2] + bx, acc[mi][ni][3] + by);
                *(float2*)&C[(long)(row + 8) * N + col] = o;
            }
        }
    }
}

// ---------------------------------------------------------------------------
// FF1 fused with GeGLU. Each block covers 64 output (G) columns:
// B tile cols [0,64) = lin cols n0..n0+63, cols [64,128) = gate cols 2048+n0..
// wn=0 warps -> lin, wn=1 warps -> gate. Epilogue: gate warps write
// gelu(gate+bias) to smem; lin warps multiply and store G.
struct FF1Desc {
    const float* Bp;     // Wff1
    const float* bip;    // bff1
    long offA[3], offC[3];
    int  M[3];
};

#define GB_STRIDE 72

__global__ void __launch_bounds__(256, 2)
k_gemm_ff1(FF1Desc d) {
    extern __shared__ float dsm[];
    int z = blockIdx.z;
    int M = d.M[z];
    int m0 = blockIdx.y * 128;
    if (m0 >= M) return;
    const int N = 4096, K = DM;
    const float* A  = d_arena + d.offA[z];
    const float* Bm = d.Bp + (long)z * DM * 4096;
    const float* bi = d.bip + (long)z * 4096;
    float*       G  = d_arena + d.offC[z];

    int tid  = threadIdx.x;
    int lane = tid & 31, wid = tid >> 5;
    int wm = wid & 3, wn = wid >> 2;
    int g  = lane >> 2, tg = lane & 3;
    int n0 = blockIdx.x * 64;

    int ar  = tid >> 1;
    int ac0 = (tid & 1) << 4;
    int bk  = tid >> 3;
    int bn0 = (tid & 7) << 4;
    int gcolbase = (bn0 < 64) ? (n0 + bn0) : (2048 + n0 + bn0 - 64);

    long grow = m0 + ar;
    long arowc = (grow < M ? grow : (long)(M - 1));
    int  asz = (grow < M) ? 16 : 0;

    float acc[2][8][4];
#pragma unroll
    for (int mi = 0; mi < 2; mi++)
#pragma unroll
        for (int ni = 0; ni < 8; ni++)
#pragma unroll
            for (int r = 0; r < 4; r++) acc[mi][ni][r] = 0.f;

    int nk = K >> 5;

    {
        const float* as = A + arowc * K + ac0;
        const float* bs = Bm + (long)bk * N + gcolbase;
#pragma unroll
        for (int c = 0; c < 16; c += 4) cp16(smem_u32(&dsm[AS_IDX(0, ar, ac0 + c)]), as + c, asz);
#pragma unroll
        for (int c = 0; c < 16; c += 4) cp16(smem_u32(&dsm[BS_IDX(0, bk, bn0 + c)]), bs + c, 16);
        cp_commit();
    }

    for (int kt = 0; kt < nk; kt++) {
        int cur = kt & 1;
        if (kt + 1 < nk) {
            int nxt = cur ^ 1;
            int kbase = (kt + 1) << 5;
            const float* as = A + arowc * K + kbase + ac0;
            const float* bs = Bm + (long)(kbase + bk) * N + gcolbase;
#pragma unroll
            for (int c = 0; c < 16; c += 4) cp16(smem_u32(&dsm[AS_IDX(nxt, ar, ac0 + c)]), as + c, asz);
#pragma unroll
            for (int c = 0; c < 16; c += 4) cp16(smem_u32(&dsm[BS_IDX(nxt, bk, bn0 + c)]), bs + c, 16);
            cp_commit();
            cp_wait<1>();
        } else {
            cp_wait<0>();
        }
        __syncthreads();

#pragma unroll
        for (int k0 = 0; k0 < 32; k0 += 8) {
            uint32_t af[2][4];
#pragma unroll
            for (int mi = 0; mi < 2; mi++) {
                int r = wm * 32 + mi * 16 + g;
                af[mi][0] = __float_as_uint(dsm[AS_IDX(cur, r, k0 + tg)]);
                af[mi][1] = __float_as_uint(dsm[AS_IDX(cur, r + 8, k0 + tg)]);
                af[mi][2] = __float_as_uint(dsm[AS_IDX(cur, r, k0 + tg + 4)]);
                af[mi][3] = __float_as_uint(dsm[AS_IDX(cur, r + 8, k0 + tg + 4)]);
            }
            uint32_t bf[8][2];
#pragma unroll
            for (int ni = 0; ni < 8; ni++) {
                int cn = wn * 64 + ni * 8 + g;
                bf[ni][0] = __float_as_uint(dsm[BS_IDX(cur, k0 + tg, cn)]);
                bf[ni][1] = __float_as_uint(dsm[BS_IDX(cur, k0 + tg + 4, cn)]);
            }
#pragma unroll
            for (int mi = 0; mi < 2; mi++)
#pragma unroll
                for (int ni = 0; ni < 8; ni++)
                    mma_tf32(acc[mi][ni], af[mi], bf[ni]);
        }
        __syncthreads();
    }

    // epilogue: gate warps (wn=1) -> gelu into smem, lin warps (wn=0) -> G
    if (wn == 1) {
#pragma unroll
        for (int mi = 0; mi < 2; mi++) {
            int r0 = wm * 32 + mi * 16 + g;
#pragma unroll
            for (int ni = 0; ni < 8; ni++) {
                int c = ni * 8 + tg * 2;
                float bx = bi[2048 + n0 + c], by = bi[2048 + n0 + c + 1];
                float g0 = acc[mi][ni][0] + bx, g1 = acc[mi][ni][1] + by;
                float g2 = acc[mi][ni][2] + bx, g3 = acc[mi][ni][3] + by;
                dsm[r0 * GB_STRIDE + c]           = 0.5f * g0 * (1.f + erff(g0 * 0.7071067811865475f));
                dsm[r0 * GB_STRIDE + c + 1]       = 0.5f * g1 * (1.f + erff(g1 * 0.7071067811865475f));
                dsm[(r0 + 8) * GB_STRIDE + c]     = 0.5f * g2 * (1.f + erff(g2 * 0.7071067811865475f));
                dsm[(r0 + 8) * GB_STRIDE + c + 1] = 0.5f * g3 * (1.f + erff(g3 * 0.7071067811865475f));
            }
        }
    }
    __syncthreads();
    if (wn == 0) {
#pragma unroll
        for (int mi = 0; mi < 2; mi++) {
            int rl = wm * 32 + mi * 16 + g;
            int row = m0 + rl;
#pragma unroll
            for (int ni = 0; ni < 8; ni++) {
                int c = ni * 8 + tg * 2;
                float bx = bi[n0 + c], by = bi[n0 + c + 1];
                if (row < M) {
                    float2 o;
                    o.x = (acc[mi][ni][0] + bx) * dsm[rl * GB_STRIDE + c];
                    o.y = (acc[mi][ni][1] + by) * dsm[rl * GB_STRIDE + c + 1];
                    *(float2*)&G[(long)row * 2048 + n0 + c] = o;
                }
                if (row + 8 < M) {
                    float2 o;
                    o.x = (acc[mi][ni][2] + bx) * dsm[(rl + 8) * GB_STRIDE + c];
                    o.y = (acc[mi][ni][3] + by) * dsm[(rl + 8) * GB_STRIDE + c + 1];
                    *(float2*)&G[(long)(row + 8) * 2048 + n0 + c] = o;
                }
            }
        }
    }
}

// ---------------------------------------------------------------------------
// FF2 fused with final residual: out = h + g_m * (acc + bias), written
// directly to d_out in concat [txt, src, hid] layout.
struct FF2Desc {
    const float* Bp;     // Wff2
    const float* bip;    // bff2
    float* out;
    long offA[3];
    long tokOff[3];
    int  M[3], len[3], catOff[3];
};

__global__ void __launch_bounds__(256, 2)
k_gemm_ff2(FF2Desc d) {
    extern __shared__ float dsm[];
    int z = blockIdx.z;
    int M = d.M[z];
    int m0 = blockIdx.y * 128;
    if (m0 >= M) return;
    const int N = DM, K = 2048;
    const float* A  = d_arena + d.offA[z];
    const float* Bm = d.Bp + (long)z * 2048 * DM;
    const float* bi = d.bip + (long)z * DM;

    int tid  = threadIdx.x;
    int lane = tid & 31, wid = tid >> 5;
    int wm = wid & 3, wn = wid >> 2;
    int g  = lane >> 2, tg = lane & 3;
    int n0 = blockIdx.x * 128;

    int ar  = tid >> 1;
    int ac0 = (tid & 1) << 4;
    int bk  = tid >> 3;
    int bn0 = (tid & 7) << 4;

    long grow = m0 + ar;
    long arowc = (grow < M ? grow : (long)(M - 1));
    int  asz = (grow < M) ? 16 : 0;

    float acc[2][8][4];
#pragma unroll
    for (int mi = 0; mi < 2; mi++)
#pragma unroll
        for (int ni = 0; ni < 8; ni++)
#pragma unroll
            for (int r = 0; r < 4; r++) acc[mi][ni][r] = 0.f;

    int nk = K >> 5;

    {
        const float* as = A + arowc * K + ac0;
        const float* bs = Bm + (long)bk * N + n0 + bn0;
#pragma unroll
        for (int c = 0; c < 16; c += 4) cp16(smem_u32(&dsm[AS_IDX(0, ar, ac0 + c)]), as + c, asz);
#pragma unroll
        for (int c = 0; c < 16; c += 4) cp16(smem_u32(&dsm[BS_IDX(0, bk, bn0 + c)]), bs + c, 16);
        cp_commit();
    }

    for (int kt = 0; kt < nk; kt++) {
        int cur = kt & 1;
        if (kt + 1 < nk) {
            int nxt = cur ^ 1;
            int kbase = (kt + 1) << 5;
            const float* as = A + arowc * K + kbase + ac0;
            const float* bs = Bm + (long)(kbase + bk) * N + n0 + bn0;
#pragma unroll
            for (int c = 0; c < 16; c += 4) cp16(smem_u32(&dsm[AS_IDX(nxt, ar, ac0 + c)]), as + c, asz);
#pragma unroll
            for (int c = 0; c < 16; c += 4) cp16(smem_u32(&dsm[BS_IDX(nxt, bk, bn0 + c)]), bs + c, 16);
            cp_commit();
            cp_wait<1>();
        } else {
            cp_wait<0>();
        }
        __syncthreads();

#pragma unroll
        for (int k0 = 0; k0 < 32; k0 += 8) {
            uint32_t af[2][4];
#pragma unroll
            for (int mi = 0; mi < 2; mi++) {
                int r = wm * 32 + mi * 16 + g;
                af[mi][0] = __float_as_uint(dsm[AS_IDX(cur, r, k0 + tg)]);
                af[mi][1] = __float_as_uint(dsm[AS_IDX(cur, r + 8, k0 + tg)]);
                af[mi][2] = __float_as_uint(dsm[AS_IDX(cur, r, k0 + tg + 4)]);
                af[mi][3] = __float_as_uint(dsm[AS_IDX(cur, r + 8, k0 + tg + 4)]);
            }
            uint32_t bf[8][2];
#pragma unroll
            for (int ni = 0; ni < 8; ni++) {
                int cn = wn * 64 + ni * 8 + g;
                bf[ni][0] = __float_as_uint(dsm[BS_IDX(cur, k0 + tg, cn)]);
                bf[ni][1] = __float_as_uint(dsm[BS_IDX(cur, k0 + tg + 4, cn)]);
            }
#pragma unroll
            for (int mi = 0; mi < 2; mi++)
#pragma unroll
                for (int ni = 0; ni < 8; ni++)
                    mma_tf32(acc[mi][ni], af[mi], bf[ni]);
        }
        __syncthreads();
    }

    int len = d.len[z], catOff = d.catOff[z];
    long tokOff = d.tokOff[z];
#pragma unroll
    for (int mi = 0; mi < 2; mi++) {
#pragma unroll
        for (int half = 0; half < 2; half++) {
            int r = m0 + wm * 32 + mi * 16 + g + half * 8;
            if (r >= M) continue;
            int bidx = r / len, t = r - bidx * len;
            float* orow = d.out + ((long)bidx * LL + catOff + t) * DM;
            const float* hrow = d_arena + OFF_HBUF + (tokOff + r) * DM;
            const float* gm = d_arena + OFF_ADA + ((long)z * BB + bidx) * 3072 + 2560;
#pragma unroll
            for (int ni = 0; ni < 8; ni++) {
                int col = n0 + wn * 64 + ni * 8 + tg * 2;
                float fx = acc[mi][ni][half * 2 + 0] + bi[col];
                float fy = acc[mi][ni][half * 2 + 1] + bi[col + 1];
                float2 hv = *(const float2*)&hrow[col];
                float2 gv = *(const float2*)&gm[col];
                float2 o = make_float2(hv.x + gv.x * fx, hv.y + gv.y * fy);
                *(float2*)&orow[col] = o;
            }
        }
    }
}

// ---------------------------------------------------------------------------
__device__ __forceinline__ void block_ln_stats(float s, float q, float* mean, float* ri) {
    __shared__ float sh[8];
    int lane = threadIdx.x & 31, wid = threadIdx.x >> 5;
#pragma unroll
    for (int off = 16; off; off >>= 1) {
        s += __shfl_xor_sync(~0u, s, off);
        q += __shfl_xor_sync(~0u, q, off);
    }
    if (lane == 0) { sh[wid] = s; sh[4 + wid] = q; }
    __syncthreads();
    if (threadIdx.x == 0) {
        float S = sh[0] + sh[1] + sh[2] + sh[3];
        float Q = sh[4] + sh[5] + sh[6] + sh[7];
        float m = S * (1.f / 512.f);
        float v = Q * (1.f / 512.f) - m * m;
        sh[0] = m;
        sh[1] = rsqrtf(v + 1e-6f);
    }
    __syncthreads();
    *mean = sh[0];
    *ri   = sh[1];
}

__global__ void k_modln(const float* __restrict__ inp, int istream, int len, long tokOff) {
    int row = blockIdx.x;
    int b = row / len;
    int tid = threadIdx.x;
    float4 v = *(const float4*)&inp[(long)row * DM + tid * 4];
    float s = v.x + v.y + v.z + v.w;
    float q = v.x * v.x + v.y * v.y + v.z * v.z + v.w * v.w;
    float mean, ri;
    block_ln_stats(s, q, &mean, &ri);
    const float* ada = d_arena + OFF_ADA + ((long)istream * BB + b) * 3072;
    float4 sc = *(const float4*)&ada[512 + tid * 4];
    float4 shv = *(const float4*)&ada[tid * 4];
    float4 o;
    o.x = (v.x - mean) * ri * (1.f + sc.x) + shv.x;
    o.y = (v.y - mean) * ri * (1.f + sc.y) + shv.y;
    o.z = (v.z - mean) * ri * (1.f + sc.z) + shv.z;
    o.w = (v.w - mean) * ri * (1.f + sc.w) + shv.w;
    *(float4*)&d_arena[OFF_NBUF + (tokOff + row) * DM + tid * 4] = o;
}

// ---------------------------------------------------------------------------
__global__ void k_qkvx(const float* __restrict__ gqk,
                       const float* __restrict__ pos_q,
                       const float* __restrict__ pos_k) {
    int w = threadIdx.x >> 5;
    int lane = threadIdx.x & 31;
    int g = blockIdx.x * 4 + w;
    int h = g & 7;
    int bl = g >> 3;
    int l = bl % LL;
    int b = bl / LL;

    int istream, t;
    long r;
    if (l < TT)            { istream = 2; t = l;            r = (long)b * TT + t; }
    else if (l < TT + SSRC){ istream = 1; t = l - TT;       r = 1232 + (long)b * SSRC + t; }
    else                   { istream = 0; t = l - TT - SSRC; r = 6032 + (long)b * NHID + t; }

    long base = r * DM + h * HD;
    float q0 = d_arena[OFF_QKV + base + lane];
    float q1 = d_arena[OFF_QKV + base + lane + 32];
    float k0 = d_arena[OFF_QKV + (long)TOKS * DM + base + lane];
    float k1 = d_arena[OFF_QKV + (long)TOKS * DM + base + lane + 32];
    float v0 = d_arena[OFF_QKV + 2L * TOKS * DM + base + lane];
    float v1 = d_arena[OFF_QKV + 2L * TOKS * DM + base + lane + 32];

    float sq = q0 * q0 + q1 * q1;
    float sk = k0 * k0 + k1 * k1;
#pragma unroll
    for (int off = 16; off; off >>= 1) {
        sq += __shfl_xor_sync(~0u, sq, off);
        sk += __shfl_xor_sync(~0u, sk, off);
    }
    float rq = rsqrtf(sq * (1.f / 64.f) + 1e-6f);
    float rk = rsqrtf(sk * (1.f / 64.f) + 1e-6f);
    q0 *= rq * gqk[(istream * 2 + 0) * 64 + lane];
    q1 *= rq * gqk[(istream * 2 + 0) * 64 + lane + 32];
    k0 *= rk * gqk[(istream * 2 + 1) * 64 + lane];
    k1 *= rk * gqk[(istream * 2 + 1) * 64 + lane + 32];

    if (istream == 2) {
        q0 += pos_q[t * 64 + lane];
        q1 += pos_q[t * 64 + lane + 32];
        k0 += pos_k[t * 64 + lane];
        k1 += pos_k[t * 64 + lane + 32];
    } else {
        float rq0 = __shfl_xor_sync(~0u, q0, 1);
        float rq1 = __shfl_xor_sync(~0u, q1, 1);
        float rk0 = __shfl_xor_sync(~0u, k0, 1);
        float rk1 = __shfl_xor_sync(~0u, k1, 1);
        float tf = (float)t;
        float pw = (tf - 150.f) * (1.f / 512.f);
        {
            int d = lane, ii = d >> 1;
            float inv = powf(10000.f, -(float)(2 * ii) * (1.f / 64.f));
            float ang = tf * inv;
            float c = cosf(ang), s = sinf(ang);
            float scl = powf(((float)(2 * ii) + 25.6f) * (1.f / 89.6f), pw);
            float rotq = (d & 1) ? rq0 : -rq0;
            float rotk = (d & 1) ? rk0 : -rk0;
            q0 = q0 * (c * scl) + rotq * (s * scl);
            k0 = k0 * (c / scl) + rotk * (s / scl);
        }
        {
            int d = lane + 32, ii = d >> 1;
            float inv = powf(10000.f, -(float)(2 * ii) * (1.f / 64.f));
            float ang = tf * inv;
            float c = cosf(ang), s = sinf(ang);
            float scl = powf(((float)(2 * ii) + 25.6f) * (1.f / 89.6f), pw);
            float rotq = (d & 1) ? rq1 : -rq1;
            float rotk = (d & 1) ? rk1 : -rk1;
            q1 = q1 * (c * scl) + rotq * (s * scl);
            k1 = k1 * (c / scl) + rotk * (s / scl);
        }
    }

    long o = (((long)(b * NH + h)) * LL + l) * HD;
    d_arena[OFF_QA + o + lane]      = q0;
    d_arena[OFF_QA + o + lane + 32] = q1;
    d_arena[OFF_KA + o + lane]      = k0;
    d_arena[OFF_KA + o + lane + 32] = k1;
    d_arena[OFF_VA + o + lane]      = v0;
    d_arena[OFF_VA + o + lane + 32] = v1;
}

// ---------------------------------------------------------------------------
// tensor-core flash attention: 64 queries/block, 4 warps, K-tile 32.
#define QTILES 11
__device__ __forceinline__ int tok_row(int l, int b) {
    if (l < TT)        return b * TT + l;
    if (l < TT + SSRC) return 1232 + b * SSRC + (l - TT);
    return 6032 + b * NHID + (l - TT - SSRC);
}

__global__ void __launch_bounds__(128)
k_attn_tc(const int* __restrict__ valid) {
    __shared__ float Qs[64][68];
    __shared__ float Ks[32][68];
    __shared__ float Vs[32][68];
    __shared__ float Ps[64][36];
    __shared__ int   sVal[LL];

    int tid = threadIdx.x;
    int lane = tid & 31, wid = tid >> 5;
    int g = lane >> 2, tg = lane & 3;
    int bh = blockIdx.x / QTILES;
    int qt = blockIdx.x % QTILES;
    int b = bh >> 3, h = bh & 7;
    int qbase = qt * 64;
    long hbase = (long)bh * LL * HD;

    for (int m = tid; m < LL; m += 128) sVal[m] = valid[b * LL + m];

    for (int e = tid; e < 1024; e += 128) {
        int r = e >> 4, c4 = (e & 15) << 2;
        int l = qbase + r;
        float4 v = make_float4(0.f, 0.f, 0.f, 0.f);
        if (l < LL) v = *(const float4*)&d_arena[OFF_QA + hbase + (long)l * HD + c4];
        *(float4*)&Qs[r][c4] = v;
    }
    __syncthreads();

    int l0 = qbase + wid * 16 + g;
    int l1 = l0 + 8;
    int qv0 = (l0 < LL) ? sVal[l0] : 0;
    int qv1 = (l1 < LL) ? sVal[l1] : 0;

    float m0r = -1e30f, m1r = -1e30f;
    float l0r = 0.f, l1r = 0.f;
    float of[8][4];
#pragma unroll
    for (int ni = 0; ni < 8; ni++)
#pragma unroll
        for (int c = 0; c < 4; c++) of[ni][c] = 0.f;

    for (int kb = 0; kb < LL; kb += 32) {
        for (int e = tid; e < 512; e += 128) {
            int j = e >> 4, c4 = (e & 15) << 2;
            int m = kb + j;
            float4 kv = make_float4(0.f, 0.f, 0.f, 0.f), vv = kv;
            if (m < LL) {
                long p = hbase + (long)m * HD + c4;
                kv = *(const float4*)&d_arena[OFF_KA + p];
                vv = *(const float4*)&d_arena[OFF_VA + p];
            }
            *(float4*)&Ks[j][c4] = kv;
            *(float4*)&Vs[j][c4] = vv;
        }
        __syncthreads();

        float sf[4][4];
#pragma unroll
        for (int ni = 0; ni < 4; ni++)
#pragma unroll
            for (int c = 0; c < 4; c++) sf[ni][c] = 0.f;
#pragma unroll
        for (int k0 = 0; k0 < 64; k0 += 8) {
            uint32_t af[4];
            int r = wid * 16 + g;
            af[0] = __float_as_uint(Qs[r][k0 + tg]);
            af[1] = __float_as_uint(Qs[r + 8][k0 + tg]);
            af[2] = __float_as_uint(Qs[r][k0 + tg + 4]);
            af[3] = __float_as_uint(Qs[r + 8][k0 + tg + 4]);
#pragma unroll
            for (int ni = 0; ni < 4; ni++) {
                uint32_t bf[2];
                bf[0] = __float_as_uint(Ks[ni * 8 + g][k0 + tg]);
                bf[1] = __float_as_uint(Ks[ni * 8 + g][k0 + tg + 4]);
                mma_tf32(sf[ni], af, bf);
            }
        }

        float rmax0 = -1e30f, rmax1 = -1e30f;
        float sv[4][4];
        int okm[4][4];
#pragma unroll
        for (int ni = 0; ni < 4; ni++) {
#pragma unroll
            for (int c = 0; c < 2; c++) {
                int key = kb + ni * 8 + tg * 2 + c;
                int kvv = (key < LL) ? sVal[key] : 0;
                int ok0 = (key < LL) && (((qv0 != 0) && (kvv != 0)) || (key == l0));
                int ok1 = (key < LL) && (((qv1 != 0) && (kvv != 0)) || (key == l1));
                float s0 = sf[ni][c] * 0.125f;
                float s1 = sf[ni][c + 2] * 0.125f;
                sv[ni][c] = s0; sv[ni][c + 2] = s1;
                okm[ni][c] = ok0; okm[ni][c + 2] = ok1;
                if (ok0) rmax0 = fmaxf(rmax0, s0);
                if (ok1) rmax1 = fmaxf(rmax1, s1);
            }
        }
        rmax0 = fmaxf(rmax0, __shfl_xor_sync(~0u, rmax0, 1));
        rmax0 = fmaxf(rmax0, __shfl_xor_sync(~0u, rmax0, 2));
        rmax1 = fmaxf(rmax1, __shfl_xor_sync(~0u, rmax1, 1));
        rmax1 = fmaxf(rmax1, __shfl_xor_sync(~0u, rmax1, 2));
        float nm0 = fmaxf(m0r, rmax0);
        float nm1 = fmaxf(m1r, rmax1);
        float corr0 = __expf(m0r - nm0);
        float corr1 = __expf(m1r - nm1);

        float rs0 = 0.f, rs1 = 0.f;
        float pv[4][4];
#pragma unroll
        for (int ni = 0; ni < 4; ni++) {
#pragma unroll
            for (int c = 0; c < 2; c++) {
                float p0 = okm[ni][c]     ? __expf(sv[ni][c] - nm0)     : 0.f;
                float p1 = okm[ni][c + 2] ? __expf(sv[ni][c + 2] - nm1) : 0.f;
                pv[ni][c] = p0; pv[ni][c + 2] = p1;
                rs0 += p0; rs1 += p1;
            }
        }
        rs0 += __shfl_xor_sync(~0u, rs0, 1);
        rs0 += __shfl_xor_sync(~0u, rs0, 2);
        rs1 += __shfl_xor_sync(~0u, rs1, 1);
        rs1 += __shfl_xor_sync(~0u, rs1, 2);
        l0r = l0r * corr0 + rs0;
        l1r = l1r * corr1 + rs1;
        m0r = nm0; m1r = nm1;

#pragma unroll
        for (int ni = 0; ni < 8; ni++) {
            of[ni][0] *= corr0; of[ni][1] *= corr0;
            of[ni][2] *= corr1; of[ni][3] *= corr1;
        }

        {
            int r = wid * 16 + g;
#pragma unroll
            for (int ni = 0; ni < 4; ni++) {
                int cc = ni * 8 + tg * 2;
                *(float2*)&Ps[r][cc]     = make_float2(pv[ni][0], pv[ni][1]);
                *(float2*)&Ps[r + 8][cc] = make_float2(pv[ni][2], pv[ni][3]);
            }
        }
        __syncwarp();

#pragma unroll
        for (int k0 = 0; k0 < 32; k0 += 8) {
            uint32_t af[4];
            int r = wid * 16 + g;
            af[0] = __float_as_uint(Ps[r][k0 + tg]);
            af[1] = __float_as_uint(Ps[r + 8][k0 + tg]);
            af[2] = __float_as_uint(Ps[r][k0 + tg + 4]);
            af[3] = __float_as_uint(Ps[r + 8][k0 + tg + 4]);
#pragma unroll
            for (int ni = 0; ni < 8; ni++) {
                uint32_t bf[2];
                bf[0] = __float_as_uint(Vs[k0 + tg][ni * 8 + g]);
                bf[1] = __float_as_uint(Vs[k0 + tg + 4][ni * 8 + g]);
                mma_tf32(of[ni], af, bf);
            }
        }
        __syncwarp();
        __syncthreads();
    }

    float inv0 = 1.f / l0r;
    float inv1 = 1.f / l1r;
    if (l0 < LL) {
        long op = (long)tok_row(l0, b) * DM + h * HD;
#pragma unroll
        for (int ni = 0; ni < 8; ni++) {
            int dd = ni * 8 + tg * 2;
            *(float2*)&d_arena[OFF_OGAT + op + dd] =
                make_float2(of[ni][0] * inv0, of[ni][1] * inv0);
        }
    }
    if (l1 < LL) {
        long op = (long)tok_row(l1, b) * DM + h * HD;
#pragma unroll
        for (int ni = 0; ni < 8; ni++) {
            int dd = ni * 8 + tg * 2;
            *(float2*)&d_arena[OFF_OGAT + op + dd] =
                make_float2(of[ni][2] * inv1, of[ni][3] * inv1);
        }
    }
}

// ---------------------------------------------------------------------------
__global__ void k_resln(const float* __restrict__ inp, int istream, int len, long tokOff) {
    int row = blockIdx.x;
    int b = row / len;
    int tid = threadIdx.x;
    long rb = (tokOff + row) * (long)DM;
    const float* ada = d_arena + OFF_ADA + ((long)istream * BB + b) * 3072;

    float4 x4 = *(const float4*)&inp[(long)row * DM + tid * 4];
    float4 a4 = *(const float4*)&d_arena[OFF_ABUF + rb + tid * 4];
    float4 g4 = *(const float4*)&ada[1024 + tid * 4];
    float4 hv;
    hv.x = x4.x + g4.x * a4.x;
    hv.y = x4.y + g4.y * a4.y;
    hv.z = x4.z + g4.z * a4.z;
    hv.w = x4.w + g4.w * a4.w;
    *(float4*)&d_arena[OFF_HBUF + rb + tid * 4] = hv;

    float s = hv.x + hv.y + hv.z + hv.w;
    float q = hv.x * hv.x + hv.y * hv.y + hv.z * hv.z + hv.w * hv.w;
    float mean, ri;
    block_ln_stats(s, q, &mean, &ri);
    float4 sc = *(const float4*)&ada[2048 + tid * 4];
    float4 shv = *(const float4*)&ada[1536 + tid * 4];
    float4 o;
    o.x = (hv.x - mean) * ri * (1.f + sc.x) + shv.x;
    o.y = (hv.y - mean) * ri * (1.f + sc.y) + shv.y;
    o.z = (hv.z - mean) * ri * (1.f + sc.z) + shv.z;
    o.w = (hv.w - mean) * ri * (1.f + sc.w) + shv.w;
    *(float4*)&d_arena[OFF_N2 + rb + tid * 4] = o;
}

// ---------------------------------------------------------------------------
extern "C" void kernel_launch(void* const* d_in, const int* in_sizes, int n_in,
                              void* d_out, int out_size) {
    const float* x     = (const float*)d_in[0];
    const float* src   = (const float*)d_in[1];
    const float* txt   = (const float*)d_in[2];
    const float* temb  = (const float*)d_in[3];
    const float* Wqkv  = (const float*)d_in[4];
    const float* bqkv  = (const float*)d_in[5];
    const float* Wo    = (const float*)d_in[6];
    const float* bo    = (const float*)d_in[7];
    const float* gqk   = (const float*)d_in[8];
    const float* Wada  = (const float*)d_in[9];
    const float* bada  = (const float*)d_in[10];
    const float* Wff1  = (const float*)d_in[11];
    const float* bff1  = (const float*)d_in[12];
    const float* Wff2  = (const float*)d_in[13];
    const float* bff2  = (const float*)d_in[14];
    const float* pos_q = (const float*)d_in[15];
    const float* pos_k = (const float*)d_in[16];
    const int*   valid = (const int*)d_in[17];
    float* out = (float*)d_out;

    static bool attr_set = false;
    if (!attr_set) {
        cudaFuncSetAttribute(k_gemm_tc2, cudaFuncAttributeMaxDynamicSharedMemorySize, GT_SMEM);
        cudaFuncSetAttribute(k_gemm_ff1, cudaFuncAttributeMaxDynamicSharedMemorySize, GT_SMEM);
        cudaFuncSetAttribute(k_gemm_ff2, cudaFuncAttributeMaxDynamicSharedMemorySize, GT_SMEM);
        attr_set = true;
    }

    const int  lens[3]    = {NHID, SSRC, TT};
    const long tokOffs[3] = {6032, 1232, 0};
    const int  catOffs[3] = {377, 77, 0};
    const float* inps[3]  = {x, src, txt};

    // 1. silu(temb)
    k_silu<<<(BB * DM + 255) / 256, 256>>>(temb);

    // 2. ada = st @ Wada[s] + bada[s]
    {
        dim3 g(3072 / 64, 1, 3);
        k_gemm<<<g, 256>>>(Wada, bada, OFF_ST, OFF_ADA, BB, 3072, DM,
                           512L * 3072, 3072L, 16L * 3072);
    }

    // 3. modulated LN per stream
    for (int i = 0; i < 3; i++)
        k_modln<<<BB * lens[i], 128>>>(inps[i], i, lens[i], tokOffs[i]);

    // 4. QKV GEMMs: one batched launch, z = s*3 + j
    {
        GemmDesc d;
        d.Bp = Wqkv; d.bip = bqkv;
        d.szB = (long)DM * DM; d.szBias = DM;
        d.N = DM; d.K = DM;
        for (int z = 0; z < 9; z++) {
            int s = z / 3, j = z % 3;
            d.offA[z] = OFF_NBUF + tokOffs[s] * DM;
            d.offC[z] = OFF_QKV + (long)j * TOKS * DM + tokOffs[s] * DM;
            d.M[z]    = BB * lens[s];
        }
        dim3 g(DM / 128, 38, 9);
        k_gemm_tc2<<<g, 256, GT_SMEM>>>(d);
    }

    // 5. RMS + RoPE/pos, scatter to [B,H,L,64]
    k_qkvx<<<(BB * LL * NH) / 4, 128>>>(gqk, pos_q, pos_k);

    // 6. attention (tensor-core flash)
    k_attn_tc<<<BB * NH * QTILES, 128>>>(valid);

    // 7. output projection
    {
        GemmDesc d;
        d.Bp = Wo; d.bip = bo;
        d.szB = (long)DM * DM; d.szBias = DM;
        d.N = DM; d.K = DM;
        for (int z = 0; z < 3; z++) {
            d.offA[z] = OFF_OGAT + tokOffs[z] * DM;
            d.offC[z] = OFF_ABUF + tokOffs[z] * DM;
            d.M[z]    = BB * lens[z];
        }
        dim3 g(DM / 128, 38, 3);
        k_gemm_tc2<<<g, 256, GT_SMEM>>>(d);
    }

    // 8. residual + LN2
    for (int i = 0; i < 3; i++)
        k_resln<<<BB * lens[i], 128>>>(inps[i], i, lens[i], tokOffs[i]);

    // 9. FF1 fused with GeGLU -> G
    {
        FF1Desc d;
        d.Bp = Wff1; d.bip = bff1;
        for (int z = 0; z < 3; z++) {
            d.offA[z] = OFF_N2 + tokOffs[z] * DM;
            d.offC[z] = OFF_G + tokOffs[z] * 2048;
            d.M[z]    = BB * lens[z];
        }
        dim3 g(2048 / 64, 38, 3);
        k_gemm_ff1<<<g, 256, GT_SMEM>>>(d);
    }

    // 10. FF2 fused with final residual -> out
    {
        FF2Desc d;
        d.Bp = Wff2; d.bip = bff2; d.out = out;
        for (int z = 0; z < 3; z++) {
            d.offA[z]   = OFF_G + tokOffs[z] * 2048;
            d.tokOff[z] = tokOffs[z];
            d.M[z]      = BB * lens[z];
            d.len[z]    = lens[z];
            d.catOff[z] = catOffs[z];
        }
        dim3 g(DM / 128, 38, 3);
        k_gemm_ff2<<<g, 256, GT_SMEM>>>(d);
    }
}

// round 7
// speedup vs baseline: 5.1425x; 1.5164x over previous
#include <cuda_runtime.h>
#include <cuda_bf16.h>
#include <math.h>
#include <stdint.h>

#define BB 16
#define TT 77
#define SSRC 300
#define NHID 300
#define LL 677
#define DM 512
#define NH 8
#define HD 64
#define TOKS 10832   // 16*77 + 16*300 + 16*300

// ----- arena offsets (float/u32 word units) -----
#define OFF_ST    0L
#define OFF_ADA   8192L          // 3*16*3072
#define OFF_NBUF  155648L        // bf16 TOKS*512 -> 2772992 words
#define OFF_QKV   2928640L       // fp32 3*TOKS*512
#define OFF_QA    19566592L      // fp32 [B,H,L,64]
#define OFF_KA    25112576L
#define OFF_VA    30658560L
#define OFF_OGAT  36204544L      // bf16 TOKS*512
#define OFF_ABUF  38977536L      // fp32
#define OFF_HBUF  44523520L      // fp32
#define OFF_N2    50069504L      // bf16 TOKS*512
#define OFF_G     52842496L      // bf16 TOKS*2048 -> 11091968 words
#define OFF_WQ    63934464L      // packed u32: 9 * 256*512
#define OFF_WO    65114112L      // 3 * 256*512
#define OFF_WF1   65507328L      // 3 * 256*4096
#define OFF_WF2   68653056L      // 3 * 1024*512
#define ARENA_SZ  70225920L

__device__ float d_arena[ARENA_SZ];

__device__ __forceinline__ uint32_t pack_bf(float x, float y) {
    __nv_bfloat162 h = __floats2bfloat162_rn(x, y);
    return *(uint32_t*)&h;
}

// ---------------------------------------------------------------------------
__global__ void k_silu(const float* __restrict__ temb) {
    int i = blockIdx.x * blockDim.x + threadIdx.x;
    if (i < BB * DM) {
        float v = temb[i];
        d_arena[OFF_ST + i] = v / (1.f + __expf(-v));
    }
}

// ---------------------------------------------------------------------------
// weight prepack: fp32 [nz][K][N] -> u32 [nz][K/2][N], word = (bf16 hi=odd k)<<16 | even k
__global__ void k_wconv(const float* __restrict__ src, long dstW, int K2, int N, int nz) {
    uint32_t* au = (uint32_t*)d_arena;
    long total = (long)nz * K2 * N;
    for (long idx = (long)blockIdx.x * blockDim.x + threadIdx.x; idx < total;
         idx += (long)gridDim.x * blockDim.x) {
        long z = idx / ((long)K2 * N);
        long rem = idx - z * (long)K2 * N;
        int k2 = (int)(rem / N);
        int n  = (int)(rem - (long)k2 * N);
        const float* s = src + z * (long)K2 * 2 * N + (long)(2 * k2) * N + n;
        au[dstW + idx] = pack_bf(s[0], s[N]);
    }
}

// ---------------------------------------------------------------------------
// small SIMT GEMM for the tiny ada projection (M=16)
__global__ void k_gemm(const float* __restrict__ Bmat, const float* __restrict__ bias,
                       long offA, long offC, int M, int N, int K,
                       long szB, long szBias, long szC) {
    const float* A  = d_arena + offA;
    const float* Bm = Bmat + (long)blockIdx.z * szB;
    const float* bi = bias + (long)blockIdx.z * szBias;
    float*       C  = d_arena + offC + (long)blockIdx.z * szC;

    __shared__ float As[16][68];
    __shared__ float Bs[16][64];

    int tid = threadIdx.x;
    int tx = tid & 15, ty = tid >> 4;
    int arow = tid >> 2;
    int akc  = (tid & 3) << 2;
    int brow = tid >> 4;
    int bcol = (tid & 15) << 2;
    long grow  = (long)blockIdx.y * 64 + arow;
    int  gcolB = blockIdx.x * 64 + bcol;

    float acc[4][4];
#pragma unroll
    for (int i = 0; i < 4; i++)
#pragma unroll
        for (int j = 0; j < 4; j++) acc[i][j] = 0.f;

    for (int kt = 0; kt < K; kt += 16) {
        float4 a4 = make_float4(0.f, 0.f, 0.f, 0.f);
        if (grow < M) a4 = *(const float4*)&A[grow * K + kt + akc];
        As[akc + 0][arow] = a4.x;
        As[akc + 1][arow] = a4.y;
        As[akc + 2][arow] = a4.z;
        As[akc + 3][arow] = a4.w;
        float4 b4 = *(const float4*)&Bm[(long)(kt + brow) * N + gcolB];
        *(float4*)&Bs[brow][bcol] = b4;
        __syncthreads();
#pragma unroll
        for (int k = 0; k < 16; k++) {
            float4 av = *(const float4*)&As[k][ty << 2];
            float4 bv = *(const float4*)&Bs[k][tx << 2];
            float a[4] = {av.x, av.y, av.z, av.w};
            float b[4] = {bv.x, bv.y, bv.z, bv.w};
#pragma unroll
            for (int i = 0; i < 4; i++)
#pragma unroll
                for (int j = 0; j < 4; j++) acc[i][j] += a[i] * b[j];
        }
        __syncthreads();
    }

    int crow0 = blockIdx.y * 64 + (ty << 2);
    int ccol0 = blockIdx.x * 64 + (tx << 2);
    float4 bi4 = *(const float4*)&bi[ccol0];
#pragma unroll
    for (int i = 0; i < 4; i++) {
        if (crow0 + i < M) {
            float4 o;
            o.x = acc[i][0] + bi4.x;
            o.y = acc[i][1] + bi4.y;
            o.z = acc[i][2] + bi4.z;
            o.w = acc[i][3] + bi4.w;
            *(float4*)&C[(long)(crow0 + i) * N + ccol0] = o;
        }
    }
}

// ---------------------------------------------------------------------------
__device__ __forceinline__ void mma_tf32(float c[4], const uint32_t a[4], const uint32_t b[2]) {
    asm volatile(
        "mma.sync.aligned.m16n8k8.row.col.f32.tf32.tf32.f32 "
        "{%0,%1,%2,%3},{%4,%5,%6,%7},{%8,%9},{%0,%1,%2,%3};"
        : "+f"(c[0]), "+f"(c[1]), "+f"(c[2]), "+f"(c[3])
        : "r"(a[0]), "r"(a[1]), "r"(a[2]), "r"(a[3]), "r"(b[0]), "r"(b[1]));
}
__device__ __forceinline__ void mma_bf16(float c[4], const uint32_t a[4], const uint32_t b[2]) {
    asm volatile(
        "mma.sync.aligned.m16n8k16.row.col.f32.bf16.bf16.f32 "
        "{%0,%1,%2,%3},{%4,%5,%6,%7},{%8,%9},{%0,%1,%2,%3};"
        : "+f"(c[0]), "+f"(c[1]), "+f"(c[2]), "+f"(c[3])
        : "r"(a[0]), "r"(a[1]), "r"(a[2]), "r"(a[3]), "r"(b[0]), "r"(b[1]));
}

__device__ __forceinline__ uint32_t smem_u32(const void* p) {
    return (uint32_t)__cvta_generic_to_shared(p);
}
__device__ __forceinline__ void cp16(uint32_t dst, const void* src, int sz) {
    asm volatile("cp.async.cg.shared.global [%0], [%1], 16, %2;\n"
                 :: "r"(dst), "l"(src), "r"(sz));
}
__device__ __forceinline__ void cp_commit() { asm volatile("cp.async.commit_group;\n"); }
template <int N> __device__ __forceinline__ void cp_wait() {
    asm volatile("cp.async.wait_group %0;\n" :: "n"(N));
}

// bf16 GEMM smem (u32 words): As[2][128][20] = 5120, Bs[2][16][136] = 4352
#define GT_SMEM 37888
#define AS_IDX(buf, r, k2) ((buf) * 2560 + (r) * 20 + (k2))
#define BS_IDX(buf, k2, n) (5120 + (buf) * 2176 + (k2) * 136 + (n))

// ---------------------------------------------------------------------------
// bf16 tensor-core GEMM: A packed bf16 rows (Kw u32/row) in arena,
// B pre-packed [K/2][N] u32 in arena, C fp32 + bias. 128x128 tile, Ktile 32.
struct GemmDescB {
    const float* bip;
    long szBias;
    long offA[9], offC[9];
    long bW;        // weight word base
    long szBW;      // words per z weight
    int  M[9];
    int  N, K;
};

__global__ void __launch_bounds__(256, 2)
k_gemm_bf(GemmDescB d) {
    extern __shared__ uint32_t dsu[];
    uint32_t* au = (uint32_t*)d_arena;
    int z = blockIdx.z;
    int M = d.M[z];
    int m0 = blockIdx.y * 128;
    if (m0 >= M) return;
    int N = d.N;
    int Kw = d.K >> 1;
    const uint32_t* A  = au + d.offA[z];
    const uint32_t* Bm = au + d.bW + (long)z * d.szBW;
    const float*    bi = d.bip + (long)z * d.szBias;
    float*          C  = d_arena + d.offC[z];

    int tid  = threadIdx.x;
    int lane = tid & 31, wid = tid >> 5;
    int wm = wid & 3, wn = wid >> 2;
    int g  = lane >> 2, tg = lane & 3;
    int n0 = blockIdx.x * 128;

    int ar  = tid >> 1;            // A row 0..127
    int ac0 = (tid & 1) << 3;      // word col 0 or 8
    int bk  = tid >> 4;            // B k2-row 0..15
    int bn0 = (tid & 15) << 3;     // word col 0..120

    long grow = m0 + ar;
    long arowc = (grow < M ? grow : (long)(M - 1));
    int  asz = (grow < M) ? 16 : 0;

    float acc[2][8][4];
#pragma unroll
    for (int mi = 0; mi < 2; mi++)
#pragma unroll
        for (int ni = 0; ni < 8; ni++)
#pragma unroll
            for (int r = 0; r < 4; r++) acc[mi][ni][r] = 0.f;

    int nk = d.K >> 5;

    {
        const uint32_t* as = A + arowc * Kw + ac0;
        const uint32_t* bs = Bm + (long)bk * N + n0 + bn0;
#pragma unroll
        for (int c = 0; c < 8; c += 4) cp16(smem_u32(&dsu[AS_IDX(0, ar, ac0 + c)]), as + c, asz);
#pragma unroll
        for (int c = 0; c < 8; c += 4) cp16(smem_u32(&dsu[BS_IDX(0, bk, bn0 + c)]), bs + c, 16);
        cp_commit();
    }

    for (int kt = 0; kt < nk; kt++) {
        int cur = kt & 1;
        if (kt + 1 < nk) {
            int nxt = cur ^ 1;
            int kw = (kt + 1) << 4;
            const uint32_t* as = A + arowc * Kw + kw + ac0;
            const uint32_t* bs = Bm + (long)(kw + bk) * N + n0 + bn0;
#pragma unroll
            for (int c = 0; c < 8; c += 4) cp16(smem_u32(&dsu[AS_IDX(nxt, ar, ac0 + c)]), as + c, asz);
#pragma unroll
            for (int c = 0; c < 8; c += 4) cp16(smem_u32(&dsu[BS_IDX(nxt, bk, bn0 + c)]), bs + c, 16);
            cp_commit();
            cp_wait<1>();
        } else {
            cp_wait<0>();
        }
        __syncthreads();

#pragma unroll
        for (int s8 = 0; s8 < 16; s8 += 8) {
            uint32_t af[2][4];
#pragma unroll
            for (int mi = 0; mi < 2; mi++) {
                int r = wm * 32 + mi * 16 + g;
                af[mi][0] = dsu[AS_IDX(cur, r, s8 + tg)];
                af[mi][1] = dsu[AS_IDX(cur, r + 8, s8 + tg)];
                af[mi][2] = dsu[AS_IDX(cur, r, s8 + tg + 4)];
                af[mi][3] = dsu[AS_IDX(cur, r + 8, s8 + tg + 4)];
            }
            uint32_t bf[8][2];
#pragma unroll
            for (int ni = 0; ni < 8; ni++) {
                int cn = wn * 64 + ni * 8 + g;
                bf[ni][0] = dsu[BS_IDX(cur, s8 + tg, cn)];
                bf[ni][1] = dsu[BS_IDX(cur, s8 + 4 + tg, cn)];
            }
#pragma unroll
            for (int mi = 0; mi < 2; mi++)
#pragma unroll
                for (int ni = 0; ni < 8; ni++)
                    mma_bf16(acc[mi][ni], af[mi], bf[ni]);
        }
        __syncthreads();
    }

#pragma unroll
    for (int mi = 0; mi < 2; mi++) {
        int row = m0 + wm * 32 + mi * 16 + g;
#pragma unroll
        for (int ni = 0; ni < 8; ni++) {
            int col = n0 + wn * 64 + ni * 8 + tg * 2;
            float bx = bi[col], by = bi[col + 1];
            if (row < M) {
                float2 o = make_float2(acc[mi][ni][0] + bx, acc[mi][ni][1] + by);
                *(float2*)&C[(long)row * N + col] = o;
            }
            if (row + 8 < M) {
                float2 o = make_float2(acc[mi][ni][2] + bx, acc[mi][ni][3] + by);
                *(float2*)&C[(long)(row + 8) * N + col] = o;
            }
        }
    }
}

// ---------------------------------------------------------------------------
// FF1 (bf16) fused with GeGLU -> G (bf16).  64 output cols/block:
// B cols [0,64) = lin n0.., [64,128) = gate 2048+n0.. ; wn=0 lin, wn=1 gate.
struct FF1DescB {
    const float* bip;
    long offA[3], offGW[3];   // offGW: G word base per z
    int  M[3];
};

#define GB_STRIDE 72

__global__ void __launch_bounds__(256, 2)
k_gemm_ff1(FF1DescB d) {
    extern __shared__ uint32_t dsu[];
    float* dsf = (float*)dsu;
    uint32_t* au = (uint32_t*)d_arena;
    int z = blockIdx.z;
    int M = d.M[z];
    int m0 = blockIdx.y * 128;
    if (m0 >= M) return;
    const int N = 4096;
    const int Kw = 256;
    const uint32_t* A  = au + d.offA[z];
    const uint32_t* Bm = au + OFF_WF1 + (long)z * 256 * 4096;
    const float*    bi = d.bip + (long)z * 4096;
    uint32_t*       Gw = au + d.offGW[z];

    int tid  = threadIdx.x;
    int lane = tid & 31, wid = tid >> 5;
    int wm = wid & 3, wn = wid >> 2;
    int g  = lane >> 2, tg = lane & 3;
    int n0 = blockIdx.x * 64;

    int ar  = tid >> 1;
    int ac0 = (tid & 1) << 3;
    int bk  = tid >> 4;
    int bn0 = (tid & 15) << 3;
    int gcol = (bn0 < 64) ? (n0 + bn0) : (2048 + n0 + bn0 - 64);

    long grow = m0 + ar;
    long arowc = (grow < M ? grow : (long)(M - 1));
    int  asz = (grow < M) ? 16 : 0;

    float acc[2][8][4];
#pragma unroll
    for (int mi = 0; mi < 2; mi++)
#pragma unroll
        for (int ni = 0; ni < 8; ni++)
#pragma unroll
            for (int r = 0; r < 4; r++) acc[mi][ni][r] = 0.f;

    const int nk = 16;   // K=512

    {
        const uint32_t* as = A + arowc * Kw + ac0;
        const uint32_t* bs = Bm + (long)bk * N + gcol;
#pragma unroll
        for (int c = 0; c < 8; c += 4) cp16(smem_u32(&dsu[AS_IDX(0, ar, ac0 + c)]), as + c, asz);
#pragma unroll
        for (int c = 0; c < 8; c += 4) cp16(smem_u32(&dsu[BS_IDX(0, bk, bn0 + c)]), bs + c, 16);
        cp_commit();
    }

    for (int kt = 0; kt < nk; kt++) {
        int cur = kt & 1;
        if (kt + 1 < nk) {
            int nxt = cur ^ 1;
            int kw = (kt + 1) << 4;
            const uint32_t* as = A + arowc * Kw + kw + ac0;
            const uint32_t* bs = Bm + (long)(kw + bk) * N + gcol;
#pragma unroll
            for (int c = 0; c < 8; c += 4) cp16(smem_u32(&dsu[AS_IDX(nxt, ar, ac0 + c)]), as + c, asz);
#pragma unroll
            for (int c = 0; c < 8; c += 4) cp16(smem_u32(&dsu[BS_IDX(nxt, bk, bn0 + c)]), bs + c, 16);
            cp_commit();
            cp_wait<1>();
        } else {
            cp_wait<0>();
        }
        __syncthreads();

#pragma unroll
        for (int s8 = 0; s8 < 16; s8 += 8) {
            uint32_t af[2][4];
#pragma unroll
            for (int mi = 0; mi < 2; mi++) {
                int r = wm * 32 + mi * 16 + g;
                af[mi][0] = dsu[AS_IDX(cur, r, s8 + tg)];
                af[mi][1] = dsu[AS_IDX(cur, r + 8, s8 + tg)];
                af[mi][2] = dsu[AS_IDX(cur, r, s8 + tg + 4)];
                af[mi][3] = dsu[AS_IDX(cur, r + 8, s8 + tg + 4)];
            }
            uint32_t bf[8][2];
#pragma unroll
            for (int ni = 0; ni < 8; ni++) {
                int cn = wn * 64 + ni * 8 + g;
                bf[ni][0] = dsu[BS_IDX(cur, s8 + tg, cn)];
                bf[ni][1] = dsu[BS_IDX(cur, s8 + 4 + tg, cn)];
            }
#pragma unroll
            for (int mi = 0; mi < 2; mi++)
#pragma unroll
                for (int ni = 0; ni < 8; ni++)
                    mma_bf16(acc[mi][ni], af[mi], bf[ni]);
        }
        __syncthreads();
    }

    // epilogue: gate warps gelu -> smem; lin warps multiply -> G (bf16)
    if (wn == 1) {
#pragma unroll
        for (int mi = 0; mi < 2; mi++) {
            int r0 = wm * 32 + mi * 16 + g;
#pragma unroll
            for (int ni = 0; ni < 8; ni++) {
                int c = ni * 8 + tg * 2;
                float bx = bi[2048 + n0 + c], by = bi[2048 + n0 + c + 1];
                float g0 = acc[mi][ni][0] + bx, g1 = acc[mi][ni][1] + by;
                float g2 = acc[mi][ni][2] + bx, g3 = acc[mi][ni][3] + by;
                dsf[r0 * GB_STRIDE + c]           = 0.5f * g0 * (1.f + erff(g0 * 0.7071067811865475f));
                dsf[r0 * GB_STRIDE + c + 1]       = 0.5f * g1 * (1.f + erff(g1 * 0.7071067811865475f));
                dsf[(r0 + 8) * GB_STRIDE + c]     = 0.5f * g2 * (1.f + erff(g2 * 0.7071067811865475f));
                dsf[(r0 + 8) * GB_STRIDE + c + 1] = 0.5f * g3 * (1.f + erff(g3 * 0.7071067811865475f));
            }
        }
    }
    __syncthreads();
    if (wn == 0) {
#pragma unroll
        for (int mi = 0; mi < 2; mi++) {
            int rl = wm * 32 + mi * 16 + g;
            int row = m0 + rl;
#pragma unroll
            for (int ni = 0; ni < 8; ni++) {
                int c = ni * 8 + tg * 2;
                float bx = bi[n0 + c], by = bi[n0 + c + 1];
                if (row < M) {
                    float ox = (acc[mi][ni][0] + bx) * dsf[rl * GB_STRIDE + c];
                    float oy = (acc[mi][ni][1] + by) * dsf[rl * GB_STRIDE + c + 1];
                    Gw[(long)row * 1024 + ((n0 + c) >> 1)] = pack_bf(ox, oy);
                }
                if (row + 8 < M) {
                    float ox = (acc[mi][ni][2] + bx) * dsf[(rl + 8) * GB_STRIDE + c];
                    float oy = (acc[mi][ni][3] + by) * dsf[(rl + 8) * GB_STRIDE + c + 1];
                    Gw[(long)(row + 8) * 1024 + ((n0 + c) >> 1)] = pack_bf(ox, oy);
                }
            }
        }
    }
}

// ---------------------------------------------------------------------------
// FF2 (bf16, K=2048) fused with final residual -> d_out
struct FF2DescB {
    const float* bip;
    float* out;
    long offA[3];
    long tokOff[3];
    int  M[3], len[3], catOff[3];
};

__global__ void __launch_bounds__(256, 2)
k_gemm_ff2(FF2DescB d) {
    extern __shared__ uint32_t dsu[];
    uint32_t* au = (uint32_t*)d_arena;
    int z = blockIdx.z;
    int M = d.M[z];
    int m0 = blockIdx.y * 128;
    if (m0 >= M) return;
    const int N = DM;
    const int Kw = 1024;
    const uint32_t* A  = au + d.offA[z];
    const uint32_t* Bm = au + OFF_WF2 + (long)z * 1024 * 512;
    const float*    bi = d.bip + (long)z * DM;

    int tid  = threadIdx.x;
    int lane = tid & 31, wid = tid >> 5;
    int wm = wid & 3, wn = wid >> 2;
    int g  = lane >> 2, tg = lane & 3;
    int n0 = blockIdx.x * 128;

    int ar  = tid >> 1;
    int ac0 = (tid & 1) << 3;
    int bk  = tid >> 4;
    int bn0 = (tid & 15) << 3;

    long grow = m0 + ar;
    long arowc = (grow < M ? grow : (long)(M - 1));
    int  asz = (grow < M) ? 16 : 0;

    float acc[2][8][4];
#pragma unroll
    for (int mi = 0; mi < 2; mi++)
#pragma unroll
        for (int ni = 0; ni < 8; ni++)
#pragma unroll
            for (int r = 0; r < 4; r++) acc[mi][ni][r] = 0.f;

    const int nk = 64;   // K=2048

    {
        const uint32_t* as = A + arowc * Kw + ac0;
        const uint32_t* bs = Bm + (long)bk * N + n0 + bn0;
#pragma unroll
        for (int c = 0; c < 8; c += 4) cp16(smem_u32(&dsu[AS_IDX(0, ar, ac0 + c)]), as + c, asz);
#pragma unroll
        for (int c = 0; c < 8; c += 4) cp16(smem_u32(&dsu[BS_IDX(0, bk, bn0 + c)]), bs + c, 16);
        cp_commit();
    }

    for (int kt = 0; kt < nk; kt++) {
        int cur = kt & 1;
        if (kt + 1 < nk) {
            int nxt = cur ^ 1;
            int kw = (kt + 1) << 4;
            const uint32_t* as = A + arowc * Kw + kw + ac0;
            const uint32_t* bs = Bm + (long)(kw + bk) * N + n0 + bn0;
#pragma unroll
            for (int c = 0; c < 8; c += 4) cp16(smem_u32(&dsu[AS_IDX(nxt, ar, ac0 + c)]), as + c, asz);
#pragma unroll
            for (int c = 0; c < 8; c += 4) cp16(smem_u32(&dsu[BS_IDX(nxt, bk, bn0 + c)]), bs + c, 16);
            cp_commit();
            cp_wait<1>();
        } else {
            cp_wait<0>();
        }
        __syncthreads();

#pragma unroll
        for (int s8 = 0; s8 < 16; s8 += 8) {
            uint32_t af[2][4];
#pragma unroll
            for (int mi = 0; mi < 2; mi++) {
                int r = wm * 32 + mi * 16 + g;
                af[mi][0] = dsu[AS_IDX(cur, r, s8 + tg)];
                af[mi][1] = dsu[AS_IDX(cur, r + 8, s8 + tg)];
                af[mi][2] = dsu[AS_IDX(cur, r, s8 + tg + 4)];
                af[mi][3] = dsu[AS_IDX(cur, r + 8, s8 + tg + 4)];
            }
            uint32_t bf[8][2];
#pragma unroll
            for (int ni = 0; ni < 8; ni++) {
                int cn = wn * 64 + ni * 8 + g;
                bf[ni][0] = dsu[BS_IDX(cur, s8 + tg, cn)];
                bf[ni][1] = dsu[BS_IDX(cur, s8 + 4 + tg, cn)];
            }
#pragma unroll
            for (int mi = 0; mi < 2; mi++)
#pragma unroll
                for (int ni = 0; ni < 8; ni++)
                    mma_bf16(acc[mi][ni], af[mi], bf[ni]);
        }
        __syncthreads();
    }

    int len = d.len[z], catOff = d.catOff[z];
    long tokOff = d.tokOff[z];
#pragma unroll
    for (int mi = 0; mi < 2; mi++) {
#pragma unroll
        for (int half = 0; half < 2; half++) {
            int r = m0 + wm * 32 + mi * 16 + g + half * 8;
            if (r >= M) continue;
            int bidx = r / len, t = r - bidx * len;
            float* orow = d.out + ((long)bidx * LL + catOff + t) * DM;
            const float* hrow = d_arena + OFF_HBUF + (tokOff + r) * DM;
            const float* gm = d_arena + OFF_ADA + ((long)z * BB + bidx) * 3072 + 2560;
#pragma unroll
            for (int ni = 0; ni < 8; ni++) {
                int col = n0 + wn * 64 + ni * 8 + tg * 2;
                float fx = acc[mi][ni][half * 2 + 0] + bi[col];
                float fy = acc[mi][ni][half * 2 + 1] + bi[col + 1];
                float2 hv = *(const float2*)&hrow[col];
                float2 gv = *(const float2*)&gm[col];
                float2 o = make_float2(hv.x + gv.x * fx, hv.y + gv.y * fy);
                *(float2*)&orow[col] = o;
            }
        }
    }
}

// ---------------------------------------------------------------------------
__device__ __forceinline__ void block_ln_stats(float s, float q, float* mean, float* ri) {
    __shared__ float sh[8];
    int lane = threadIdx.x & 31, wid = threadIdx.x >> 5;
#pragma unroll
    for (int off = 16; off; off >>= 1) {
        s += __shfl_xor_sync(~0u, s, off);
        q += __shfl_xor_sync(~0u, q, off);
    }
    if (lane == 0) { sh[wid] = s; sh[4 + wid] = q; }
    __syncthreads();
    if (threadIdx.x == 0) {
        float S = sh[0] + sh[1] + sh[2] + sh[3];
        float Q = sh[4] + sh[5] + sh[6] + sh[7];
        float m = S * (1.f / 512.f);
        float v = Q * (1.f / 512.f) - m * m;
        sh[0] = m;
        sh[1] = rsqrtf(v + 1e-6f);
    }
    __syncthreads();
    *mean = sh[0];
    *ri   = sh[1];
}

__device__ __forceinline__ void row_decode(int r, int* istream, int* b, int* t) {
    if (r < 1232)      { *istream = 2; *b = r / TT;            *t = r - *b * TT; }
    else if (r < 6032) { int rr = r - 1232; *istream = 1; *b = rr / SSRC; *t = rr - *b * SSRC; }
    else               { int rr = r - 6032; *istream = 0; *b = rr / NHID; *t = rr - *b * NHID; }
}

// merged modulated LN over all TOKS rows -> NBUF (bf16 packed)
__global__ void k_modln(const float* __restrict__ x, const float* __restrict__ src,
                        const float* __restrict__ txt) {
    int row = blockIdx.x;
    int istream, b, t;
    row_decode(row, &istream, &b, &t);
    const float* inp = (istream == 2) ? txt : (istream == 1 ? src : x);
    int lrow = (istream == 2) ? (b * TT + t) : (istream == 1 ? (b * SSRC + t) : (b * NHID + t));
    int tid = threadIdx.x;
    float4 v = *(const float4*)&inp[(long)lrow * DM + tid * 4];
    float s = v.x + v.y + v.z + v.w;
    float q = v.x * v.x + v.y * v.y + v.z * v.z + v.w * v.w;
    float mean, ri;
    block_ln_stats(s, q, &mean, &ri);
    const float* ada = d_arena + OFF_ADA + ((long)istream * BB + b) * 3072;
    float4 sc = *(const float4*)&ada[512 + tid * 4];
    float4 shv = *(const float4*)&ada[tid * 4];
    float ox = (v.x - mean) * ri * (1.f + sc.x) + shv.x;
    float oy = (v.y - mean) * ri * (1.f + sc.y) + shv.y;
    float oz = (v.z - mean) * ri * (1.f + sc.z) + shv.z;
    float ow = (v.w - mean) * ri * (1.f + sc.w) + shv.w;
    uint32_t* au = (uint32_t*)d_arena;
    uint2 pk = make_uint2(pack_bf(ox, oy), pack_bf(oz, ow));
    *(uint2*)&au[OFF_NBUF + (long)row * 256 + tid * 2] = pk;
}

// merged residual + LN2 -> HBUF fp32, N2 bf16
__global__ void k_resln(const float* __restrict__ x, const float* __restrict__ src,
                        const float* __restrict__ txt) {
    int row = blockIdx.x;
    int istream, b, t;
    row_decode(row, &istream, &b, &t);
    const float* inp = (istream == 2) ? txt : (istream == 1 ? src : x);
    int lrow = (istream == 2) ? (b * TT + t) : (istream == 1 ? (b * SSRC + t) : (b * NHID + t));
    int tid = threadIdx.x;
    long rb = (long)row * DM;
    const float* ada = d_arena + OFF_ADA + ((long)istream * BB + b) * 3072;

    float4 x4 = *(const float4*)&inp[(long)lrow * DM + tid * 4];
    float4 a4 = *(const float4*)&d_arena[OFF_ABUF + rb + tid * 4];
    float4 g4 = *(const float4*)&ada[1024 + tid * 4];
    float4 hv;
    hv.x = x4.x + g4.x * a4.x;
    hv.y = x4.y + g4.y * a4.y;
    hv.z = x4.z + g4.z * a4.z;
    hv.w = x4.w + g4.w * a4.w;
    *(float4*)&d_arena[OFF_HBUF + rb + tid * 4] = hv;

    float s = hv.x + hv.y + hv.z + hv.w;
    float q = hv.x * hv.x + hv.y * hv.y + hv.z * hv.z + hv.w * hv.w;
    float mean, ri;
    block_ln_stats(s, q, &mean, &ri);
    float4 sc = *(const float4*)&ada[2048 + tid * 4];
    float4 shv = *(const float4*)&ada[1536 + tid * 4];
    float ox = (hv.x - mean) * ri * (1.f + sc.x) + shv.x;
    float oy = (hv.y - mean) * ri * (1.f + sc.y) + shv.y;
    float oz = (hv.z - mean) * ri * (1.f + sc.z) + shv.z;
    float ow = (hv.w - mean) * ri * (1.f + sc.w) + shv.w;
    uint32_t* au = (uint32_t*)d_arena;
    uint2 pk = make_uint2(pack_bf(ox, oy), pack_bf(oz, ow));
    *(uint2*)&au[OFF_N2 + (long)row * 256 + tid * 2] = pk;
}

// ---------------------------------------------------------------------------
__global__ void k_qkvx(const float* __restrict__ gqk,
                       const float* __restrict__ pos_q,
                       const float* __restrict__ pos_k) {
    int w = threadIdx.x >> 5;
    int lane = threadIdx.x & 31;
    int g = blockIdx.x * 4 + w;
    int h = g & 7;
    int bl = g >> 3;
    int l = bl % LL;
    int b = bl / LL;

    int istream, t;
    long r;
    if (l < TT)            { istream = 2; t = l;            r = (long)b * TT + t; }
    else if (l < TT + SSRC){ istream = 1; t = l - TT;       r = 1232 + (long)b * SSRC + t; }
    else                   { istream = 0; t = l - TT - SSRC; r = 6032 + (long)b * NHID + t; }

    long base = r * DM + h * HD;
    float q0 = d_arena[OFF_QKV + base + lane];
    float q1 = d_arena[OFF_QKV + base + lane + 32];
    float k0 = d_arena[OFF_QKV + (long)TOKS * DM + base + lane];
    float k1 = d_arena[OFF_QKV + (long)TOKS * DM + base + lane + 32];
    float v0 = d_arena[OFF_QKV + 2L * TOKS * DM + base + lane];
    float v1 = d_arena[OFF_QKV + 2L * TOKS * DM + base + lane + 32];

    float sq = q0 * q0 + q1 * q1;
    float sk = k0 * k0 + k1 * k1;
#pragma unroll
    for (int off = 16; off; off >>= 1) {
        sq += __shfl_xor_sync(~0u, sq, off);
        sk += __shfl_xor_sync(~0u, sk, off);
    }
    float rq = rsqrtf(sq * (1.f / 64.f) + 1e-6f);
    float rk = rsqrtf(sk * (1.f / 64.f) + 1e-6f);
    q0 *= rq * gqk[(istream * 2 + 0) * 64 + lane];
    q1 *= rq * gqk[(istream * 2 + 0) * 64 + lane + 32];
    k0 *= rk * gqk[(istream * 2 + 1) * 64 + lane];
    k1 *= rk * gqk[(istream * 2 + 1) * 64 + lane + 32];

    if (istream == 2) {
        q0 += pos_q[t * 64 + lane];
        q1 += pos_q[t * 64 + lane + 32];
        k0 += pos_k[t * 64 + lane];
        k1 += pos_k[t * 64 + lane + 32];
    } else {
        float rq0 = __shfl_xor_sync(~0u, q0, 1);
        float rq1 = __shfl_xor_sync(~0u, q1, 1);
        float rk0 = __shfl_xor_sync(~0u, k0, 1);
        float rk1 = __shfl_xor_sync(~0u, k1, 1);
        float tf = (float)t;
        float pw = (tf - 150.f) * (1.f / 512.f);
        {
            int d = lane, ii = d >> 1;
            float inv = powf(10000.f, -(float)(2 * ii) * (1.f / 64.f));
            float ang = tf * inv;
            float c = cosf(ang), s = sinf(ang);
            float scl = powf(((float)(2 * ii) + 25.6f) * (1.f / 89.6f), pw);
            float rotq = (d & 1) ? rq0 : -rq0;
            float rotk = (d & 1) ? rk0 : -rk0;
            q0 = q0 * (c * scl) + rotq * (s * scl);
            k0 = k0 * (c / scl) + rotk * (s / scl);
        }
        {
            int d = lane + 32, ii = d >> 1;
            float inv = powf(10000.f, -(float)(2 * ii) * (1.f / 64.f));
            float ang = tf * inv;
            float c = cosf(ang), s = sinf(ang);
            float scl = powf(((float)(2 * ii) + 25.6f) * (1.f / 89.6f), pw);
            float rotq = (d & 1) ? rq1 : -rq1;
            float rotk = (d & 1) ? rk1 : -rk1;
            q1 = q1 * (c * scl) + rotq * (s * scl);
            k1 = k1 * (c / scl) + rotk * (s / scl);
        }
    }

    long o = (((long)(b * NH + h)) * LL + l) * HD;
    d_arena[OFF_QA + o + lane]      = q0;
    d_arena[OFF_QA + o + lane + 32] = q1;
    d_arena[OFF_KA + o + lane]      = k0;
    d_arena[OFF_KA + o + lane + 32] = k1;
    d_arena[OFF_VA + o + lane]      = v0;
    d_arena[OFF_VA + o + lane + 32] = v1;
}

// ---------------------------------------------------------------------------
// tensor-core flash attention (tf32), OGAT written as packed bf16.
#define QTILES 11
__device__ __forceinline__ int tok_row(int l, int b) {
    if (l < TT)        return b * TT + l;
    if (l < TT + SSRC) return 1232 + b * SSRC + (l - TT);
    return 6032 + b * NHID + (l - TT - SSRC);
}

__global__ void __launch_bounds__(128)
k_attn_tc(const int* __restrict__ valid) {
    __shared__ float Qs[64][68];
    __shared__ float Ks[32][68];
    __shared__ float Vs[32][68];
    __shared__ float Ps[64][36];
    __shared__ int   sVal[LL];

    int tid = threadIdx.x;
    int lane = tid & 31, wid = tid >> 5;
    int g = lane >> 2, tg = lane & 3;
    int bh = blockIdx.x / QTILES;
    int qt = blockIdx.x % QTILES;
    int b = bh >> 3, h = bh & 7;
    int qbase = qt * 64;
    long hbase = (long)bh * LL * HD;

    for (int m = tid; m < LL; m += 128) sVal[m] = valid[b * LL + m];

    for (int e = tid; e < 1024; e += 128) {
        int r = e >> 4, c4 = (e & 15) << 2;
        int l = qbase + r;
        float4 v = make_float4(0.f, 0.f, 0.f, 0.f);
        if (l < LL) v = *(const float4*)&d_arena[OFF_QA + hbase + (long)l * HD + c4];
        *(float4*)&Qs[r][c4] = v;
    }
    __syncthreads();

    int l0 = qbase + wid * 16 + g;
    int l1 = l0 + 8;
    int qv0 = (l0 < LL) ? sVal[l0] : 0;
    int qv1 = (l1 < LL) ? sVal[l1] : 0;

    float m0r = -1e30f, m1r = -1e30f;
    float l0r = 0.f, l1r = 0.f;
    float of[8][4];
#pragma unroll
    for (int ni = 0; ni < 8; ni++)
#pragma unroll
        for (int c = 0; c < 4; c++) of[ni][c] = 0.f;

    for (int kb = 0; kb < LL; kb += 32) {
        for (int e = tid; e < 512; e += 128) {
            int j = e >> 4, c4 = (e & 15) << 2;
            int m = kb + j;
            float4 kv = make_float4(0.f, 0.f, 0.f, 0.f), vv = kv;
            if (m < LL) {
                long p = hbase + (long)m * HD + c4;
                kv = *(const float4*)&d_arena[OFF_KA + p];
                vv = *(const float4*)&d_arena[OFF_VA + p];
            }
            *(float4*)&Ks[j][c4] = kv;
            *(float4*)&Vs[j][c4] = vv;
        }
        __syncthreads();

        float sf[4][4];
#pragma unroll
        for (int ni = 0; ni < 4; ni++)
#pragma unroll
            for (int c = 0; c < 4; c++) sf[ni][c] = 0.f;
#pragma unroll
        for (int k0 = 0; k0 < 64; k0 += 8) {
            uint32_t af[4];
            int r = wid * 16 + g;
            af[0] = __float_as_uint(Qs[r][k0 + tg]);
            af[1] = __float_as_uint(Qs[r + 8][k0 + tg]);
            af[2] = __float_as_uint(Qs[r][k0 + tg + 4]);
            af[3] = __float_as_uint(Qs[r + 8][k0 + tg + 4]);
#pragma unroll
            for (int ni = 0; ni < 4; ni++) {
                uint32_t bf[2];
                bf[0] = __float_as_uint(Ks[ni * 8 + g][k0 + tg]);
                bf[1] = __float_as_uint(Ks[ni * 8 + g][k0 + tg + 4]);
                mma_tf32(sf[ni], af, bf);
            }
        }

        float rmax0 = -1e30f, rmax1 = -1e30f;
        float sv[4][4];
        int okm[4][4];
#pragma unroll
        for (int ni = 0; ni < 4; ni++) {
#pragma unroll
            for (int c = 0; c < 2; c++) {
                int key = kb + ni * 8 + tg * 2 + c;
                int kvv = (key < LL) ? sVal[key] : 0;
                int ok0 = (key < LL) && (((qv0 != 0) && (kvv != 0)) || (key == l0));
                int ok1 = (key < LL) && (((qv1 != 0) && (kvv != 0)) || (key == l1));
                float s0 = sf[ni][c] * 0.125f;
                float s1 = sf[ni][c + 2] * 0.125f;
                sv[ni][c] = s0; sv[ni][c + 2] = s1;
                okm[ni][c] = ok0; okm[ni][c + 2] = ok1;
                if (ok0) rmax0 = fmaxf(rmax0, s0);
                if (ok1) rmax1 = fmaxf(rmax1, s1);
            }
        }
        rmax0 = fmaxf(rmax0, __shfl_xor_sync(~0u, rmax0, 1));
        rmax0 = fmaxf(rmax0, __shfl_xor_sync(~0u, rmax0, 2));
        rmax1 = fmaxf(rmax1, __shfl_xor_sync(~0u, rmax1, 1));
        rmax1 = fmaxf(rmax1, __shfl_xor_sync(~0u, rmax1, 2));
        float nm0 = fmaxf(m0r, rmax0);
        float nm1 = fmaxf(m1r, rmax1);
        float corr0 = __expf(m0r - nm0);
        float corr1 = __expf(m1r - nm1);

        float rs0 = 0.f, rs1 = 0.f;
        float pv[4][4];
#pragma unroll
        for (int ni = 0; ni < 4; ni++) {
#pragma unroll
            for (int c = 0; c < 2; c++) {
                float p0 = okm[ni][c]     ? __expf(sv[ni][c] - nm0)     : 0.f;
                float p1 = okm[ni][c + 2] ? __expf(sv[ni][c + 2] - nm1) : 0.f;
                pv[ni][c] = p0; pv[ni][c + 2] = p1;
                rs0 += p0; rs1 += p1;
            }
        }
        rs0 += __shfl_xor_sync(~0u, rs0, 1);
        rs0 += __shfl_xor_sync(~0u, rs0, 2);
        rs1 += __shfl_xor_sync(~0u, rs1, 1);
        rs1 += __shfl_xor_sync(~0u, rs1, 2);
        l0r = l0r * corr0 + rs0;
        l1r = l1r * corr1 + rs1;
        m0r = nm0; m1r = nm1;

#pragma unroll
        for (int ni = 0; ni < 8; ni++) {
            of[ni][0] *= corr0; of[ni][1] *= corr0;
            of[ni][2] *= corr1; of[ni][3] *= corr1;
        }

        {
            int r = wid * 16 + g;
#pragma unroll
            for (int ni = 0; ni < 4; ni++) {
                int cc = ni * 8 + tg * 2;
                *(float2*)&Ps[r][cc]     = make_float2(pv[ni][0], pv[ni][1]);
                *(float2*)&Ps[r + 8][cc] = make_float2(pv[ni][2], pv[ni][3]);
            }
        }
        __syncwarp();

#pragma unroll
        for (int k0 = 0; k0 < 32; k0 += 8) {
            uint32_t af[4];
            int r = wid * 16 + g;
            af[0] = __float_as_uint(Ps[r][k0 + tg]);
            af[1] = __float_as_uint(Ps[r + 8][k0 + tg]);
            af[2] = __float_as_uint(Ps[r][k0 + tg + 4]);
            af[3] = __float_as_uint(Ps[r + 8][k0 + tg + 4]);
#pragma unroll
            for (int ni = 0; ni < 8; ni++) {
                uint32_t bf[2];
                bf[0] = __float_as_uint(Vs[k0 + tg][ni * 8 + g]);
                bf[1] = __float_as_uint(Vs[k0 + tg + 4][ni * 8 + g]);
                mma_tf32(of[ni], af, bf);
            }
        }
        __syncwarp();
        __syncthreads();
    }

    uint32_t* au = (uint32_t*)d_arena;
    float inv0 = 1.f / l0r;
    float inv1 = 1.f / l1r;
    if (l0 < LL) {
        long op = (long)tok_row(l0, b) * 256 + h * 32;
#pragma unroll
        for (int ni = 0; ni < 8; ni++)
            au[OFF_OGAT + op + ni * 4 + tg] = pack_bf(of[ni][0] * inv0, of[ni][1] * inv0);
    }
    if (l1 < LL) {
        long op = (long)tok_row(l1, b) * 256 + h * 32;
#pragma unroll
        for (int ni = 0; ni < 8; ni++)
            au[OFF_OGAT + op + ni * 4 + tg] = pack_bf(of[ni][2] * inv1, of[ni][3] * inv1);
    }
}

// ---------------------------------------------------------------------------
extern "C" void kernel_launch(void* const* d_in, const int* in_sizes, int n_in,
                              void* d_out, int out_size) {
    const float* x     = (const float*)d_in[0];
    const float* src   = (const float*)d_in[1];
    const float* txt   = (const float*)d_in[2];
    const float* temb  = (const float*)d_in[3];
    const float* Wqkv  = (const float*)d_in[4];
    const float* bqkv  = (const float*)d_in[5];
    const float* Wo    = (const float*)d_in[6];
    const float* bo    = (const float*)d_in[7];
    const float* gqk   = (const float*)d_in[8];
    const float* Wada  = (const float*)d_in[9];
    const float* bada  = (const float*)d_in[10];
    const float* Wff1  = (const float*)d_in[11];
    const float* bff1  = (const float*)d_in[12];
    const float* Wff2  = (const float*)d_in[13];
    const float* bff2  = (const float*)d_in[14];
    const float* pos_q = (const float*)d_in[15];
    const float* pos_k = (const float*)d_in[16];
    const int*   valid = (const int*)d_in[17];
    float* out = (float*)d_out;

    const int  lens[3]    = {NHID, SSRC, TT};
    const long tokOffs[3] = {6032, 1232, 0};
    const int  catOffs[3] = {377, 77, 0};

    // 0. weight prepack (bf16, k-pair packed)
    k_wconv<<<1184, 256>>>(Wqkv, OFF_WQ, 256, 512, 9);
    k_wconv<<<512,  256>>>(Wo,   OFF_WO, 256, 512, 3);
    k_wconv<<<1184, 256>>>(Wff1, OFF_WF1, 256, 4096, 3);
    k_wconv<<<1184, 256>>>(Wff2, OFF_WF2, 1024, 512, 3);

    // 1. silu(temb)
    k_silu<<<(BB * DM + 255) / 256, 256>>>(temb);

    // 2. ada = st @ Wada[s] + bada[s] (fp32 SIMT, tiny)
    {
        dim3 g(3072 / 64, 1, 3);
        k_gemm<<<g, 256>>>(Wada, bada, OFF_ST, OFF_ADA, BB, 3072, DM,
                           512L * 3072, 3072L, 16L * 3072);
    }

    // 3. modulated LN (merged) -> NBUF bf16
    k_modln<<<TOKS, 128>>>(x, src, txt);

    // 4. QKV GEMMs (bf16), z = s*3 + j
    {
        GemmDescB d;
        d.bip = bqkv; d.szBias = DM;
        d.bW = OFF_WQ; d.szBW = 256L * 512;
        d.N = DM; d.K = DM;
        for (int z = 0; z < 9; z++) {
            int s = z / 3, j = z % 3;
            d.offA[z] = OFF_NBUF + tokOffs[s] * 256;
            d.offC[z] = OFF_QKV + (long)j * TOKS * DM + tokOffs[s] * DM;
            d.M[z]    = BB * lens[s];
        }
        dim3 g(DM / 128, 38, 9);
        k_gemm_bf<<<g, 256, GT_SMEM>>>(d);
    }

    // 5. RMS + RoPE/pos, scatter to [B,H,L,64]
    k_qkvx<<<(BB * LL * NH) / 4, 128>>>(gqk, pos_q, pos_k);

    // 6. attention (tf32 flash) -> OGAT bf16
    k_attn_tc<<<BB * NH * QTILES, 128>>>(valid);

    // 7. output projection (bf16)
    {
        GemmDescB d;
        d.bip = bo; d.szBias = DM;
        d.bW = OFF_WO; d.szBW = 256L * 512;
        d.N = DM; d.K = DM;
        for (int z = 0; z < 3; z++) {
            d.offA[z] = OFF_OGAT + tokOffs[z] * 256;
            d.offC[z] = OFF_ABUF + tokOffs[z] * DM;
            d.M[z]    = BB * lens[z];
        }
        dim3 g(DM / 128, 38, 3);
        k_gemm_bf<<<g, 256, GT_SMEM>>>(d);
    }

    // 8. residual + LN2 (merged) -> HBUF fp32, N2 bf16
    k_resln<<<TOKS, 128>>>(x, src, txt);

    // 9. FF1 (bf16) fused GeGLU -> G bf16
    {
        FF1DescB d;
        d.bip = bff1;
        for (int z = 0; z < 3; z++) {
            d.offA[z]  = OFF_N2 + tokOffs[z] * 256;
            d.offGW[z] = OFF_G + tokOffs[z] * 1024;
            d.M[z]     = BB * lens[z];
        }
        dim3 g(2048 / 64, 38, 3);
        k_gemm_ff1<<<g, 256, GT_SMEM>>>(d);
    }

    // 10. FF2 (bf16) fused final residual -> out
    {
        FF2DescB d;
        d.bip = bff2; d.out = out;
        for (int z = 0; z < 3; z++) {
            d.offA[z]   = OFF_G + tokOffs[z] * 1024;
            d.tokOff[z] = tokOffs[z];
            d.M[z]      = BB * lens[z];
            d.len[z]    = lens[z];
            d.catOff[z] = catOffs[z];
        }
        dim3 g(DM / 128, 38, 3);
        k_gemm_ff2<<<g, 256, GT_SMEM>>>(d);
    }
}

// round 8
// speedup vs baseline: 5.8580x; 1.1391x over previous
#include <cuda_runtime.h>
#include <cuda_bf16.h>
#include <math.h>
#include <stdint.h>

#define BB 16
#define TT 77
#define SSRC 300
#define NHID 300
#define LL 677
#define DM 512
#define NH 8
#define HD 64
#define TOKS 10832   // 16*77 + 16*300 + 16*300

// ----- arena offsets (float/u32 word units) -----
#define OFF_ST    0L
#define OFF_ADA   8192L          // 3*16*3072
#define OFF_NBUF  155648L        // bf16 TOKS*512 packed
#define OFF_QKV   2928640L       // fp32 3*TOKS*512
#define OFF_QAW   19566592L      // packed bf16 [B*H][L][32 words]
#define OFF_KAW   22339584L
#define OFF_VA    25112576L      // fp32 [B*H][L][64]
#define OFF_OGAT  30658560L      // packed bf16 TOKS*256 words
#define OFF_ABUF  33431552L      // fp32
#define OFF_HBUF  38977536L      // fp32
#define OFF_N2    44523520L      // packed bf16
#define OFF_G     47296512L      // packed bf16 TOKS*1024 words
#define OFF_WQ    58388480L      // 9 * 256*512
#define OFF_WO    59568128L      // 3 * 256*512
#define OFF_WF1   59961344L      // 3 * 256*4096
#define OFF_WF2   63107072L      // 3 * 1024*512
#define ARENA_SZ  64679936L

__device__ float d_arena[ARENA_SZ];

__device__ __forceinline__ uint32_t pack_bf(float x, float y) {
    __nv_bfloat162 h = __floats2bfloat162_rn(x, y);
    return *(uint32_t*)&h;
}

// ---------------------------------------------------------------------------
__global__ void k_silu(const float* __restrict__ temb) {
    int i = blockIdx.x * blockDim.x + threadIdx.x;
    if (i < BB * DM) {
        float v = temb[i];
        d_arena[OFF_ST + i] = v / (1.f + __expf(-v));
    }
}

// ---------------------------------------------------------------------------
// weight prepack x4: fp32 [nz][K][N] -> u32 [nz][K/2][N]; each thread emits
// 4 consecutive words (uint4) from two float4 loads.
__global__ void k_wconv4(const float* __restrict__ src, long dstW, int K2, int N, int total4) {
    int i = blockIdx.x * blockDim.x + threadIdx.x;
    if (i >= total4) return;
    int w = i << 2;
    int K2N = K2 * N;
    int z = w / K2N;
    int rem = w - z * K2N;
    int k2 = rem / N;
    int n = rem - k2 * N;
    const float* s = src + (long)z * K2N * 2 + (long)(2 * k2) * N + n;
    float4 e = *(const float4*)s;
    float4 o = *(const float4*)(s + N);
    uint4 r;
    r.x = pack_bf(e.x, o.x);
    r.y = pack_bf(e.y, o.y);
    r.z = pack_bf(e.z, o.z);
    r.w = pack_bf(e.w, o.w);
    *(uint4*)&((uint32_t*)d_arena)[dstW + w] = r;
}

// ---------------------------------------------------------------------------
// small SIMT GEMM for the tiny ada projection (M=16)
__global__ void k_gemm(const float* __restrict__ Bmat, const float* __restrict__ bias,
                       long offA, long offC, int M, int N, int K,
                       long szB, long szBias, long szC) {
    const float* A  = d_arena + offA;
    const float* Bm = Bmat + (long)blockIdx.z * szB;
    const float* bi = bias + (long)blockIdx.z * szBias;
    float*       C  = d_arena + offC + (long)blockIdx.z * szC;

    __shared__ float As[16][68];
    __shared__ float Bs[16][64];

    int tid = threadIdx.x;
    int tx = tid & 15, ty = tid >> 4;
    int arow = tid >> 2;
    int akc  = (tid & 3) << 2;
    int brow = tid >> 4;
    int bcol = (tid & 15) << 2;
    long grow  = (long)blockIdx.y * 64 + arow;
    int  gcolB = blockIdx.x * 64 + bcol;

    float acc[4][4];
#pragma unroll
    for (int i = 0; i < 4; i++)
#pragma unroll
        for (int j = 0; j < 4; j++) acc[i][j] = 0.f;

    for (int kt = 0; kt < K; kt += 16) {
        float4 a4 = make_float4(0.f, 0.f, 0.f, 0.f);
        if (grow < M) a4 = *(const float4*)&A[grow * K + kt + akc];
        As[akc + 0][arow] = a4.x;
        As[akc + 1][arow] = a4.y;
        As[akc + 2][arow] = a4.z;
        As[akc + 3][arow] = a4.w;
        float4 b4 = *(const float4*)&Bm[(long)(kt + brow) * N + gcolB];
        *(float4*)&Bs[brow][bcol] = b4;
        __syncthreads();
#pragma unroll
        for (int k = 0; k < 16; k++) {
            float4 av = *(const float4*)&As[k][ty << 2];
            float4 bv = *(const float4*)&Bs[k][tx << 2];
            float a[4] = {av.x, av.y, av.z, av.w};
            float b[4] = {bv.x, bv.y, bv.z, bv.w};
#pragma unroll
            for (int i = 0; i < 4; i++)
#pragma unroll
                for (int j = 0; j < 4; j++) acc[i][j] += a[i] * b[j];
        }
        __syncthreads();
    }

    int crow0 = blockIdx.y * 64 + (ty << 2);
    int ccol0 = blockIdx.x * 64 + (tx << 2);
    float4 bi4 = *(const float4*)&bi[ccol0];
#pragma unroll
    for (int i = 0; i < 4; i++) {
        if (crow0 + i < M) {
            float4 o;
            o.x = acc[i][0] + bi4.x;
            o.y = acc[i][1] + bi4.y;
            o.z = acc[i][2] + bi4.z;
            o.w = acc[i][3] + bi4.w;
            *(float4*)&C[(long)(crow0 + i) * N + ccol0] = o;
        }
    }
}

// ---------------------------------------------------------------------------
__device__ __forceinline__ void mma_bf16(float c[4], const uint32_t a[4], const uint32_t b[2]) {
    asm volatile(
        "mma.sync.aligned.m16n8k16.row.col.f32.bf16.bf16.f32 "
        "{%0,%1,%2,%3},{%4,%5,%6,%7},{%8,%9},{%0,%1,%2,%3};"
        : "+f"(c[0]), "+f"(c[1]), "+f"(c[2]), "+f"(c[3])
        : "r"(a[0]), "r"(a[1]), "r"(a[2]), "r"(a[3]), "r"(b[0]), "r"(b[1]));
}

__device__ __forceinline__ uint32_t smem_u32(const void* p) {
    return (uint32_t)__cvta_generic_to_shared(p);
}
__device__ __forceinline__ void cp16(uint32_t dst, const void* src, int sz) {
    asm volatile("cp.async.cg.shared.global [%0], [%1], 16, %2;\n"
                 :: "r"(dst), "l"(src), "r"(sz));
}
__device__ __forceinline__ void cp_commit() { asm volatile("cp.async.commit_group;\n"); }
template <int N> __device__ __forceinline__ void cp_wait() {
    asm volatile("cp.async.wait_group %0;\n" :: "n"(N));
}

// bf16 GEMM smem (u32 words): As[2][128][20] = 5120, Bs[2][16][136] = 4352
#define GT_SMEM 37888
#define AS_IDX(buf, r, k2) ((buf) * 2560 + (r) * 20 + (k2))
#define BS_IDX(buf, k2, n) (5120 + (buf) * 2176 + (k2) * 136 + (n))

// ---------------------------------------------------------------------------
struct GemmDescB {
    const float* bip;
    long szBias;
    long offA[9], offC[9];
    long bW;
    long szBW;
    int  M[9];
    int  N, K;
};

__global__ void __launch_bounds__(256, 2)
k_gemm_bf(GemmDescB d) {
    extern __shared__ uint32_t dsu[];
    uint32_t* au = (uint32_t*)d_arena;
    int z = blockIdx.z;
    int M = d.M[z];
    int m0 = blockIdx.y * 128;
    if (m0 >= M) return;
    int N = d.N;
    int Kw = d.K >> 1;
    const uint32_t* A  = au + d.offA[z];
    const uint32_t* Bm = au + d.bW + (long)z * d.szBW;
    const float*    bi = d.bip + (long)z * d.szBias;
    float*          C  = d_arena + d.offC[z];

    int tid  = threadIdx.x;
    int lane = tid & 31, wid = tid >> 5;
    int wm = wid & 3, wn = wid >> 2;
    int g  = lane >> 2, tg = lane & 3;
    int n0 = blockIdx.x * 128;

    int ar  = tid >> 1;
    int ac0 = (tid & 1) << 3;
    int bk  = tid >> 4;
    int bn0 = (tid & 15) << 3;

    long grow = m0 + ar;
    long arowc = (grow < M ? grow : (long)(M - 1));
    int  asz = (grow < M) ? 16 : 0;

    float acc[2][8][4];
#pragma unroll
    for (int mi = 0; mi < 2; mi++)
#pragma unroll
        for (int ni = 0; ni < 8; ni++)
#pragma unroll
            for (int r = 0; r < 4; r++) acc[mi][ni][r] = 0.f;

    int nk = d.K >> 5;

    {
        const uint32_t* as = A + arowc * Kw + ac0;
        const uint32_t* bs = Bm + (long)bk * N + n0 + bn0;
#pragma unroll
        for (int c = 0; c < 8; c += 4) cp16(smem_u32(&dsu[AS_IDX(0, ar, ac0 + c)]), as + c, asz);
#pragma unroll
        for (int c = 0; c < 8; c += 4) cp16(smem_u32(&dsu[BS_IDX(0, bk, bn0 + c)]), bs + c, 16);
        cp_commit();
    }

    for (int kt = 0; kt < nk; kt++) {
        int cur = kt & 1;
        if (kt + 1 < nk) {
            int nxt = cur ^ 1;
            int kw = (kt + 1) << 4;
            const uint32_t* as = A + arowc * Kw + kw + ac0;
            const uint32_t* bs = Bm + (long)(kw + bk) * N + n0 + bn0;
#pragma unroll
            for (int c = 0; c < 8; c += 4) cp16(smem_u32(&dsu[AS_IDX(nxt, ar, ac0 + c)]), as + c, asz);
#pragma unroll
            for (int c = 0; c < 8; c += 4) cp16(smem_u32(&dsu[BS_IDX(nxt, bk, bn0 + c)]), bs + c, 16);
            cp_commit();
            cp_wait<1>();
        } else {
            cp_wait<0>();
        }
        __syncthreads();

#pragma unroll
        for (int s8 = 0; s8 < 16; s8 += 8) {
            uint32_t af[2][4];
#pragma unroll
            for (int mi = 0; mi < 2; mi++) {
                int r = wm * 32 + mi * 16 + g;
                af[mi][0] = dsu[AS_IDX(cur, r, s8 + tg)];
                af[mi][1] = dsu[AS_IDX(cur, r + 8, s8 + tg)];
                af[mi][2] = dsu[AS_IDX(cur, r, s8 + tg + 4)];
                af[mi][3] = dsu[AS_IDX(cur, r + 8, s8 + tg + 4)];
            }
            uint32_t bf[8][2];
#pragma unroll
            for (int ni = 0; ni < 8; ni++) {
                int cn = wn * 64 + ni * 8 + g;
                bf[ni][0] = dsu[BS_IDX(cur, s8 + tg, cn)];
                bf[ni][1] = dsu[BS_IDX(cur, s8 + 4 + tg, cn)];
            }
#pragma unroll
            for (int mi = 0; mi < 2; mi++)
#pragma unroll
                for (int ni = 0; ni < 8; ni++)
                    mma_bf16(acc[mi][ni], af[mi], bf[ni]);
        }
        __syncthreads();
    }

#pragma unroll
    for (int mi = 0; mi < 2; mi++) {
        int row = m0 + wm * 32 + mi * 16 + g;
#pragma unroll
        for (int ni = 0; ni < 8; ni++) {
            int col = n0 + wn * 64 + ni * 8 + tg * 2;
            float bx = bi[col], by = bi[col + 1];
            if (row < M) {
                float2 o = make_float2(acc[mi][ni][0] + bx, acc[mi][ni][1] + by);
                *(float2*)&C[(long)row * N + col] = o;
            }
            if (row + 8 < M) {
                float2 o = make_float2(acc[mi][ni][2] + bx, acc[mi][ni][3] + by);
                *(float2*)&C[(long)(row + 8) * N + col] = o;
            }
        }
    }
}

// ---------------------------------------------------------------------------
// FF1 (bf16) fused with GeGLU -> G (bf16)
struct FF1DescB {
    const float* bip;
    long offA[3], offGW[3];
    int  M[3];
};

#define GB_STRIDE 72

__global__ void __launch_bounds__(256, 2)
k_gemm_ff1(FF1DescB d) {
    extern __shared__ uint32_t dsu[];
    float* dsf = (float*)dsu;
    uint32_t* au = (uint32_t*)d_arena;
    int z = blockIdx.z;
    int M = d.M[z];
    int m0 = blockIdx.y * 128;
    if (m0 >= M) return;
    const int N = 4096;
    const int Kw = 256;
    const uint32_t* A  = au + d.offA[z];
    const uint32_t* Bm = au + OFF_WF1 + (long)z * 256 * 4096;
    const float*    bi = d.bip + (long)z * 4096;
    uint32_t*       Gw = au + d.offGW[z];

    int tid  = threadIdx.x;
    int lane = tid & 31, wid = tid >> 5;
    int wm = wid & 3, wn = wid >> 2;
    int g  = lane >> 2, tg = lane & 3;
    int n0 = blockIdx.x * 64;

    int ar  = tid >> 1;
    int ac0 = (tid & 1) << 3;
    int bk  = tid >> 4;
    int bn0 = (tid & 15) << 3;
    int gcol = (bn0 < 64) ? (n0 + bn0) : (2048 + n0 + bn0 - 64);

    long grow = m0 + ar;
    long arowc = (grow < M ? grow : (long)(M - 1));
    int  asz = (grow < M) ? 16 : 0;

    float acc[2][8][4];
#pragma unroll
    for (int mi = 0; mi < 2; mi++)
#pragma unroll
        for (int ni = 0; ni < 8; ni++)
#pragma unroll
            for (int r = 0; r < 4; r++) acc[mi][ni][r] = 0.f;

    const int nk = 16;

    {
        const uint32_t* as = A + arowc * Kw + ac0;
        const uint32_t* bs = Bm + (long)bk * N + gcol;
#pragma unroll
        for (int c = 0; c < 8; c += 4) cp16(smem_u32(&dsu[AS_IDX(0, ar, ac0 + c)]), as + c, asz);
#pragma unroll
        for (int c = 0; c < 8; c += 4) cp16(smem_u32(&dsu[BS_IDX(0, bk, bn0 + c)]), bs + c, 16);
        cp_commit();
    }

    for (int kt = 0; kt < nk; kt++) {
        int cur = kt & 1;
        if (kt + 1 < nk) {
            int nxt = cur ^ 1;
            int kw = (kt + 1) << 4;
            const uint32_t* as = A + arowc * Kw + kw + ac0;
            const uint32_t* bs = Bm + (long)(kw + bk) * N + gcol;
#pragma unroll
            for (int c = 0; c < 8; c += 4) cp16(smem_u32(&dsu[AS_IDX(nxt, ar, ac0 + c)]), as + c, asz);
#pragma unroll
            for (int c = 0; c < 8; c += 4) cp16(smem_u32(&dsu[BS_IDX(nxt, bk, bn0 + c)]), bs + c, 16);
            cp_commit();
            cp_wait<1>();
        } else {
            cp_wait<0>();
        }
        __syncthreads();

#pragma unroll
        for (int s8 = 0; s8 < 16; s8 += 8) {
            uint32_t af[2][4];
#pragma unroll
            for (int mi = 0; mi < 2; mi++) {
                int r = wm * 32 + mi * 16 + g;
                af[mi][0] = dsu[AS_IDX(cur, r, s8 + tg)];
                af[mi][1] = dsu[AS_IDX(cur, r + 8, s8 + tg)];
                af[mi][2] = dsu[AS_IDX(cur, r, s8 + tg + 4)];
                af[mi][3] = dsu[AS_IDX(cur, r + 8, s8 + tg + 4)];
            }
            uint32_t bf[8][2];
#pragma unroll
            for (int ni = 0; ni < 8; ni++) {
                int cn = wn * 64 + ni * 8 + g;
                bf[ni][0] = dsu[BS_IDX(cur, s8 + tg, cn)];
                bf[ni][1] = dsu[BS_IDX(cur, s8 + 4 + tg, cn)];
            }
#pragma unroll
            for (int mi = 0; mi < 2; mi++)
#pragma unroll
                for (int ni = 0; ni < 8; ni++)
                    mma_bf16(acc[mi][ni], af[mi], bf[ni]);
        }
        __syncthreads();
    }

    if (wn == 1) {
#pragma unroll
        for (int mi = 0; mi < 2; mi++) {
            int r0 = wm * 32 + mi * 16 + g;
#pragma unroll
            for (int ni = 0; ni < 8; ni++) {
                int c = ni * 8 + tg * 2;
                float bx = bi[2048 + n0 + c], by = bi[2048 + n0 + c + 1];
                float g0 = acc[mi][ni][0] + bx, g1 = acc[mi][ni][1] + by;
                float g2 = acc[mi][ni][2] + bx, g3 = acc[mi][ni][3] + by;
                dsf[r0 * GB_STRIDE + c]           = 0.5f * g0 * (1.f + erff(g0 * 0.7071067811865475f));
                dsf[r0 * GB_STRIDE + c + 1]       = 0.5f * g1 * (1.f + erff(g1 * 0.7071067811865475f));
                dsf[(r0 + 8) * GB_STRIDE + c]     = 0.5f * g2 * (1.f + erff(g2 * 0.7071067811865475f));
                dsf[(r0 + 8) * GB_STRIDE + c + 1] = 0.5f * g3 * (1.f + erff(g3 * 0.7071067811865475f));
            }
        }
    }
    __syncthreads();
    if (wn == 0) {
#pragma unroll
        for (int mi = 0; mi < 2; mi++) {
            int rl = wm * 32 + mi * 16 + g;
            int row = m0 + rl;
#pragma unroll
            for (int ni = 0; ni < 8; ni++) {
                int c = ni * 8 + tg * 2;
                float bx = bi[n0 + c], by = bi[n0 + c + 1];
                if (row < M) {
                    float ox = (acc[mi][ni][0] + bx) * dsf[rl * GB_STRIDE + c];
                    float oy = (acc[mi][ni][1] + by) * dsf[rl * GB_STRIDE + c + 1];
                    Gw[(long)row * 1024 + ((n0 + c) >> 1)] = pack_bf(ox, oy);
                }
                if (row + 8 < M) {
                    float ox = (acc[mi][ni][2] + bx) * dsf[(rl + 8) * GB_STRIDE + c];
                    float oy = (acc[mi][ni][3] + by) * dsf[(rl + 8) * GB_STRIDE + c + 1];
                    Gw[(long)(row + 8) * 1024 + ((n0 + c) >> 1)] = pack_bf(ox, oy);
                }
            }
        }
    }
}

// ---------------------------------------------------------------------------
// FF2 (bf16, K=2048) fused with final residual -> d_out
struct FF2DescB {
    const float* bip;
    float* out;
    long offA[3];
    long tokOff[3];
    int  M[3], len[3], catOff[3];
};

__global__ void __launch_bounds__(256, 2)
k_gemm_ff2(FF2DescB d) {
    extern __shared__ uint32_t dsu[];
    uint32_t* au = (uint32_t*)d_arena;
    int z = blockIdx.z;
    int M = d.M[z];
    int m0 = blockIdx.y * 128;
    if (m0 >= M) return;
    const int N = DM;
    const int Kw = 1024;
    const uint32_t* A  = au + d.offA[z];
    const uint32_t* Bm = au + OFF_WF2 + (long)z * 1024 * 512;
    const float*    bi = d.bip + (long)z * DM;

    int tid  = threadIdx.x;
    int lane = tid & 31, wid = tid >> 5;
    int wm = wid & 3, wn = wid >> 2;
    int g  = lane >> 2, tg = lane & 3;
    int n0 = blockIdx.x * 128;

    int ar  = tid >> 1;
    int ac0 = (tid & 1) << 3;
    int bk  = tid >> 4;
    int bn0 = (tid & 15) << 3;

    long grow = m0 + ar;
    long arowc = (grow < M ? grow : (long)(M - 1));
    int  asz = (grow < M) ? 16 : 0;

    float acc[2][8][4];
#pragma unroll
    for (int mi = 0; mi < 2; mi++)
#pragma unroll
        for (int ni = 0; ni < 8; ni++)
#pragma unroll
            for (int r = 0; r < 4; r++) acc[mi][ni][r] = 0.f;

    const int nk = 64;

    {
        const uint32_t* as = A + arowc * Kw + ac0;
        const uint32_t* bs = Bm + (long)bk * N + n0 + bn0;
#pragma unroll
        for (int c = 0; c < 8; c += 4) cp16(smem_u32(&dsu[AS_IDX(0, ar, ac0 + c)]), as + c, asz);
#pragma unroll
        for (int c = 0; c < 8; c += 4) cp16(smem_u32(&dsu[BS_IDX(0, bk, bn0 + c)]), bs + c, 16);
        cp_commit();
    }

    for (int kt = 0; kt < nk; kt++) {
        int cur = kt & 1;
        if (kt + 1 < nk) {
            int nxt = cur ^ 1;
            int kw = (kt + 1) << 4;
            const uint32_t* as = A + arowc * Kw + kw + ac0;
            const uint32_t* bs = Bm + (long)(kw + bk) * N + n0 + bn0;
#pragma unroll
            for (int c = 0; c < 8; c += 4) cp16(smem_u32(&dsu[AS_IDX(nxt, ar, ac0 + c)]), as + c, asz);
#pragma unroll
            for (int c = 0; c < 8; c += 4) cp16(smem_u32(&dsu[BS_IDX(nxt, bk, bn0 + c)]), bs + c, 16);
            cp_commit();
            cp_wait<1>();
        } else {
            cp_wait<0>();
        }
        __syncthreads();

#pragma unroll
        for (int s8 = 0; s8 < 16; s8 += 8) {
            uint32_t af[2][4];
#pragma unroll
            for (int mi = 0; mi < 2; mi++) {
                int r = wm * 32 + mi * 16 + g;
                af[mi][0] = dsu[AS_IDX(cur, r, s8 + tg)];
                af[mi][1] = dsu[AS_IDX(cur, r + 8, s8 + tg)];
                af[mi][2] = dsu[AS_IDX(cur, r, s8 + tg + 4)];
                af[mi][3] = dsu[AS_IDX(cur, r + 8, s8 + tg + 4)];
            }
            uint32_t bf[8][2];
#pragma unroll
            for (int ni = 0; ni < 8; ni++) {
                int cn = wn * 64 + ni * 8 + g;
                bf[ni][0] = dsu[BS_IDX(cur, s8 + tg, cn)];
                bf[ni][1] = dsu[BS_IDX(cur, s8 + 4 + tg, cn)];
            }
#pragma unroll
            for (int mi = 0; mi < 2; mi++)
#pragma unroll
                for (int ni = 0; ni < 8; ni++)
                    mma_bf16(acc[mi][ni], af[mi], bf[ni]);
        }
        __syncthreads();
    }

    int len = d.len[z], catOff = d.catOff[z];
    long tokOff = d.tokOff[z];
#pragma unroll
    for (int mi = 0; mi < 2; mi++) {
#pragma unroll
        for (int half = 0; half < 2; half++) {
            int r = m0 + wm * 32 + mi * 16 + g + half * 8;
            if (r >= M) continue;
            int bidx = r / len, t = r - bidx * len;
            float* orow = d.out + ((long)bidx * LL + catOff + t) * DM;
            const float* hrow = d_arena + OFF_HBUF + (tokOff + r) * (long)DM;
            const float* gm = d_arena + OFF_ADA + ((long)z * BB + bidx) * 3072 + 2560;
#pragma unroll
            for (int ni = 0; ni < 8; ni++) {
                int col = n0 + wn * 64 + ni * 8 + tg * 2;
                float fx = acc[mi][ni][half * 2 + 0] + bi[col];
                float fy = acc[mi][ni][half * 2 + 1] + bi[col + 1];
                float2 hv = *(const float2*)&hrow[col];
                float2 gv = *(const float2*)&gm[col];
                float2 o = make_float2(hv.x + gv.x * fx, hv.y + gv.y * fy);
                *(float2*)&orow[col] = o;
            }
        }
    }
}

// ---------------------------------------------------------------------------
__device__ __forceinline__ void block_ln_stats(float s, float q, float* mean, float* ri) {
    __shared__ float sh[8];
    int lane = threadIdx.x & 31, wid = threadIdx.x >> 5;
#pragma unroll
    for (int off = 16; off; off >>= 1) {
        s += __shfl_xor_sync(~0u, s, off);
        q += __shfl_xor_sync(~0u, q, off);
    }
    if (lane == 0) { sh[wid] = s; sh[4 + wid] = q; }
    __syncthreads();
    if (threadIdx.x == 0) {
        float S = sh[0] + sh[1] + sh[2] + sh[3];
        float Q = sh[4] + sh[5] + sh[6] + sh[7];
        float m = S * (1.f / 512.f);
        float v = Q * (1.f / 512.f) - m * m;
        sh[0] = m;
        sh[1] = rsqrtf(v + 1e-6f);
    }
    __syncthreads();
    *mean = sh[0];
    *ri   = sh[1];
}

__device__ __forceinline__ void row_decode(int r, int* istream, int* b, int* t) {
    if (r < 1232)      { *istream = 2; *b = r / TT;            *t = r - *b * TT; }
    else if (r < 6032) { int rr = r - 1232; *istream = 1; *b = rr / SSRC; *t = rr - *b * SSRC; }
    else               { int rr = r - 6032; *istream = 0; *b = rr / NHID; *t = rr - *b * NHID; }
}

__global__ void k_modln(const float* __restrict__ x, const float* __restrict__ src,
                        const float* __restrict__ txt) {
    int row = blockIdx.x;
    int istream, b, t;
    row_decode(row, &istream, &b, &t);
    const float* inp = (istream == 2) ? txt : (istream == 1 ? src : x);
    int lrow = (istream == 2) ? (b * TT + t) : (istream == 1 ? (b * SSRC + t) : (b * NHID + t));
    int tid = threadIdx.x;
    float4 v = *(const float4*)&inp[(long)lrow * DM + tid * 4];
    float s = v.x + v.y + v.z + v.w;
    float q = v.x * v.x + v.y * v.y + v.z * v.z + v.w * v.w;
    float mean, ri;
    block_ln_stats(s, q, &mean, &ri);
    const float* ada = d_arena + OFF_ADA + ((long)istream * BB + b) * 3072;
    float4 sc = *(const float4*)&ada[512 + tid * 4];
    float4 shv = *(const float4*)&ada[tid * 4];
    float ox = (v.x - mean) * ri * (1.f + sc.x) + shv.x;
    float oy = (v.y - mean) * ri * (1.f + sc.y) + shv.y;
    float oz = (v.z - mean) * ri * (1.f + sc.z) + shv.z;
    float ow = (v.w - mean) * ri * (1.f + sc.w) + shv.w;
    uint32_t* au = (uint32_t*)d_arena;
    uint2 pk = make_uint2(pack_bf(ox, oy), pack_bf(oz, ow));
    *(uint2*)&au[OFF_NBUF + (long)row * 256 + tid * 2] = pk;
}

__global__ void k_resln(const float* __restrict__ x, const float* __restrict__ src,
                        const float* __restrict__ txt) {
    int row = blockIdx.x;
    int istream, b, t;
    row_decode(row, &istream, &b, &t);
    const float* inp = (istream == 2) ? txt : (istream == 1 ? src : x);
    int lrow = (istream == 2) ? (b * TT + t) : (istream == 1 ? (b * SSRC + t) : (b * NHID + t));
    int tid = threadIdx.x;
    long rb = (long)row * DM;
    const float* ada = d_arena + OFF_ADA + ((long)istream * BB + b) * 3072;

    float4 x4 = *(const float4*)&inp[(long)lrow * DM + tid * 4];
    float4 a4 = *(const float4*)&d_arena[OFF_ABUF + rb + tid * 4];
    float4 g4 = *(const float4*)&ada[1024 + tid * 4];
    float4 hv;
    hv.x = x4.x + g4.x * a4.x;
    hv.y = x4.y + g4.y * a4.y;
    hv.z = x4.z + g4.z * a4.z;
    hv.w = x4.w + g4.w * a4.w;
    *(float4*)&d_arena[OFF_HBUF + rb + tid * 4] = hv;

    float s = hv.x + hv.y + hv.z + hv.w;
    float q = hv.x * hv.x + hv.y * hv.y + hv.z * hv.z + hv.w * hv.w;
    float mean, ri;
    block_ln_stats(s, q, &mean, &ri);
    float4 sc = *(const float4*)&ada[2048 + tid * 4];
    float4 shv = *(const float4*)&ada[1536 + tid * 4];
    float ox = (hv.x - mean) * ri * (1.f + sc.x) + shv.x;
    float oy = (hv.y - mean) * ri * (1.f + sc.y) + shv.y;
    float oz = (hv.z - mean) * ri * (1.f + sc.z) + shv.z;
    float ow = (hv.w - mean) * ri * (1.f + sc.w) + shv.w;
    uint32_t* au = (uint32_t*)d_arena;
    uint2 pk = make_uint2(pack_bf(ox, oy), pack_bf(oz, ow));
    *(uint2*)&au[OFF_N2 + (long)row * 256 + tid * 2] = pk;
}

// ---------------------------------------------------------------------------
// qkv postprocess: each lane owns adjacent d-pair (2*lane, 2*lane+1).
// RMS + RoPE-xpos (rotate-half partner is in-thread) / learned pos, then
// Q/K written as packed bf16 d-pair words, V as fp32.
__global__ void k_qkvx(const float* __restrict__ gqk,
                       const float* __restrict__ pos_q,
                       const float* __restrict__ pos_k) {
    int w = threadIdx.x >> 5;
    int lane = threadIdx.x & 31;
    int gi = blockIdx.x * 4 + w;
    int h = gi & 7;
    int bl = gi >> 3;
    int l = bl % LL;
    int b = bl / LL;

    int istream, t;
    long r;
    if (l < TT)            { istream = 2; t = l;            r = (long)b * TT + t; }
    else if (l < TT + SSRC){ istream = 1; t = l - TT;       r = 1232 + (long)b * SSRC + t; }
    else                   { istream = 0; t = l - TT - SSRC; r = 6032 + (long)b * NHID + t; }

    long base = r * DM + h * HD + 2 * lane;
    float2 q = *(const float2*)&d_arena[OFF_QKV + base];
    float2 k = *(const float2*)&d_arena[OFF_QKV + (long)TOKS * DM + base];
    float2 v = *(const float2*)&d_arena[OFF_QKV + 2L * TOKS * DM + base];

    float sq = q.x * q.x + q.y * q.y;
    float sk = k.x * k.x + k.y * k.y;
#pragma unroll
    for (int off = 16; off; off >>= 1) {
        sq += __shfl_xor_sync(~0u, sq, off);
        sk += __shfl_xor_sync(~0u, sk, off);
    }
    float rq = rsqrtf(sq * (1.f / 64.f) + 1e-6f);
    float rk = rsqrtf(sk * (1.f / 64.f) + 1e-6f);
    float2 gq = *(const float2*)&gqk[(istream * 2 + 0) * 64 + 2 * lane];
    float2 gk = *(const float2*)&gqk[(istream * 2 + 1) * 64 + 2 * lane];
    q.x *= rq * gq.x; q.y *= rq * gq.y;
    k.x *= rk * gk.x; k.y *= rk * gk.y;

    if (istream == 2) {
        float2 pq = *(const float2*)&pos_q[t * 64 + 2 * lane];
        float2 pk2 = *(const float2*)&pos_k[t * 64 + 2 * lane];
        q.x += pq.x; q.y += pq.y;
        k.x += pk2.x; k.y += pk2.y;
    } else {
        float tf = (float)t;
        float pw = (tf - 150.f) * (1.f / 512.f);
        float inv = powf(10000.f, -(float)(2 * lane) * (1.f / 64.f));
        float ang = tf * inv;
        float c = cosf(ang), s = sinf(ang);
        float scl = powf(((float)(2 * lane) + 25.6f) * (1.f / 89.6f), pw);
        float csq = c * scl, snq = s * scl;
        float csk = c / scl, snk = s / scl;
        float qe = q.x, qo = q.y, ke = k.x, ko = k.y;
        q.x = qe * csq - qo * snq;
        q.y = qo * csq + qe * snq;
        k.x = ke * csk - ko * snk;
        k.y = ko * csk + ke * snk;
    }

    uint32_t* au = (uint32_t*)d_arena;
    long wo = ((long)(b * NH + h) * LL + l) * 32 + lane;
    au[OFF_QAW + wo] = pack_bf(q.x, q.y);
    au[OFF_KAW + wo] = pack_bf(k.x, k.y);
    *(float2*)&d_arena[OFF_VA + ((long)(b * NH + h) * LL + l) * 64 + 2 * lane] = v;
}

// ---------------------------------------------------------------------------
// bf16 tensor-core flash attention: 64 queries/block, 4 warps, K-tile 32,
// m16n8k16 for both QK^T and P.V; OGAT packed bf16.
#define QTILES 11
__device__ __forceinline__ int tok_row(int l, int b) {
    if (l < TT)        return b * TT + l;
    if (l < TT + SSRC) return 1232 + b * SSRC + (l - TT);
    return 6032 + b * NHID + (l - TT - SSRC);
}

__global__ void __launch_bounds__(128)
k_attn_tc(const int* __restrict__ valid) {
    __shared__ uint32_t Qs[64][36];   // packed d-pair words (32 used)
    __shared__ uint32_t Ks[32][36];
    __shared__ uint32_t Vt[64][20];   // [d][key-pair word] (16 used)
    __shared__ uint32_t Ps[64][20];   // [q-row][key-pair word] (16 used)
    __shared__ int      sVal[LL];

    uint32_t* au = (uint32_t*)d_arena;
    int tid = threadIdx.x;
    int lane = tid & 31, wid = tid >> 5;
    int g = lane >> 2, tg = lane & 3;
    int bh = blockIdx.x / QTILES;
    int qt = blockIdx.x % QTILES;
    int b = bh >> 3, h = bh & 7;
    int qbase = qt * 64;
    long qkbase = (long)bh * LL * 32;   // word base for QAW/KAW
    long vbase  = (long)bh * LL * 64;   // float base for VA

    for (int m = tid; m < LL; m += 128) sVal[m] = valid[b * LL + m];

    // stage Q (64 rows x 8 uint4)
    for (int e = tid; e < 512; e += 128) {
        int r = e >> 3, c4 = (e & 7) << 2;
        int l = qbase + r;
        uint4 v = make_uint4(0u, 0u, 0u, 0u);
        if (l < LL) v = *(const uint4*)&au[OFF_QAW + qkbase + (long)l * 32 + c4];
        *(uint4*)&Qs[r][c4] = v;
    }
    __syncthreads();

    int l0 = qbase + wid * 16 + g;
    int l1 = l0 + 8;
    int qv0 = (l0 < LL) ? sVal[l0] : 0;
    int qv1 = (l1 < LL) ? sVal[l1] : 0;

    float m0r = -1e30f, m1r = -1e30f;
    float l0r = 0.f, l1r = 0.f;
    float of[8][4];
#pragma unroll
    for (int ni = 0; ni < 8; ni++)
#pragma unroll
        for (int c = 0; c < 4; c++) of[ni][c] = 0.f;

    // V-stage thread mapping: j2 = key-pair 0..15, dg = d-group 0..7
    int vj2 = tid & 15, vdg = tid >> 4;

    for (int kb = 0; kb < LL; kb += 32) {
        // stage K (32 rows x 8 uint4)
        for (int e = tid; e < 256; e += 128) {
            int r = e >> 3, c4 = (e & 7) << 2;
            int m = kb + r;
            uint4 v = make_uint4(0u, 0u, 0u, 0u);
            if (m < LL) v = *(const uint4*)&au[OFF_KAW + qkbase + (long)m * 32 + c4];
            *(uint4*)&Ks[r][c4] = v;
        }
        // stage V transposed: word (d, j2) = pack(V[kb+2*j2][d], V[kb+2*j2+1][d])
        {
            int ke = kb + 2 * vj2, ko = ke + 1;
            float4 e0 = make_float4(0.f, 0.f, 0.f, 0.f), e1 = e0, o0 = e0, o1 = e0;
            if (ke < LL) {
                const float* p = &d_arena[OFF_VA + vbase + (long)ke * 64 + vdg * 8];
                e0 = *(const float4*)p;
                e1 = *(const float4*)(p + 4);
            }
            if (ko < LL) {
                const float* p = &d_arena[OFF_VA + vbase + (long)ko * 64 + vdg * 8];
                o0 = *(const float4*)p;
                o1 = *(const float4*)(p + 4);
            }
            int d0 = vdg * 8;
            Vt[d0 + 0][vj2] = pack_bf(e0.x, o0.x);
            Vt[d0 + 1][vj2] = pack_bf(e0.y, o0.y);
            Vt[d0 + 2][vj2] = pack_bf(e0.z, o0.z);
            Vt[d0 + 3][vj2] = pack_bf(e0.w, o0.w);
            Vt[d0 + 4][vj2] = pack_bf(e1.x, o1.x);
            Vt[d0 + 5][vj2] = pack_bf(e1.y, o1.y);
            Vt[d0 + 6][vj2] = pack_bf(e1.z, o1.z);
            Vt[d0 + 7][vj2] = pack_bf(e1.w, o1.w);
        }
        __syncthreads();

        // S = Q @ K^T  (bf16, 4 k16-steps over 64 dims)
        float sf[4][4];
#pragma unroll
        for (int ni = 0; ni < 4; ni++)
#pragma unroll
            for (int c = 0; c < 4; c++) sf[ni][c] = 0.f;
        int rq = wid * 16 + g;
#pragma unroll
        for (int s = 0; s < 4; s++) {
            uint32_t af[4];
            af[0] = Qs[rq][s * 8 + tg];
            af[1] = Qs[rq + 8][s * 8 + tg];
            af[2] = Qs[rq][s * 8 + tg + 4];
            af[3] = Qs[rq + 8][s * 8 + tg + 4];
#pragma unroll
            for (int ni = 0; ni < 4; ni++) {
                uint32_t bf[2];
                bf[0] = Ks[ni * 8 + g][s * 8 + tg];
                bf[1] = Ks[ni * 8 + g][s * 8 + tg + 4];
                mma_bf16(sf[ni], af, bf);
            }
        }

        // masking + online softmax (fragment c-layout identical to before)
        float rmax0 = -1e30f, rmax1 = -1e30f;
        float sv[4][4];
        int okm[4][4];
#pragma unroll
        for (int ni = 0; ni < 4; ni++) {
#pragma unroll
            for (int c = 0; c < 2; c++) {
                int key = kb + ni * 8 + tg * 2 + c;
                int kvv = (key < LL) ? sVal[key] : 0;
                int ok0 = (key < LL) && (((qv0 != 0) && (kvv != 0)) || (key == l0));
                int ok1 = (key < LL) && (((qv1 != 0) && (kvv != 0)) || (key == l1));
                float s0 = sf[ni][c] * 0.125f;
                float s1 = sf[ni][c + 2] * 0.125f;
                sv[ni][c] = s0; sv[ni][c + 2] = s1;
                okm[ni][c] = ok0; okm[ni][c + 2] = ok1;
                if (ok0) rmax0 = fmaxf(rmax0, s0);
                if (ok1) rmax1 = fmaxf(rmax1, s1);
            }
        }
        rmax0 = fmaxf(rmax0, __shfl_xor_sync(~0u, rmax0, 1));
        rmax0 = fmaxf(rmax0, __shfl_xor_sync(~0u, rmax0, 2));
        rmax1 = fmaxf(rmax1, __shfl_xor_sync(~0u, rmax1, 1));
        rmax1 = fmaxf(rmax1, __shfl_xor_sync(~0u, rmax1, 2));
        float nm0 = fmaxf(m0r, rmax0);
        float nm1 = fmaxf(m1r, rmax1);
        float corr0 = __expf(m0r - nm0);
        float corr1 = __expf(m1r - nm1);

        float rs0 = 0.f, rs1 = 0.f;
        float pv[4][4];
#pragma unroll
        for (int ni = 0; ni < 4; ni++) {
#pragma unroll
            for (int c = 0; c < 2; c++) {
                float p0 = okm[ni][c]     ? __expf(sv[ni][c] - nm0)     : 0.f;
                float p1 = okm[ni][c + 2] ? __expf(sv[ni][c + 2] - nm1) : 0.f;
                pv[ni][c] = p0; pv[ni][c + 2] = p1;
                rs0 += p0; rs1 += p1;
            }
        }
        rs0 += __shfl_xor_sync(~0u, rs0, 1);
        rs0 += __shfl_xor_sync(~0u, rs0, 2);
        rs1 += __shfl_xor_sync(~0u, rs1, 1);
        rs1 += __shfl_xor_sync(~0u, rs1, 2);
        l0r = l0r * corr0 + rs0;
        l1r = l1r * corr1 + rs1;
        m0r = nm0; m1r = nm1;

#pragma unroll
        for (int ni = 0; ni < 8; ni++) {
            of[ni][0] *= corr0; of[ni][1] *= corr0;
            of[ni][2] *= corr1; of[ni][3] *= corr1;
        }

        // store P as packed key-pair words (c pairs are adjacent keys)
#pragma unroll
        for (int ni = 0; ni < 4; ni++) {
            Ps[rq][ni * 4 + tg]     = pack_bf(pv[ni][0], pv[ni][1]);
            Ps[rq + 8][ni * 4 + tg] = pack_bf(pv[ni][2], pv[ni][3]);
        }
        __syncwarp();

        // O += P @ V  (bf16, 2 k16-steps over 32 keys)
#pragma unroll
        for (int s = 0; s < 2; s++) {
            uint32_t af[4];
            af[0] = Ps[rq][s * 8 + tg];
            af[1] = Ps[rq + 8][s * 8 + tg];
            af[2] = Ps[rq][s * 8 + tg + 4];
            af[3] = Ps[rq + 8][s * 8 + tg + 4];
#pragma unroll
            for (int ni = 0; ni < 8; ni++) {
                uint32_t bf[2];
                bf[0] = Vt[ni * 8 + g][s * 8 + tg];
                bf[1] = Vt[ni * 8 + g][s * 8 + tg + 4];
                mma_bf16(of[ni], af, bf);
            }
        }
        __syncwarp();
        __syncthreads();
    }

    float inv0 = 1.f / l0r;
    float inv1 = 1.f / l1r;
    if (l0 < LL) {
        long op = (long)tok_row(l0, b) * 256 + h * 32;
#pragma unroll
        for (int ni = 0; ni < 8; ni++)
            au[OFF_OGAT + op + ni * 4 + tg] = pack_bf(of[ni][0] * inv0, of[ni][1] * inv0);
    }
    if (l1 < LL) {
        long op = (long)tok_row(l1, b) * 256 + h * 32;
#pragma unroll
        for (int ni = 0; ni < 8; ni++)
            au[OFF_OGAT + op + ni * 4 + tg] = pack_bf(of[ni][2] * inv1, of[ni][3] * inv1);
    }
}

// ---------------------------------------------------------------------------
extern "C" void kernel_launch(void* const* d_in, const int* in_sizes, int n_in,
                              void* d_out, int out_size) {
    const float* x     = (const float*)d_in[0];
    const float* src   = (const float*)d_in[1];
    const float* txt   = (const float*)d_in[2];
    const float* temb  = (const float*)d_in[3];
    const float* Wqkv  = (const float*)d_in[4];
    const float* bqkv  = (const float*)d_in[5];
    const float* Wo    = (const float*)d_in[6];
    const float* bo    = (const float*)d_in[7];
    const float* gqk   = (const float*)d_in[8];
    const float* Wada  = (const float*)d_in[9];
    const float* bada  = (const float*)d_in[10];
    const float* Wff1  = (const float*)d_in[11];
    const float* bff1  = (const float*)d_in[12];
    const float* Wff2  = (const float*)d_in[13];
    const float* bff2  = (const float*)d_in[14];
    const float* pos_q = (const float*)d_in[15];
    const float* pos_k = (const float*)d_in[16];
    const int*   valid = (const int*)d_in[17];
    float* out = (float*)d_out;

    const int  lens[3]    = {NHID, SSRC, TT};
    const long tokOffs[3] = {6032, 1232, 0};
    const int  catOffs[3] = {377, 77, 0};

    // 0. weight prepack (vectorized x4)
    k_wconv4<<<(294912 + 255) / 256, 256>>>(Wqkv, OFF_WQ, 256, 512, 294912);
    k_wconv4<<<(98304 + 255) / 256, 256>>>(Wo, OFF_WO, 256, 512, 98304);
    k_wconv4<<<(786432 + 255) / 256, 256>>>(Wff1, OFF_WF1, 256, 4096, 786432);
    k_wconv4<<<(393216 + 255) / 256, 256>>>(Wff2, OFF_WF2, 1024, 512, 393216);

    // 1. silu(temb)
    k_silu<<<(BB * DM + 255) / 256, 256>>>(temb);

    // 2. ada = st @ Wada[s] + bada[s]
    {
        dim3 g(3072 / 64, 1, 3);
        k_gemm<<<g, 256>>>(Wada, bada, OFF_ST, OFF_ADA, BB, 3072, DM,
                           512L * 3072, 3072L, 16L * 3072);
    }

    // 3. modulated LN (merged) -> NBUF bf16
    k_modln<<<TOKS, 128>>>(x, src, txt);

    // 4. QKV GEMMs (bf16)
    {
        GemmDescB d;
        d.bip = bqkv; d.szBias = DM;
        d.bW = OFF_WQ; d.szBW = 256L * 512;
        d.N = DM; d.K = DM;
        for (int z = 0; z < 9; z++) {
            int s = z / 3, j = z % 3;
            d.offA[z] = OFF_NBUF + tokOffs[s] * 256;
            d.offC[z] = OFF_QKV + (long)j * TOKS * DM + tokOffs[s] * DM;
            d.M[z]    = BB * lens[s];
        }
        dim3 g(DM / 128, 38, 9);
        k_gemm_bf<<<g, 256, GT_SMEM>>>(d);
    }

    // 5. RMS + RoPE/pos -> QAW/KAW packed bf16, VA fp32
    k_qkvx<<<(BB * LL * NH) / 4, 128>>>(gqk, pos_q, pos_k);

    // 6. attention (bf16 flash) -> OGAT bf16
    k_attn_tc<<<BB * NH * QTILES, 128>>>(valid);

    // 7. output projection (bf16)
    {
        GemmDescB d;
        d.bip = bo; d.szBias = DM;
        d.bW = OFF_WO; d.szBW = 256L * 512;
        d.N = DM; d.K = DM;
        for (int z = 0; z < 3; z++) {
            d.offA[z] = OFF_OGAT + tokOffs[z] * 256;
            d.offC[z] = OFF_ABUF + tokOffs[z] * DM;
            d.M[z]    = BB * lens[z];
        }
        dim3 g(DM / 128, 38, 3);
        k_gemm_bf<<<g, 256, GT_SMEM>>>(d);
    }

    // 8. residual + LN2 (merged) -> HBUF fp32, N2 bf16
    k_resln<<<TOKS, 128>>>(x, src, txt);

    // 9. FF1 (bf16) fused GeGLU -> G bf16
    {
        FF1DescB d;
        d.bip = bff1;
        for (int z = 0; z < 3; z++) {
            d.offA[z]  = OFF_N2 + tokOffs[z] * 256;
            d.offGW[z] = OFF_G + tokOffs[z] * 1024;
            d.M[z]     = BB * lens[z];
        }
        dim3 g(2048 / 64, 38, 3);
        k_gemm_ff1<<<g, 256, GT_SMEM>>>(d);
    }

    // 10. FF2 (bf16) fused final residual -> out
    {
        FF2DescB d;
        d.bip = bff2; d.out = out;
        for (int z = 0; z < 3; z++) {
            d.offA[z]   = OFF_G + tokOffs[z] * 1024;
            d.tokOff[z] = tokOffs[z];
            d.M[z]      = BB * lens[z];
            d.len[z]    = lens[z];
            d.catOff[z] = catOffs[z];
        }
        dim3 g(DM / 128, 38, 3);
        k_gemm_ff2<<<g, 256, GT_SMEM>>>(d);
    }
}